// round 9
// baseline (speedup 1.0000x reference)
#include <cuda_runtime.h>
#include <math.h>
#include <stdint.h>

#if (defined(__CUDA_ARCH_FEAT_SM103_ALL) || (defined(__CUDA_ARCH_SPECIFIC__) && (__CUDA_ARCH__ == 1030)))
#define USE_TC 1
#else
#define USE_TC 0
#endif

#define BATCH 4
#define CCH 64
#define HH 256
#define WWI 256
#define HW (HH*WWI)
#define IMG (CCH*HW)
#define NPIX (BATCH*HW)

// ---------------- scratch (device globals, no allocs) ----------------
__device__ float g_feat[BATCH*CCH*HW];
__device__ float g_b0e[4*BATCH*CCH*HW];   // per-expert block-0 residual branch
__device__ float g_b1e[4*BATCH*CCH*HW];   // per-expert block-1 residual branch
__device__ float g_sr[BATCH*3*512*512];
__device__ int   g_top[NPIX];
__device__ float g_gsum[4*BATCH*CCH];     // [e][b][c]
__device__ float g_y0[4*BATCH*CCH];
__device__ float g_y1[4*BATCH*CCH];
// quantized / transposed weights
__device__ float d_sq_t[27*64];     // shallow, transposed [k][co]
__device__ float d_texdw[576];
__device__ float d_texpw[512];
__device__ float d_edw[8*576];
__device__ float d_epw[8*4096];     // pw weights: SW128 MMA layout (TC) or [ci][co] (fallback)
__device__ float d_ref1[81];
__device__ float d_ref2[81];
__device__ float d_rect[576*12];    // recon transposed [ci*9+k][co]

// ---------------- f32x2 helpers ----------------
__device__ __forceinline__ unsigned long long pack2(float a, float b){
    unsigned long long r;
    asm("mov.b64 %0, {%1, %2};" : "=l"(r) : "r"(__float_as_uint(a)), "r"(__float_as_uint(b)));
    return r;
}
__device__ __forceinline__ void unpack2(unsigned long long v, float& a, float& b){
    unsigned int x, y;
    asm("mov.b64 {%0, %1}, %2;" : "=r"(x), "=r"(y) : "l"(v));
    a = __uint_as_float(x); b = __uint_as_float(y);
}
__device__ __forceinline__ void fma2(unsigned long long& acc, unsigned long long w, unsigned long long x){
    asm("fma.rn.f32x2 %0, %1, %2, %0;" : "+l"(acc) : "l"(w), "l"(x));
}

__device__ __forceinline__ uint32_t smem_u32(const void* p){
    uint32_t a;
    asm("{ .reg .u64 t; cvta.to.shared.u64 t, %1; cvt.u32.u64 %0, t; }" : "=r"(a) : "l"(p));
    return a;
}

__host__ __device__ __forceinline__ uint32_t sw128(uint32_t off){ return off ^ ((off >> 3) & 0x70); }

#if USE_TC
// ---------------- tcgen05 / mbarrier helpers (sm_103a-specific pass only) ----------------
__device__ __forceinline__ uint32_t elect_one_pred(){
    uint32_t pred;
    asm volatile("{\n\t.reg .pred p;\n\telect.sync _|p, 0xFFFFFFFF;\n\tselp.b32 %0, 1, 0, p;\n\t}" : "=r"(pred));
    return pred;
}
#define TC_ALLOC(sa, n)   asm volatile("tcgen05.alloc.cta_group::1.sync.aligned.shared::cta.b32 [%0], %1;" :: "r"(sa), "r"((uint32_t)(n)) : "memory")
#define TC_DEALLOC(t, n)  asm volatile("tcgen05.dealloc.cta_group::1.sync.aligned.b32 %0, %1;" :: "r"(t), "r"((uint32_t)(n)))
#define TC_RELINQ()       asm volatile("tcgen05.relinquish_alloc_permit.cta_group::1.sync.aligned;")
#define TC_COMMIT(mb)     asm volatile("tcgen05.commit.cta_group::1.mbarrier::arrive::one.shared::cluster.b64 [%0];" :: "r"(mb) : "memory")
#define TC_FENCE_AFTER()  asm volatile("tcgen05.fence::after_thread_sync;" ::: "memory")
#define TC_WAIT_LD()      asm volatile("tcgen05.wait::ld.sync.aligned;" ::: "memory")
#define FENCE_ASYNC()     asm volatile("fence.proxy.async.shared::cta;" ::: "memory")
#define MBAR_INIT(mb, c)  asm volatile("mbarrier.init.shared.b64 [%0], %1;" :: "r"(mb), "r"((uint32_t)(c)) : "memory")
#define MBAR_INVAL(mb)    asm volatile("mbarrier.inval.shared.b64 [%0];" :: "r"(mb) : "memory")
#define MBAR_WAIT(mb, ph) do { \
    uint32_t _mb = (mb); uint32_t _p = (ph); uint32_t _done; \
    asm volatile("{\n\t.reg .pred p;\n\tmbarrier.try_wait.parity.acquire.cta.shared::cta.b64 p, [%1], %2;\n\tselp.b32 %0, 1, 0, p;\n\t}" \
        : "=r"(_done) : "r"(_mb), "r"(_p) : "memory"); \
    if (!_done){ \
        asm volatile("{\n\t.reg .pred P1;\n\tWL_%=:\n\tmbarrier.try_wait.parity.acquire.cta.shared::cta.b64 P1, [%0], %1, 0x989680;\n\t@P1 bra.uni WD_%=;\n\tbra.uni WL_%=;\n\tWD_%=:\n\t}" \
            :: "r"(_mb), "r"(_p) : "memory"); \
    } \
} while(0)
#define TC_LD_X32(r, ta) \
    asm volatile("tcgen05.ld.sync.aligned.32x32b.x32.b32 " \
        "{%0, %1, %2, %3, %4, %5, %6, %7, %8, %9, %10, %11, %12, %13, %14, %15, " \
        " %16, %17, %18, %19, %20, %21, %22, %23, %24, %25, %26, %27, %28, %29, %30, %31}, [%32];" \
        : "=r"((r)[0]),  "=r"((r)[1]),  "=r"((r)[2]),  "=r"((r)[3]), \
          "=r"((r)[4]),  "=r"((r)[5]),  "=r"((r)[6]),  "=r"((r)[7]), \
          "=r"((r)[8]),  "=r"((r)[9]),  "=r"((r)[10]), "=r"((r)[11]), \
          "=r"((r)[12]), "=r"((r)[13]), "=r"((r)[14]), "=r"((r)[15]), \
          "=r"((r)[16]), "=r"((r)[17]), "=r"((r)[18]), "=r"((r)[19]), \
          "=r"((r)[20]), "=r"((r)[21]), "=r"((r)[22]), "=r"((r)[23]), \
          "=r"((r)[24]), "=r"((r)[25]), "=r"((r)[26]), "=r"((r)[27]), \
          "=r"((r)[28]), "=r"((r)[29]), "=r"((r)[30]), "=r"((r)[31]) \
        : "r"(ta))

__device__ __forceinline__ void mma_tf32_ss(uint32_t d_tmem, unsigned long long a_desc,
                                            unsigned long long b_desc, uint32_t idesc, int en){
    asm volatile(
        "{\n\t.reg .pred p;\n\tsetp.ne.u32 p, %4, 0;\n\t"
        "tcgen05.mma.cta_group::1.kind::tf32 [%0], %1, %2, %3, p;\n\t}"
        :: "r"(d_tmem), "l"(a_desc), "l"(b_desc), "r"(idesc), "r"((uint32_t)en) : "memory");
}

// SW128 smem descriptor: LBO=1, SBO=64, version=1, layout SW128
__device__ __forceinline__ unsigned long long make_desc(uint32_t addr){
    const unsigned long long base =
        (2ull << 61) | (1ull << 46) | (64ull << 32) | (1ull << 16);
    return base | (((unsigned long long)(addr >> 4)) & 0x3FFF);
}
// idesc: dtype F32, atype/btype TF32 (2), N=64, M=128
#define TF32_IDESC 0x8100910u
#endif  // USE_TC

// ---------------- weight prep: TWN ternarize (+ transposes) ----------------
__global__ void prep_kernel(const float* shallow_w, const float* tex_dw_w, const float* tex_pw_w,
                            const float* exp_dw_w, const float* exp_pw_w,
                            const float* ref1_w, const float* ref2_w, const float* recon_w)
{
    __shared__ float sred[256];
    __shared__ float sred2[256];
    int blk = blockIdx.x, tid = threadIdx.x;
    const float* src; float* dst; int n; int mode; bool quant = true;
    if (blk == 0)       { src = shallow_w; dst = d_sq_t;  n = 1728; mode = 1; }
    else if (blk == 1)  { src = tex_dw_w;  dst = d_texdw; n = 576;  mode = 0; }
    else if (blk == 2)  { src = tex_pw_w;  dst = d_texpw; n = 512;  mode = 0; }
    else if (blk < 11)  { int eb = blk-3;  src = exp_dw_w + eb*576;  dst = d_edw + eb*576;  n = 576;  mode = 0; }
    else if (blk < 19)  { int eb = blk-11; src = exp_pw_w + eb*4096; dst = d_epw + eb*4096; n = 4096; mode = 2; }
    else if (blk == 19) { src = ref1_w; dst = d_ref1; n = 81; mode = 0; }
    else if (blk == 20) { src = ref2_w; dst = d_ref2; n = 81; mode = 0; }
    else                { src = recon_w; dst = d_rect; n = 6912; mode = 3; quant = false; }

    if (!quant){
        for (int i = tid; i < n; i += 256){ int co = i/576, t = i%576; dst[t*12 + co] = src[i]; }
        for (int i = tid; i < 4*BATCH*CCH; i += 256) g_gsum[i] = 0.f;   // init GAP accumulator once
        return;
    }
    float s = 0.f;
    for (int i = tid; i < n; i += 256) s += fabsf(src[i]);
    sred[tid] = s; __syncthreads();
    for (int off = 128; off; off >>= 1){ if (tid < off) sred[tid] += sred[tid+off]; __syncthreads(); }
    float delta = 0.75f * sred[0] / (float)n;
    __syncthreads();
    float s2 = 0.f, c2 = 0.f;
    for (int i = tid; i < n; i += 256){ float a = fabsf(src[i]); if (a > delta){ s2 += a; c2 += 1.f; } }
    sred[tid] = s2; sred2[tid] = c2; __syncthreads();
    for (int off = 128; off; off >>= 1){
        if (tid < off){ sred[tid] += sred[tid+off]; sred2[tid] += sred2[tid+off]; }
        __syncthreads();
    }
    float alpha = sred[0] / fmaxf(sred2[0], 1.f);
    for (int i = tid; i < n; i += 256){
        float w = src[i];
        float q = (fabsf(w) > delta) ? copysignf(alpha, w) : 0.f;
        int j;
        if (mode == 0) j = i;
        else if (mode == 1){ int co = i/27, k = i%27; j = k*64 + co; }
        else {
            int co = i/64, ci = i%64;
#if USE_TC
            // MMA SW128 K-major layout: chunk(ci/32), row co (128B), col ci%32
            uint32_t byte = (uint32_t)(ci>>5)*8192u + sw128((uint32_t)co*128u + (uint32_t)(ci&31)*4u);
            j = (int)(byte >> 2);
#else
            j = ci*64 + co;   // transposed [ci][co]
#endif
        }
        dst[j] = q;
    }
}

// ---------------- shallow conv 3->64 3x3 + relu ----------------
__global__ void __launch_bounds__(256) shallow_kernel(const float* __restrict__ x, const float* __restrict__ sb){
    __shared__ float xs[3*324];
    __shared__ float wt[27*64];
    __shared__ float bs[64];
    int tx = blockIdx.x, ty = blockIdx.y, bb = blockIdx.z;
    int tid = threadIdx.x;
    for (int i = tid; i < 27*64; i += 256) wt[i] = d_sq_t[i];
    if (tid < 64) bs[tid] = sb[tid];
    int x0 = tx*16 - 1, y0 = ty*16 - 1;
    for (int i = tid; i < 3*324; i += 256){
        int c = i/324, r = i%324, yy = r/18, xx = r%18;
        int gy = y0 + yy, gx = x0 + xx;
        float v = 0.f;
        if ((unsigned)gy < 256u && (unsigned)gx < 256u) v = x[(bb*3+c)*HW + gy*256 + gx];
        xs[i] = v;
    }
    __syncthreads();
    int px = tid % 16, py = tid / 16;
    float in[27];
    #pragma unroll
    for (int c = 0; c < 3; c++)
        #pragma unroll
        for (int ky = 0; ky < 3; ky++)
            #pragma unroll
            for (int kx = 0; kx < 3; kx++)
                in[c*9 + ky*3 + kx] = xs[c*324 + (py+ky)*18 + (px+kx)];
    unsigned long long acc[32];
    #pragma unroll
    for (int j = 0; j < 32; j++) acc[j] = 0ull;
    #pragma unroll
    for (int k = 0; k < 27; k++){
        unsigned long long x2 = pack2(in[k], in[k]);
        const unsigned long long* w2 = (const unsigned long long*)(wt + k*64);
        #pragma unroll
        for (int j = 0; j < 32; j++) fma2(acc[j], w2[j], x2);
    }
    int gy = ty*16 + py, gx = tx*16 + px;
    int ob = bb*IMG + gy*256 + gx;
    #pragma unroll
    for (int j = 0; j < 32; j++){
        float a, b2; unpack2(acc[j], a, b2);
        a  = fmaxf(a  + bs[2*j],   0.f);
        b2 = fmaxf(b2 + bs[2*j+1], 0.f);
        g_feat[ob + (2*j)*HW]   = a;
        g_feat[ob + (2*j+1)*HW] = b2;
    }
}

// ---------------- texture encoder + router + argmax ----------------
#define TEX_SMEM ((20736 + 576 + 64 + 512 + 8 + 32 + 4) * 4)
__global__ void __launch_bounds__(256,2) texture_kernel(const float* __restrict__ tdwb, const float* __restrict__ tpwb,
                                                        const float* __restrict__ rw,   const float* __restrict__ rb){
    extern __shared__ float sm[];
    float* fs  = sm;            // 20736
    float* tq  = fs + 20736;    // 576
    float* tb  = tq + 576;      // 64
    float* pq  = tb + 64;       // 512
    float* pb  = pq + 512;      // 8
    float* rws = pb + 8;        // 32
    float* rbs = rws + 32;      // 4
    int tid = threadIdx.x;
    for (int i = tid; i < 576; i += 256) tq[i] = d_texdw[i];
    for (int i = tid; i < 512; i += 256) pq[i] = d_texpw[i];
    if (tid < 64) tb[tid] = tdwb[tid];
    if (tid < 8)  pb[tid] = tpwb[tid];
    if (tid < 32) rws[tid] = rw[tid];
    if (tid < 4)  rbs[tid] = rb[tid];
    int tx = blockIdx.x, ty = blockIdx.y, bb = blockIdx.z;
    int x0 = tx*16 - 1, y0 = ty*16 - 1;
    for (int i = tid; i < 64*324; i += 256){
        int c = i/324, r = i%324, yy = r/18, xx = r%18;
        int gy = y0 + yy, gx = x0 + xx;
        float v = 0.f;
        if ((unsigned)gy < 256u && (unsigned)gx < 256u) v = g_feat[(bb*64+c)*HW + gy*256 + gx];
        fs[i] = v;
    }
    __syncthreads();
    int px = tid % 16, py = tid / 16;
    float a8[8];
    #pragma unroll
    for (int k = 0; k < 8; k++) a8[k] = 0.f;
    for (int c = 0; c < 64; c++){
        const float* h = fs + c*324 + py*18 + px;
        float v = tb[c];
        #pragma unroll
        for (int ky = 0; ky < 3; ky++)
            #pragma unroll
            for (int kx = 0; kx < 3; kx++)
                v += tq[c*9 + ky*3 + kx] * h[ky*18 + kx];
        v = fmaxf(v, 0.f);
        #pragma unroll
        for (int k = 0; k < 8; k++) a8[k] += pq[k*64 + c] * v;
    }
    float s[8];
    #pragma unroll
    for (int k = 0; k < 8; k++) s[k] = 1.f / (1.f + expf(-(a8[k] + pb[k])));
    float best = -1e30f; int be = 0;
    #pragma unroll
    for (int e = 0; e < 4; e++){
        float l = rbs[e];
        #pragma unroll
        for (int k = 0; k < 8; k++) l += rws[e*8 + k] * s[k];
        if (l > best){ best = l; be = e; }
    }
    g_top[bb*HW + (ty*16+py)*256 + (tx*16+px)] = be;
}

// ---------------- res-block part A ----------------
// z = e*4+bb; in = feat (BLK 0) or feat + b0e*y0 (BLK 1, folded at stage time)
#define PA_SMEM ((256 + 18244) * 4)
#if USE_TC
// smem floats from 1KB-aligned base:
//   A [0,8192)  B [8192,12288)  meta@12288 (mbar @ byte 49160)
//   halo [12292,15204)  (8 ch x 364, row stride 20, cols 0..17 used)
//   dqp [15204,15972)   (64 ch x 12, padded weights)
//   db [15972,16036) pb [16036,16100) ys [16100,16164)
//   red overlays halo
// halo staging: 288 units (144 rows split 8+10), vector STS
template<int BLK>
__global__ void __launch_bounds__(256,3) partA_kernel(const float* __restrict__ edwb, const float* __restrict__ epwb){
    extern __shared__ float sm[];
    uint32_t sbase = smem_u32(sm);
    uint32_t sb1k = (sbase + 1023u) & ~1023u;
    float* base = sm + ((sb1k - sbase) >> 2);
    float* halo = base + 12292;
    float* red  = halo;
    float* dqp  = base + 15204;
    float* db   = base + 15972;
    float* pb   = base + 16036;
    float* ys   = base + 16100;
    int tid = threadIdx.x;
    int zz = blockIdx.z;
    int e = zz >> 2, bb = zz & 3;
    int wsel = e*2 + BLK;
    int eb64 = zz * 64;
    const float* srcf = g_feat + (size_t)bb*IMG;
    const float* src1 = BLK ? (g_b0e + (size_t)eb64 * HW) : (const float*)0;
    float* outb = (BLK ? g_b1e : g_b0e) + (size_t)eb64 * HW;
    uint32_t A_addr = sb1k;
    uint32_t B_addr = sb1k + 32768u;
    uint32_t meta   = sb1k + 49152u;
    uint32_t mbar   = sb1k + 49160u;
    if (tid < 32){
        TC_ALLOC(meta, 128);
        TC_RELINQ();
    }
    if (tid == 64) MBAR_INIT(mbar, 1);
    {
        float* Bbuf = base + 8192;
        for (int i = tid; i < 4096; i += 256) Bbuf[i] = d_epw[wsel*4096 + i];
    }
    for (int i = tid; i < 576; i += 256){
        int c9 = i/9, k = i - c9*9;
        dqp[c9*12 + k] = d_edw[wsel*576 + i];
    }
    if (tid < 64){
        db[tid] = edwb[wsel*64 + tid];
        pb[tid] = epwb[wsel*64 + tid];
        ys[tid] = BLK ? g_y0[eb64 + tid] : 0.f;
    }
    __syncthreads();
    uint32_t tmem;
    asm volatile("ld.shared.b32 %0, [%1];" : "=r"(tmem) : "r"(meta));

    int tx = blockIdx.x, ty = blockIdx.y;
    int x0 = tx*16 - 1, y0 = ty*16 - 1;

    // dw strip mapping: q = channel-pair, s = strip (py, 4-px group)
    int q  = tid & 3;
    int s  = tid >> 2;
    int spy = s >> 2;
    int ssx = (s & 3) * 4;

    // halo staging units: u in [0,288): cil=u/36, rem=u%36, yy=rem>>1, half=rem&1
    // half=0: cols 0..7 (8 floats); half=1: cols 8..17 (10 floats)
    auto ldunit = [&](int u, int ch, float* vf, float* vb){
        int cil = u/36, rem = u - cil*36;
        int yy = rem >> 1, half = rem & 1;
        int col0 = half ? 8 : 0;
        int len  = half ? 10 : 8;
        int gy = y0 + yy;
        bool rowok = (unsigned)gy < 256u;
        const float* fp = srcf + (size_t)(ch*8 + cil)*HW + (size_t)gy*256;
        const float* bp = BLK ? (src1 + (size_t)(ch*8 + cil)*HW + (size_t)gy*256) : (const float*)0;
        #pragma unroll
        for (int j = 0; j < 10; j++){
            float f = 0.f, b = 0.f;
            int gx = x0 + col0 + j;
            if (j < len && rowok && (unsigned)gx < 256u){
                f = fp[gx];
                if (BLK) b = bp[gx];
            }
            vf[j] = f;
            if (BLK) vb[j] = b;
        }
    };
    auto stunit = [&](int u, int ch, const float* vf, const float* vb){
        int cil = u/36, rem = u - cil*36;
        int yy = rem >> 1, half = rem & 1;
        float ysc = BLK ? ys[ch*8 + cil] : 0.f;
        float w[10];
        #pragma unroll
        for (int j = 0; j < 10; j++) w[j] = BLK ? (vf[j] + vb[j]*ysc) : vf[j];
        float* dst = halo + cil*364 + yy*20 + (half ? 8 : 0);
        *(float4*)dst       = make_float4(w[0], w[1], w[2], w[3]);
        *(float4*)(dst + 4) = make_float4(w[4], w[5], w[6], w[7]);
        if (half) *(float2*)(dst + 8) = make_float2(w[8], w[9]);
    };

    float pf[10];
    float pbv[BLK ? 10 : 1];
    ldunit(tid, 0, pf, pbv);

    #pragma unroll 1
    for (int ch = 0; ch < 8; ch++){
        __syncthreads();   // prior chunk's halo LDS complete
        stunit(tid, ch, pf, pbv);
        if (tid < 32){
            float tf[10];
            float tb2[BLK ? 10 : 1];
            ldunit(tid + 256, ch, tf, tb2);
            stunit(tid + 256, ch, tf, tb2);
        }
        if (ch < 7) ldunit(tid, ch+1, pf, pbv);   // prefetch next chunk across barrier+compute
        __syncthreads();
        if (ch == 4){   // A (ci 0-31) fully written -> issue MMA batch 0
            FENCE_ASYNC();
            if (tid < 32 && elect_one_pred()){
                unsigned long long a0 = make_desc(A_addr);
                unsigned long long b0d = make_desc(B_addr);
                #pragma unroll
                for (int t = 0; t < 2; t++)
                    #pragma unroll
                    for (int k = 0; k < 4; k++)
                        mma_tf32_ss(tmem + 64*t, a0 + t*1024 + k*2, b0d + k*2, TF32_IDESC, k > 0);
                TC_COMMIT(mbar);
            }
        }
        // dw conv: 2 channels x 4 pixels per thread, vectorized LDS
        float o[8];
        #pragma unroll
        for (int cc = 0; cc < 2; cc++){
            int cil = q*2 + cc;
            int cg = ch*8 + cil;
            const float* hb = halo + cil*364;
            const float4* wp = (const float4*)(dqp + cg*12);
            float4 wA = wp[0];            // w0..w3
            float4 wB = wp[1];            // w4..w7
            float4 wC = wp[2];            // w8 (+pad)
            float bias = db[cg];
            float o0 = bias, o1 = bias, o2 = bias, o3 = bias;
            #pragma unroll
            for (int ky = 0; ky < 3; ky++){
                const float* rp = hb + (spy + ky)*20 + ssx;
                float4 a = *(const float4*)rp;
                float2 b2 = *(const float2*)(rp + 4);
                float w0, w1, w2;
                if (ky == 0){ w0 = wA.x; w1 = wA.y; w2 = wA.z; }
                else if (ky == 1){ w0 = wA.w; w1 = wB.x; w2 = wB.y; }
                else { w0 = wB.z; w1 = wB.w; w2 = wC.x; }
                o0 += w0*a.x + w1*a.y + w2*a.z;
                o1 += w0*a.y + w1*a.z + w2*a.w;
                o2 += w0*a.z + w1*a.w + w2*b2.x;
                o3 += w0*a.w + w1*b2.x + w2*b2.y;
            }
            o[cc*4+0] = fmaxf(o0, 0.f);
            o[cc*4+1] = fmaxf(o1, 0.f);
            o[cc*4+2] = fmaxf(o2, 0.f);
            o[cc*4+3] = fmaxf(o3, 0.f);
        }
        if (ch == 4) MBAR_WAIT(mbar, 0);   // batch-0 MMA done before A overwrite
        // A-tile STS: 4 pixels, channel pair -> STS.64 each
        #pragma unroll
        for (int j = 0; j < 4; j++){
            int p = spy*16 + ssx + j;
            uint32_t ad = A_addr + sw128((uint32_t)p*128u + (uint32_t)((ch & 3)*8 + q*2)*4u);
            asm volatile("st.shared.v2.b32 [%0], {%1,%2};"
                :: "r"(ad), "r"(__float_as_uint(o[j])), "r"(__float_as_uint(o[4+j])) : "memory");
        }
    }
    __syncthreads();   // all A-STS done; halo dead -> red usable

    FENCE_ASYNC();
    if (tid < 32 && elect_one_pred()){
        unsigned long long a0 = make_desc(A_addr);
        unsigned long long b1d = make_desc(B_addr + 8192u);
        #pragma unroll
        for (int t = 0; t < 2; t++)
            #pragma unroll
            for (int k = 0; k < 4; k++)
                mma_tf32_ss(tmem + 64*t, a0 + t*1024 + k*2, b1d + k*2, TF32_IDESC, 1);
        TC_COMMIT(mbar);
    }
    MBAR_WAIT(mbar, 1);
    TC_FENCE_AFTER();

    int px_ = tid & 15, py_ = tid >> 4;
    int gy = ty*16 + py_, gx = tx*16 + px_;
    size_t ob = (size_t)gy*256 + gx;
    int lane = tid & 31, warp = tid >> 5;
    #pragma unroll 1
    for (int hh = 0; hh < 2; hh++){
        uint32_t dr[32];
        TC_LD_X32(dr, tmem + 64*(tid >> 7) + hh*32);
        TC_WAIT_LD();
        #pragma unroll
        for (int c2 = 0; c2 < 32; c2++){
            int c = hh*32 + c2;
            float a = __uint_as_float(dr[c2]) + pb[c];
            outb[(size_t)c*HW + ob] = a;
            float ra = a;
            ra += __shfl_xor_sync(0xffffffffu, ra, 16);
            ra += __shfl_xor_sync(0xffffffffu, ra, 8);
            ra += __shfl_xor_sync(0xffffffffu, ra, 4);
            ra += __shfl_xor_sync(0xffffffffu, ra, 2);
            ra += __shfl_xor_sync(0xffffffffu, ra, 1);
            if (lane == 0) red[c*8 + warp] = ra;
        }
    }
    __syncthreads();
    if (tid < 64){
        float ssum = 0.f;
        #pragma unroll
        for (int i = 0; i < 8; i++) ssum += red[tid*8 + i];
        atomicAdd(&g_gsum[eb64 + tid], ssum);
    }
    if (tid == 64) MBAR_INVAL(mbar);
    if (tid < 32) TC_DEALLOC(tmem, 128);
}
#else
// fallback (non-sm_103a pass): R7 f32x2 implementation
template<int BLK>
__global__ void __launch_bounds__(256,3) partA_kernel(const float* __restrict__ edwb, const float* __restrict__ epwb){
    extern __shared__ float sm[];
    uint32_t sbase = smem_u32(sm);
    uint32_t sb1k = (sbase + 1023u) & ~1023u;
    float* base = sm + ((sb1k - sbase) >> 2);
    float* Bbuf = base + 8192;
    float* halo = base + 12292;
    float* red  = halo;
    float* dq   = base + 17476;
    float* db   = base + 18052;
    float* pb   = base + 18116;
    float* ys   = base + 18180;
    int tid = threadIdx.x;
    int zz = blockIdx.z;
    int e = zz >> 2, bb = zz & 3;
    int wsel = e*2 + BLK;
    int eb64 = zz * 64;
    const float* srcf = g_feat + (size_t)bb*IMG;
    const float* src1 = BLK ? (g_b0e + (size_t)eb64 * HW) : (const float*)0;
    float* outb = (BLK ? g_b1e : g_b0e) + (size_t)eb64 * HW;
    for (int i = tid; i < 4096; i += 256) Bbuf[i] = d_epw[wsel*4096 + i];
    for (int i = tid; i < 576;  i += 256) dq[i]   = d_edw[wsel*576 + i];
    if (tid < 64){
        db[tid] = edwb[wsel*64 + tid];
        pb[tid] = epwb[wsel*64 + tid];
        ys[tid] = BLK ? g_y0[eb64 + tid] : 0.f;
    }
    __syncthreads();
    int tx = blockIdx.x, ty = blockIdx.y;
    int x0 = tx*16 - 1, y0 = ty*16 - 1;
    int px_ = tid & 15, py_ = tid >> 4;
    float sf[11];
    float sbv[BLK ? 11 : 1];
    auto stage = [&](int ch){
        const float* fp = srcf + (size_t)(ch*8)*HW;
        const float* bp = BLK ? (src1 + (size_t)(ch*8)*HW) : (const float*)0;
        #pragma unroll
        for (int k = 0; k < 11; k++){
            int i = tid + k*256;
            float f = 0.f, b = 0.f;
            if (i < 2592){
                int cil = i / 324;
                int r = i - cil*324;
                int yy = r / 18;
                int xx = r - yy*18;
                int gy = y0 + yy, gx = x0 + xx;
                if ((unsigned)gy < 256u && (unsigned)gx < 256u){
                    int off = cil*HW + gy*256 + gx;
                    f = fp[off];
                    if (BLK) b = bp[off];
                }
            }
            sf[k] = f;
            if (BLK) sbv[k] = b;
        }
    };
    unsigned long long acc[32];
    #pragma unroll
    for (int j = 0; j < 32; j++) acc[j] = 0ull;
    stage(0);
    #pragma unroll 1
    for (int ch = 0; ch < 8; ch++){
        float* hbuf = halo + (ch & 1)*2592;
        #pragma unroll
        for (int k = 0; k < 11; k++){
            int i = tid + k*256;
            if (i < 2592){
                float v = sf[k];
                if (BLK){ int cil = i/324; v += sbv[k]*ys[ch*8 + cil]; }
                hbuf[i] = v;
            }
        }
        if (ch < 7) stage(ch+1);
        __syncthreads();
        #pragma unroll
        for (int u = 0; u < 8; u++){
            int cg = ch*8 + u;
            const float* h = hbuf + u*324 + py_*18 + px_;
            const float* w9 = dq + cg*9;
            float v = db[cg];
            #pragma unroll
            for (int ky = 0; ky < 3; ky++)
                #pragma unroll
                for (int kx = 0; kx < 3; kx++)
                    v += w9[ky*3 + kx] * h[ky*18 + kx];
            v = fmaxf(v, 0.f);
            unsigned long long x2 = pack2(v, v);
            const ulonglong2* w4 = (const ulonglong2*)(Bbuf + cg*64);
            #pragma unroll
            for (int j = 0; j < 16; j++){
                ulonglong2 w = w4[j];
                fma2(acc[2*j],   w.x, x2);
                fma2(acc[2*j+1], w.y, x2);
            }
        }
        __syncthreads();
    }
    int gy = ty*16 + py_, gx = tx*16 + px_;
    size_t ob = (size_t)gy*256 + gx;
    int lane = tid & 31, warp = tid >> 5;
    #pragma unroll
    for (int j = 0; j < 32; j++){
        float a, b2; unpack2(acc[j], a, b2);
        a  += pb[2*j];
        b2 += pb[2*j+1];
        outb[(size_t)(2*j)*HW + ob]   = a;
        outb[(size_t)(2*j+1)*HW + ob] = b2;
        float ra = a, rb2 = b2;
        ra  += __shfl_xor_sync(0xffffffffu, ra, 16);
        ra  += __shfl_xor_sync(0xffffffffu, ra, 8);
        ra  += __shfl_xor_sync(0xffffffffu, ra, 4);
        ra  += __shfl_xor_sync(0xffffffffu, ra, 2);
        ra  += __shfl_xor_sync(0xffffffffu, ra, 1);
        rb2 += __shfl_xor_sync(0xffffffffu, rb2, 16);
        rb2 += __shfl_xor_sync(0xffffffffu, rb2, 8);
        rb2 += __shfl_xor_sync(0xffffffffu, rb2, 4);
        rb2 += __shfl_xor_sync(0xffffffffu, rb2, 2);
        rb2 += __shfl_xor_sync(0xffffffffu, rb2, 1);
        if (lane == 0){ red[(2*j)*8 + warp] = ra; red[(2*j+1)*8 + warp] = rb2; }
    }
    __syncthreads();
    if (tid < 64){
        float s = 0.f;
        #pragma unroll
        for (int i = 0; i < 8; i++) s += red[tid*8 + i];
        atomicAdd(&g_gsum[eb64 + tid], s);
    }
}
#endif

// ---------------- channel attention (one block per expert) ----------------
__global__ void y_kernel(const float* __restrict__ fc1_all, const float* __restrict__ fc2_all, int blk){
    __shared__ float m[256];
    __shared__ float h1[64];
    int tid = threadIdx.x;
    int e = blockIdx.x;
    const float* fc1 = fc1_all + (e*2 + blk)*1024;
    const float* fc2 = fc2_all + (e*2 + blk)*1024;
    int base = e*256;
    m[tid] = g_gsum[base + tid] * (1.f / 65536.f);
    __syncthreads();
    g_gsum[base + tid] = 0.f;
    if (tid < 64){
        int b = tid / 16, j = tid % 16;
        float s = 0.f;
        for (int c = 0; c < 64; c++) s += m[b*64 + c] * fc1[j*64 + c];
        h1[tid] = fmaxf(s, 0.f);
    }
    __syncthreads();
    int b = tid / 64, co = tid % 64;
    float s = 0.f;
    #pragma unroll
    for (int j = 0; j < 16; j++) s += h1[b*16 + j] * fc2[co*16 + j];
    float yv = 1.f / (1.f + expf(-s));
    if (blk) g_y1[base + tid] = yv; else g_y0[base + tid] = yv;
}

// ---------------- recon (FUSED MoE select) 64->12 3x3 + pixel shuffle + bilinear ----------------
// moe value materialized on the fly: feat + b0e*y0 + b1e*y1 with per-pixel expert
#define RC_SMEM ((20736 + 972 + 6912 + 12 + 256 + 256 + 324) * 4)
__global__ void __launch_bounds__(256) recon_kernel(const float* __restrict__ x, const float* __restrict__ rcb){
    extern __shared__ float sm[];
    float* halo = sm;            // 20736
    float* xs   = halo + 20736;  // 972
    float* wt   = xs + 972;      // 6912
    float* rb   = wt + 6912;     // 12
    float* ys0s = rb + 12;       // 256 (4 experts x 64)
    float* ys1s = ys0s + 256;    // 256
    int*   tops = (int*)(ys1s + 256);  // 324
    int tid = threadIdx.x;
    int tx = blockIdx.x, ty = blockIdx.y, bb = blockIdx.z;
    int x0 = tx*16 - 1, y0 = ty*16 - 1;
    for (int i = tid; i < 6912; i += 256) wt[i] = d_rect[i];
    if (tid < 12) rb[tid] = rcb[tid];
    if (tid < 256){
        int ei = tid >> 6, c = tid & 63;
        ys0s[tid] = g_y0[(ei*4 + bb)*64 + c];
        ys1s[tid] = g_y1[(ei*4 + bb)*64 + c];
    }
    for (int i = tid; i < 324; i += 256){
        int yy = i/18, xx = i%18;
        int gy = y0 + yy, gx = x0 + xx;
        int t = 0;
        if ((unsigned)gy < 256u && (unsigned)gx < 256u) t = g_top[bb*HW + gy*256 + gx];
        tops[i] = t;
    }
    __syncthreads();
    for (int i = tid; i < 64*324; i += 256){
        int c = i/324, r = i%324, yy = r/18, xx = r%18;
        int gy = y0 + yy, gx = x0 + xx;
        float v = 0.f;
        if ((unsigned)gy < 256u && (unsigned)gx < 256u){
            int sp = gy*256 + gx;
            int ei = tops[r];
            size_t eb = (size_t)((ei*4 + bb)*64 + c);
            v = g_feat[(bb*64+c)*HW + sp]
              + g_b0e[eb*HW + sp] * ys0s[ei*64 + c]
              + g_b1e[eb*HW + sp] * ys1s[ei*64 + c];
        }
        halo[i] = v;
    }
    for (int i = tid; i < 3*324; i += 256){
        int c = i/324, r = i%324, yy = r/18, xx = r%18;
        int gy = min(max(y0 + yy, 0), 255), gx = min(max(x0 + xx, 0), 255);
        xs[i] = x[(bb*3+c)*HW + gy*256 + gx];
    }
    __syncthreads();
    int px = tid % 16, py = tid / 16;
    unsigned long long acc[6];
    #pragma unroll
    for (int j = 0; j < 6; j++) acc[j] = 0ull;
    for (int ci = 0; ci < 64; ci++){
        const float* h = halo + ci*324 + py*18 + px;
        #pragma unroll
        for (int k = 0; k < 9; k++){
            float xv = h[(k/3)*18 + (k%3)];
            unsigned long long x2 = pack2(xv, xv);
            const unsigned long long* w2 = (const unsigned long long*)(wt + (ci*9 + k)*12);
            ulonglong2 wa = *(const ulonglong2*)w2;
            unsigned long long wc = w2[2];
            fma2(acc[0], wa.x, x2);
            fma2(acc[1], wa.y, x2);
            fma2(acc[2], wc,   x2);
            ulonglong2 wb = *(const ulonglong2*)(w2 + 3);
            unsigned long long wd = w2[5];
            fma2(acc[3], wb.x, x2);
            fma2(acc[4], wb.y, x2);
            fma2(acc[5], wd,   x2);
        }
    }
    float cv[12];
    #pragma unroll
    for (int j = 0; j < 6; j++){
        float a, b2; unpack2(acc[j], a, b2);
        cv[2*j]   = a  + rb[2*j];
        cv[2*j+1] = b2 + rb[2*j+1];
    }
    int gy = ty*16 + py, gx = tx*16 + px;
    #pragma unroll
    for (int r1 = 0; r1 < 2; r1++){
        int ly0 = r1 ? py+1 : py;
        int ly1 = ly0 + 1;
        float wy0 = r1 ? 0.75f : 0.25f;
        float wy1 = 1.f - wy0;
        #pragma unroll
        for (int r2 = 0; r2 < 2; r2++){
            int lx0 = r2 ? px+1 : px;
            int lx1 = lx0 + 1;
            float wx0 = r2 ? 0.75f : 0.25f;
            float wx1 = 1.f - wx0;
            int oh = 2*gy + r1, ow = 2*gx + r2;
            #pragma unroll
            for (int co = 0; co < 3; co++){
                const float* xc = xs + co*324;
                float up = wy0*(wx0*xc[ly0*18+lx0] + wx1*xc[ly0*18+lx1])
                         + wy1*(wx0*xc[ly1*18+lx0] + wx1*xc[ly1*18+lx1]);
                int ch = co*4 + r1*2 + r2;
                g_sr[(bb*3+co)*262144 + oh*512 + ow] = cv[ch] + up;
            }
        }
    }
}

// ---------------- refinement: out = sr + conv2(relu(conv1(sr))) ----------------
__global__ void __launch_bounds__(256) ref_kernel(const float* __restrict__ b1, const float* __restrict__ b2,
                                                  float* __restrict__ out){
    __shared__ float srh[3*432];   // 3 x 12 x 36
    __shared__ float th[3*340];    // 3 x 10 x 34
    __shared__ float w1[81], w2[81], sb1[3], sb2[3];
    int tid = threadIdx.x;
    if (tid < 81){ w1[tid] = d_ref1[tid]; w2[tid] = d_ref2[tid]; }
    if (tid < 3){ sb1[tid] = b1[tid]; sb2[tid] = b2[tid]; }
    int tx = blockIdx.x, ty = blockIdx.y, bb = blockIdx.z;
    int X0 = tx*32, Y0 = ty*8;
    for (int i = tid; i < 3*432; i += 256){
        int c = i/432, r = i%432, yy = r/36, xx = r%36;
        int gy = Y0 + yy - 2, gx = X0 + xx - 2;
        float v = 0.f;
        if ((unsigned)gy < 512u && (unsigned)gx < 512u) v = g_sr[(bb*3+c)*262144 + gy*512 + gx];
        srh[i] = v;
    }
    __syncthreads();
    for (int i = tid; i < 3*340; i += 256){
        int c = i/340, r = i%340, yy = r/34, xx = r%34;
        int gy = Y0 + yy - 1, gx = X0 + xx - 1;
        float v = 0.f;
        if ((unsigned)gy < 512u && (unsigned)gx < 512u){
            v = sb1[c];
            #pragma unroll
            for (int ci = 0; ci < 3; ci++)
                #pragma unroll
                for (int ky = 0; ky < 3; ky++)
                    #pragma unroll
                    for (int kx = 0; kx < 3; kx++)
                        v += w1[(c*3+ci)*9 + ky*3 + kx] * srh[ci*432 + (yy+ky)*36 + (xx+kx)];
            v = fmaxf(v, 0.f);
        }
        th[i] = v;
    }
    __syncthreads();
    int px = tid % 32, py = tid / 32;
    int oh = Y0 + py, ow = X0 + px;
    #pragma unroll
    for (int co = 0; co < 3; co++){
        float v = sb2[co];
        #pragma unroll
        for (int ci = 0; ci < 3; ci++)
            #pragma unroll
            for (int ky = 0; ky < 3; ky++)
                #pragma unroll
                for (int kx = 0; kx < 3; kx++)
                    v += w2[(co*3+ci)*9 + ky*3 + kx] * th[ci*340 + (py+ky)*34 + (px+kx)];
        out[(bb*3+co)*262144 + oh*512 + ow] = srh[co*432 + (py+2)*36 + (px+2)] + v;
    }
}

// ---------------- launch ----------------
extern "C" void kernel_launch(void* const* d_in, const int* in_sizes, int n_in,
                              void* d_out, int out_size){
    const float* x         = (const float*)d_in[0];
    const float* shallow_w = (const float*)d_in[1];
    const float* shallow_b = (const float*)d_in[2];
    const float* tex_dw_w  = (const float*)d_in[3];
    const float* tex_dw_b  = (const float*)d_in[4];
    const float* tex_pw_w  = (const float*)d_in[5];
    const float* tex_pw_b  = (const float*)d_in[6];
    const float* router_w  = (const float*)d_in[7];
    const float* router_b  = (const float*)d_in[8];
    const float* exp_dw_w  = (const float*)d_in[9];
    const float* exp_dw_b  = (const float*)d_in[10];
    const float* exp_pw_w  = (const float*)d_in[11];
    const float* exp_pw_b  = (const float*)d_in[12];
    const float* fc1       = (const float*)d_in[13];
    const float* fc2       = (const float*)d_in[14];
    const float* recon_w   = (const float*)d_in[15];
    const float* recon_b   = (const float*)d_in[16];
    const float* ref1_w    = (const float*)d_in[17];
    const float* ref1_b    = (const float*)d_in[18];
    const float* ref2_w    = (const float*)d_in[19];
    const float* ref2_b    = (const float*)d_in[20];
    float* out = (float*)d_out;

    cudaFuncSetAttribute(texture_kernel,  cudaFuncAttributeMaxDynamicSharedMemorySize, TEX_SMEM);
    cudaFuncSetAttribute(partA_kernel<0>, cudaFuncAttributeMaxDynamicSharedMemorySize, PA_SMEM);
    cudaFuncSetAttribute(partA_kernel<1>, cudaFuncAttributeMaxDynamicSharedMemorySize, PA_SMEM);
    cudaFuncSetAttribute(recon_kernel,    cudaFuncAttributeMaxDynamicSharedMemorySize, RC_SMEM);

    prep_kernel<<<22, 256>>>(shallow_w, tex_dw_w, tex_pw_w, exp_dw_w, exp_pw_w, ref1_w, ref2_w, recon_w);

    dim3 g16(16, 16, 4);
    shallow_kernel<<<g16, 256>>>(x, shallow_b);
    texture_kernel<<<g16, 256, TEX_SMEM>>>(tex_dw_b, tex_pw_b, router_w, router_b);

    dim3 gA(16, 16, 16);   // z = e*4 + batch
    partA_kernel<0><<<gA, 256, PA_SMEM>>>(exp_dw_b, exp_pw_b);
    y_kernel<<<4, 256>>>(fc1, fc2, 0);
    partA_kernel<1><<<gA, 256, PA_SMEM>>>(exp_dw_b, exp_pw_b);
    y_kernel<<<4, 256>>>(fc1, fc2, 1);

    recon_kernel<<<g16, 256, RC_SMEM>>>(x, recon_b);

    dim3 gref(16, 64, 4);
    ref_kernel<<<gref, 256>>>(ref1_b, ref2_b, out);
}

// round 10
// speedup vs baseline: 1.4924x; 1.4924x over previous
#include <cuda_runtime.h>
#include <math.h>
#include <stdint.h>

#if (defined(__CUDA_ARCH_FEAT_SM103_ALL) || (defined(__CUDA_ARCH_SPECIFIC__) && (__CUDA_ARCH__ == 1030)))
#define USE_TC 1
#else
#define USE_TC 0
#endif

#define BATCH 4
#define CCH 64
#define HH 256
#define WWI 256
#define HW (HH*WWI)
#define IMG (CCH*HW)
#define NPIX (BATCH*HW)

// ---------------- scratch (device globals, no allocs) ----------------
__device__ float g_feat[BATCH*CCH*HW];
__device__ float g_b0e[4*BATCH*CCH*HW];   // per-expert block-0 residual branch
__device__ float g_b1e[4*BATCH*CCH*HW];   // per-expert block-1 residual branch
__device__ float g_moe[BATCH*CCH*HW];
__device__ float g_sr[BATCH*3*512*512];
__device__ int   g_top[NPIX];
__device__ float g_gsum[4*BATCH*CCH];     // [e][b][c]
__device__ float g_y0[4*BATCH*CCH];
__device__ float g_y1[4*BATCH*CCH];
// quantized / transposed weights
__device__ float d_sq_t[27*64];     // shallow, transposed [k][co]
__device__ float d_texdw[576];
__device__ float d_texpw[512];
__device__ float d_edw[8*576];
__device__ float d_epw[8*4096];     // pw weights: SW128 MMA layout (TC) or [ci][co] (fallback)
__device__ float d_ref1[81];
__device__ float d_ref2[81];
__device__ float d_rect[576*12];    // recon transposed [ci*9+k][co]

// ---------------- f32x2 helpers ----------------
__device__ __forceinline__ unsigned long long pack2(float a, float b){
    unsigned long long r;
    asm("mov.b64 %0, {%1, %2};" : "=l"(r) : "r"(__float_as_uint(a)), "r"(__float_as_uint(b)));
    return r;
}
__device__ __forceinline__ void unpack2(unsigned long long v, float& a, float& b){
    unsigned int x, y;
    asm("mov.b64 {%0, %1}, %2;" : "=r"(x), "=r"(y) : "l"(v));
    a = __uint_as_float(x); b = __uint_as_float(y);
}
__device__ __forceinline__ void fma2(unsigned long long& acc, unsigned long long w, unsigned long long x){
    asm("fma.rn.f32x2 %0, %1, %2, %0;" : "+l"(acc) : "l"(w), "l"(x));
}

__device__ __forceinline__ uint32_t smem_u32(const void* p){
    uint32_t a;
    asm("{ .reg .u64 t; cvta.to.shared.u64 t, %1; cvt.u32.u64 %0, t; }" : "=r"(a) : "l"(p));
    return a;
}

__host__ __device__ __forceinline__ uint32_t sw128(uint32_t off){ return off ^ ((off >> 3) & 0x70); }

#if USE_TC
// ---------------- tcgen05 / mbarrier helpers (sm_103a-specific pass only) ----------------
__device__ __forceinline__ uint32_t elect_one_pred(){
    uint32_t pred;
    asm volatile("{\n\t.reg .pred p;\n\telect.sync _|p, 0xFFFFFFFF;\n\tselp.b32 %0, 1, 0, p;\n\t}" : "=r"(pred));
    return pred;
}
#define TC_ALLOC(sa, n)   asm volatile("tcgen05.alloc.cta_group::1.sync.aligned.shared::cta.b32 [%0], %1;" :: "r"(sa), "r"((uint32_t)(n)) : "memory")
#define TC_DEALLOC(t, n)  asm volatile("tcgen05.dealloc.cta_group::1.sync.aligned.b32 %0, %1;" :: "r"(t), "r"((uint32_t)(n)))
#define TC_RELINQ()       asm volatile("tcgen05.relinquish_alloc_permit.cta_group::1.sync.aligned;")
#define TC_COMMIT(mb)     asm volatile("tcgen05.commit.cta_group::1.mbarrier::arrive::one.shared::cluster.b64 [%0];" :: "r"(mb) : "memory")
#define TC_FENCE_AFTER()  asm volatile("tcgen05.fence::after_thread_sync;" ::: "memory")
#define TC_WAIT_LD()      asm volatile("tcgen05.wait::ld.sync.aligned;" ::: "memory")
#define FENCE_ASYNC()     asm volatile("fence.proxy.async.shared::cta;" ::: "memory")
#define MBAR_INIT(mb, c)  asm volatile("mbarrier.init.shared.b64 [%0], %1;" :: "r"(mb), "r"((uint32_t)(c)) : "memory")
#define MBAR_INVAL(mb)    asm volatile("mbarrier.inval.shared.b64 [%0];" :: "r"(mb) : "memory")
#define MBAR_WAIT(mb, ph) do { \
    uint32_t _mb = (mb); uint32_t _p = (ph); uint32_t _done; \
    asm volatile("{\n\t.reg .pred p;\n\tmbarrier.try_wait.parity.acquire.cta.shared::cta.b64 p, [%1], %2;\n\tselp.b32 %0, 1, 0, p;\n\t}" \
        : "=r"(_done) : "r"(_mb), "r"(_p) : "memory"); \
    if (!_done){ \
        asm volatile("{\n\t.reg .pred P1;\n\tWL_%=:\n\tmbarrier.try_wait.parity.acquire.cta.shared::cta.b64 P1, [%0], %1, 0x989680;\n\t@P1 bra.uni WD_%=;\n\tbra.uni WL_%=;\n\tWD_%=:\n\t}" \
            :: "r"(_mb), "r"(_p) : "memory"); \
    } \
} while(0)
#define TC_LD_X32(r, ta) \
    asm volatile("tcgen05.ld.sync.aligned.32x32b.x32.b32 " \
        "{%0, %1, %2, %3, %4, %5, %6, %7, %8, %9, %10, %11, %12, %13, %14, %15, " \
        " %16, %17, %18, %19, %20, %21, %22, %23, %24, %25, %26, %27, %28, %29, %30, %31}, [%32];" \
        : "=r"((r)[0]),  "=r"((r)[1]),  "=r"((r)[2]),  "=r"((r)[3]), \
          "=r"((r)[4]),  "=r"((r)[5]),  "=r"((r)[6]),  "=r"((r)[7]), \
          "=r"((r)[8]),  "=r"((r)[9]),  "=r"((r)[10]), "=r"((r)[11]), \
          "=r"((r)[12]), "=r"((r)[13]), "=r"((r)[14]), "=r"((r)[15]), \
          "=r"((r)[16]), "=r"((r)[17]), "=r"((r)[18]), "=r"((r)[19]), \
          "=r"((r)[20]), "=r"((r)[21]), "=r"((r)[22]), "=r"((r)[23]), \
          "=r"((r)[24]), "=r"((r)[25]), "=r"((r)[26]), "=r"((r)[27]), \
          "=r"((r)[28]), "=r"((r)[29]), "=r"((r)[30]), "=r"((r)[31]) \
        : "r"(ta))

__device__ __forceinline__ void mma_tf32_ss(uint32_t d_tmem, unsigned long long a_desc,
                                            unsigned long long b_desc, uint32_t idesc, int en){
    asm volatile(
        "{\n\t.reg .pred p;\n\tsetp.ne.u32 p, %4, 0;\n\t"
        "tcgen05.mma.cta_group::1.kind::tf32 [%0], %1, %2, %3, p;\n\t}"
        :: "r"(d_tmem), "l"(a_desc), "l"(b_desc), "r"(idesc), "r"((uint32_t)en) : "memory");
}

// SW128 smem descriptor: LBO=1, SBO=64, version=1, layout SW128
__device__ __forceinline__ unsigned long long make_desc(uint32_t addr){
    const unsigned long long base =
        (2ull << 61) | (1ull << 46) | (64ull << 32) | (1ull << 16);
    return base | (((unsigned long long)(addr >> 4)) & 0x3FFF);
}
// idesc: dtype F32, atype/btype TF32 (2), N=64, M=128
#define TF32_IDESC 0x8100910u
#endif  // USE_TC

// ---------------- weight prep: TWN ternarize (+ transposes) ----------------
__global__ void prep_kernel(const float* shallow_w, const float* tex_dw_w, const float* tex_pw_w,
                            const float* exp_dw_w, const float* exp_pw_w,
                            const float* ref1_w, const float* ref2_w, const float* recon_w)
{
    __shared__ float sred[256];
    __shared__ float sred2[256];
    int blk = blockIdx.x, tid = threadIdx.x;
    const float* src; float* dst; int n; int mode; bool quant = true;
    if (blk == 0)       { src = shallow_w; dst = d_sq_t;  n = 1728; mode = 1; }
    else if (blk == 1)  { src = tex_dw_w;  dst = d_texdw; n = 576;  mode = 0; }
    else if (blk == 2)  { src = tex_pw_w;  dst = d_texpw; n = 512;  mode = 0; }
    else if (blk < 11)  { int eb = blk-3;  src = exp_dw_w + eb*576;  dst = d_edw + eb*576;  n = 576;  mode = 0; }
    else if (blk < 19)  { int eb = blk-11; src = exp_pw_w + eb*4096; dst = d_epw + eb*4096; n = 4096; mode = 2; }
    else if (blk == 19) { src = ref1_w; dst = d_ref1; n = 81; mode = 0; }
    else if (blk == 20) { src = ref2_w; dst = d_ref2; n = 81; mode = 0; }
    else                { src = recon_w; dst = d_rect; n = 6912; mode = 3; quant = false; }

    if (!quant){
        for (int i = tid; i < n; i += 256){ int co = i/576, t = i%576; dst[t*12 + co] = src[i]; }
        for (int i = tid; i < 4*BATCH*CCH; i += 256) g_gsum[i] = 0.f;   // init GAP accumulator once
        return;
    }
    float s = 0.f;
    for (int i = tid; i < n; i += 256) s += fabsf(src[i]);
    sred[tid] = s; __syncthreads();
    for (int off = 128; off; off >>= 1){ if (tid < off) sred[tid] += sred[tid+off]; __syncthreads(); }
    float delta = 0.75f * sred[0] / (float)n;
    __syncthreads();
    float s2 = 0.f, c2 = 0.f;
    for (int i = tid; i < n; i += 256){ float a = fabsf(src[i]); if (a > delta){ s2 += a; c2 += 1.f; } }
    sred[tid] = s2; sred2[tid] = c2; __syncthreads();
    for (int off = 128; off; off >>= 1){
        if (tid < off){ sred[tid] += sred[tid+off]; sred2[tid] += sred2[tid+off]; }
        __syncthreads();
    }
    float alpha = sred[0] / fmaxf(sred2[0], 1.f);
    for (int i = tid; i < n; i += 256){
        float w = src[i];
        float q = (fabsf(w) > delta) ? copysignf(alpha, w) : 0.f;
        int j;
        if (mode == 0) j = i;
        else if (mode == 1){ int co = i/27, k = i%27; j = k*64 + co; }
        else {
            int co = i/64, ci = i%64;
#if USE_TC
            // MMA SW128 K-major layout: chunk(ci/32), row co (128B), col ci%32
            uint32_t byte = (uint32_t)(ci>>5)*8192u + sw128((uint32_t)co*128u + (uint32_t)(ci&31)*4u);
            j = (int)(byte >> 2);
#else
            j = ci*64 + co;   // transposed [ci][co]
#endif
        }
        dst[j] = q;
    }
}

// ---------------- FUSED shallow conv + texture encoder + router + argmax ----------------
// feat computed on the full 18x18 halo in smem (1.27x recompute), texture reads it
// in-place: deletes texture's 268MB g_feat re-read and one launch.
#define ST_SMEM ((20736 + 1200 + 1728 + 576 + 64 + 512 + 8 + 32 + 4 + 64) * 4)
__global__ void __launch_bounds__(256,2) shallow_tex_kernel(
    const float* __restrict__ x, const float* __restrict__ sb,
    const float* __restrict__ tdwb, const float* __restrict__ tpwb,
    const float* __restrict__ rw,   const float* __restrict__ rb){
    extern __shared__ float sm[];
    float* fs  = sm;             // 20736 (64 x 324)
    float* xs  = fs + 20736;     // 1200 (3 x 400: 20x20 x-halo)
    float* wt  = xs + 1200;      // 1728 (shallow, [k][co])
    float* tq  = wt + 1728;      // 576
    float* tb  = tq + 576;       // 64
    float* pq  = tb + 64;        // 512
    float* pb  = pq + 512;       // 8
    float* rws = pb + 8;         // 32
    float* rbs = rws + 32;       // 4
    float* bs  = rbs + 4;        // 64
    int tid = threadIdx.x;
    int tx = blockIdx.x, ty = blockIdx.y, bb = blockIdx.z;
    for (int i = tid; i < 1728; i += 256) wt[i] = d_sq_t[i];
    for (int i = tid; i < 576;  i += 256) tq[i] = d_texdw[i];
    for (int i = tid; i < 512;  i += 256) pq[i] = d_texpw[i];
    if (tid < 64) tb[tid] = tdwb[tid];
    if (tid < 8)  pb[tid] = tpwb[tid];
    if (tid < 32) rws[tid] = rw[tid];
    if (tid < 4)  rbs[tid] = rb[tid];
    if (tid < 64) bs[tid] = sb[tid];
    int X0 = tx*16 - 2, Y0 = ty*16 - 2;     // x-halo origin (feat halo origin - 1)
    for (int i = tid; i < 1200; i += 256){
        int c = i/400, r = i%400, yy = r/20, xx = r%20;
        int gy = Y0 + yy, gx = X0 + xx;
        float v = 0.f;
        if ((unsigned)gy < 256u && (unsigned)gx < 256u) v = x[(bb*3+c)*HW + gy*256 + gx];
        xs[i] = v;
    }
    __syncthreads();
    // feat on the 18x18 halo; interior pixels also written to g_feat
    for (int hp = tid; hp < 324; hp += 256){
        int yy = hp/18, xx = hp%18;
        int gy = ty*16 - 1 + yy, gx = tx*16 - 1 + xx;
        if ((unsigned)gy >= 256u || (unsigned)gx >= 256u){
            #pragma unroll 8
            for (int c = 0; c < 64; c++) fs[c*324 + hp] = 0.f;
            continue;
        }
        float in[27];
        #pragma unroll
        for (int c = 0; c < 3; c++)
            #pragma unroll
            for (int ky = 0; ky < 3; ky++)
                #pragma unroll
                for (int kx = 0; kx < 3; kx++)
                    in[c*9 + ky*3 + kx] = xs[c*400 + (yy+ky)*20 + (xx+kx)];
        unsigned long long acc[32];
        #pragma unroll
        for (int j = 0; j < 32; j++) acc[j] = 0ull;
        #pragma unroll
        for (int k = 0; k < 27; k++){
            unsigned long long x2 = pack2(in[k], in[k]);
            const unsigned long long* w2 = (const unsigned long long*)(wt + k*64);
            #pragma unroll
            for (int j = 0; j < 32; j++) fma2(acc[j], w2[j], x2);
        }
        bool inter = (yy >= 1 && yy <= 16 && xx >= 1 && xx <= 16);
        int ob = bb*IMG + gy*256 + gx;
        #pragma unroll
        for (int j = 0; j < 32; j++){
            float a, b2; unpack2(acc[j], a, b2);
            a  = fmaxf(a  + bs[2*j],   0.f);
            b2 = fmaxf(b2 + bs[2*j+1], 0.f);
            fs[(2*j)*324 + hp]   = a;
            fs[(2*j+1)*324 + hp] = b2;
            if (inter){
                g_feat[ob + (2*j)*HW]   = a;
                g_feat[ob + (2*j+1)*HW] = b2;
            }
        }
    }
    __syncthreads();
    // texture encoder + router + argmax (reads fs in-place)
    int px = tid % 16, py = tid / 16;
    float a8[8];
    #pragma unroll
    for (int k = 0; k < 8; k++) a8[k] = 0.f;
    for (int c = 0; c < 64; c++){
        const float* h = fs + c*324 + py*18 + px;
        float v = tb[c];
        #pragma unroll
        for (int ky = 0; ky < 3; ky++)
            #pragma unroll
            for (int kx = 0; kx < 3; kx++)
                v += tq[c*9 + ky*3 + kx] * h[ky*18 + kx];
        v = fmaxf(v, 0.f);
        #pragma unroll
        for (int k = 0; k < 8; k++) a8[k] += pq[k*64 + c] * v;
    }
    float s[8];
    #pragma unroll
    for (int k = 0; k < 8; k++) s[k] = 1.f / (1.f + expf(-(a8[k] + pb[k])));
    float best = -1e30f; int be = 0;
    #pragma unroll
    for (int e = 0; e < 4; e++){
        float l = rbs[e];
        #pragma unroll
        for (int k = 0; k < 8; k++) l += rws[e*8 + k] * s[k];
        if (l > best){ best = l; be = e; }
    }
    g_top[bb*HW + (ty*16+py)*256 + (tx*16+px)] = be;
}

// ---------------- res-block part A ----------------
// z = e*4+bb; in = feat (BLK 0) or feat + b0e*y0 (BLK 1, folded at stage time)
#define PA_SMEM ((256 + 18244) * 4)
#if USE_TC
// smem floats from 1KB-aligned base:
//   A [0,8192)  B [8192,12288)  meta@12288 (mbar @ byte 49160)
//   halo [12292,15204)  (8 ch x 364, row stride 20, cols 0..17 used)
//   dqp [15204,15972)   (64 ch x 12, padded weights)
//   db [15972,16036) pb [16036,16100) ys [16100,16164)
//   red overlays halo
template<int BLK>
__global__ void __launch_bounds__(256,3) partA_kernel(const float* __restrict__ edwb, const float* __restrict__ epwb){
    extern __shared__ float sm[];
    uint32_t sbase = smem_u32(sm);
    uint32_t sb1k = (sbase + 1023u) & ~1023u;
    float* base = sm + ((sb1k - sbase) >> 2);
    float* halo = base + 12292;
    float* red  = halo;
    float* dqp  = base + 15204;
    float* db   = base + 15972;
    float* pb   = base + 16036;
    float* ys   = base + 16100;
    int tid = threadIdx.x;
    int zz = blockIdx.z;
    int e = zz >> 2, bb = zz & 3;
    int wsel = e*2 + BLK;
    int eb64 = zz * 64;
    const float* srcf = g_feat + (size_t)bb*IMG;
    const float* src1 = BLK ? (g_b0e + (size_t)eb64 * HW) : (const float*)0;
    float* outb = (BLK ? g_b1e : g_b0e) + (size_t)eb64 * HW;
    uint32_t A_addr = sb1k;
    uint32_t B_addr = sb1k + 32768u;
    uint32_t meta   = sb1k + 49152u;
    uint32_t mbar   = sb1k + 49160u;
    if (tid < 32){
        TC_ALLOC(meta, 128);
        TC_RELINQ();
    }
    if (tid == 64) MBAR_INIT(mbar, 1);
    {
        float* Bbuf = base + 8192;
        for (int i = tid; i < 4096; i += 256) Bbuf[i] = d_epw[wsel*4096 + i];
    }
    for (int i = tid; i < 576; i += 256){
        int c9 = i/9, k = i - c9*9;
        dqp[c9*12 + k] = d_edw[wsel*576 + i];
    }
    if (tid < 64){
        db[tid] = edwb[wsel*64 + tid];
        pb[tid] = epwb[wsel*64 + tid];
        ys[tid] = BLK ? g_y0[eb64 + tid] : 0.f;
    }
    __syncthreads();
    uint32_t tmem;
    asm volatile("ld.shared.b32 %0, [%1];" : "=r"(tmem) : "r"(meta));

    int tx = blockIdx.x, ty = blockIdx.y;
    int x0 = tx*16 - 1, y0 = ty*16 - 1;

    // dw strip mapping: q = channel-pair, s = strip (py, 4-px group)
    int q  = tid & 3;
    int s  = tid >> 2;
    int spy = s >> 2;
    int ssx = (s & 3) * 4;

    // register staging for pipelined halo (8-ci chunks, 2592 elems, <=11 per thread)
    // coalesced: i = tid + k*256
    float sf[11];
    float sbv[BLK ? 11 : 1];
    auto stage = [&](int ch){
        const float* fp = srcf + (size_t)(ch*8)*HW;
        const float* bp = BLK ? (src1 + (size_t)(ch*8)*HW) : (const float*)0;
        #pragma unroll
        for (int k = 0; k < 11; k++){
            int i = tid + k*256;
            float f = 0.f, b = 0.f;
            if (i < 2592){
                int cil = i / 324;
                int r = i - cil*324;
                int yy = r / 18;
                int xx = r - yy*18;
                int gy = y0 + yy, gx = x0 + xx;
                if ((unsigned)gy < 256u && (unsigned)gx < 256u){
                    int off = cil*HW + gy*256 + gx;
                    f = fp[off];
                    if (BLK) b = bp[off];
                }
            }
            sf[k] = f;
            if (BLK) sbv[k] = b;
        }
    };

    stage(0);
    #pragma unroll 1
    for (int ch = 0; ch < 8; ch++){
        __syncthreads();   // prior chunk's halo LDS complete
        // STS staged chunk into padded halo layout (coalesced scalar)
        #pragma unroll
        for (int k = 0; k < 11; k++){
            int i = tid + k*256;
            if (i < 2592){
                int cil = i / 324;
                int r = i - cil*324;
                int yy = r / 18;
                int xx = r - yy*18;
                float v = sf[k];
                if (BLK) v += sbv[k]*ys[ch*8 + cil];
                halo[cil*364 + yy*20 + xx] = v;
            }
        }
        if (ch < 7) stage(ch+1);   // next chunk's LDGs in flight across barrier + compute
        __syncthreads();
        if (ch == 4){   // A (ci 0-31) fully written -> issue MMA batch 0
            FENCE_ASYNC();
            if (tid < 32 && elect_one_pred()){
                unsigned long long a0 = make_desc(A_addr);
                unsigned long long b0d = make_desc(B_addr);
                #pragma unroll
                for (int t = 0; t < 2; t++)
                    #pragma unroll
                    for (int k = 0; k < 4; k++)
                        mma_tf32_ss(tmem + 64*t, a0 + t*1024 + k*2, b0d + k*2, TF32_IDESC, k > 0);
                TC_COMMIT(mbar);
            }
        }
        // dw conv: 2 channels x 4 pixels per thread, vectorized LDS
        float o[8];
        #pragma unroll
        for (int cc = 0; cc < 2; cc++){
            int cil = q*2 + cc;
            int cg = ch*8 + cil;
            const float* hb = halo + cil*364;
            const float4* wp = (const float4*)(dqp + cg*12);
            float4 wA = wp[0];            // w0..w3
            float4 wB = wp[1];            // w4..w7
            float4 wC = wp[2];            // w8 (+pad)
            float bias = db[cg];
            float o0 = bias, o1 = bias, o2 = bias, o3 = bias;
            #pragma unroll
            for (int ky = 0; ky < 3; ky++){
                const float* rp = hb + (spy + ky)*20 + ssx;
                float4 a = *(const float4*)rp;
                float2 b2 = *(const float2*)(rp + 4);
                float w0, w1, w2;
                if (ky == 0){ w0 = wA.x; w1 = wA.y; w2 = wA.z; }
                else if (ky == 1){ w0 = wA.w; w1 = wB.x; w2 = wB.y; }
                else { w0 = wB.z; w1 = wB.w; w2 = wC.x; }
                o0 += w0*a.x + w1*a.y + w2*a.z;
                o1 += w0*a.y + w1*a.z + w2*a.w;
                o2 += w0*a.z + w1*a.w + w2*b2.x;
                o3 += w0*a.w + w1*b2.x + w2*b2.y;
            }
            o[cc*4+0] = fmaxf(o0, 0.f);
            o[cc*4+1] = fmaxf(o1, 0.f);
            o[cc*4+2] = fmaxf(o2, 0.f);
            o[cc*4+3] = fmaxf(o3, 0.f);
        }
        if (ch == 4) MBAR_WAIT(mbar, 0);   // batch-0 MMA done before A overwrite
        // A-tile STS: 4 pixels, channel pair -> STS.64 each
        #pragma unroll
        for (int j = 0; j < 4; j++){
            int p = spy*16 + ssx + j;
            uint32_t ad = A_addr + sw128((uint32_t)p*128u + (uint32_t)((ch & 3)*8 + q*2)*4u);
            asm volatile("st.shared.v2.b32 [%0], {%1,%2};"
                :: "r"(ad), "r"(__float_as_uint(o[j])), "r"(__float_as_uint(o[4+j])) : "memory");
        }
    }
    __syncthreads();   // all A-STS done; halo dead -> red usable

    FENCE_ASYNC();
    if (tid < 32 && elect_one_pred()){
        unsigned long long a0 = make_desc(A_addr);
        unsigned long long b1d = make_desc(B_addr + 8192u);
        #pragma unroll
        for (int t = 0; t < 2; t++)
            #pragma unroll
            for (int k = 0; k < 4; k++)
                mma_tf32_ss(tmem + 64*t, a0 + t*1024 + k*2, b1d + k*2, TF32_IDESC, 1);
        TC_COMMIT(mbar);
    }
    MBAR_WAIT(mbar, 1);
    TC_FENCE_AFTER();

    int px_ = tid & 15, py_ = tid >> 4;
    int gy = ty*16 + py_, gx = tx*16 + px_;
    size_t ob = (size_t)gy*256 + gx;
    int lane = tid & 31, warp = tid >> 5;
    #pragma unroll 1
    for (int hh = 0; hh < 2; hh++){
        uint32_t dr[32];
        TC_LD_X32(dr, tmem + 64*(tid >> 7) + hh*32);
        TC_WAIT_LD();
        #pragma unroll
        for (int c2 = 0; c2 < 32; c2++){
            int c = hh*32 + c2;
            float a = __uint_as_float(dr[c2]) + pb[c];
            outb[(size_t)c*HW + ob] = a;
            float ra = a;
            ra += __shfl_xor_sync(0xffffffffu, ra, 16);
            ra += __shfl_xor_sync(0xffffffffu, ra, 8);
            ra += __shfl_xor_sync(0xffffffffu, ra, 4);
            ra += __shfl_xor_sync(0xffffffffu, ra, 2);
            ra += __shfl_xor_sync(0xffffffffu, ra, 1);
            if (lane == 0) red[c*8 + warp] = ra;
        }
    }
    __syncthreads();
    if (tid < 64){
        float ssum = 0.f;
        #pragma unroll
        for (int i = 0; i < 8; i++) ssum += red[tid*8 + i];
        atomicAdd(&g_gsum[eb64 + tid], ssum);
    }
    if (tid == 64) MBAR_INVAL(mbar);
    if (tid < 32) TC_DEALLOC(tmem, 128);
}
#else
// fallback (non-sm_103a pass): R7 f32x2 implementation
template<int BLK>
__global__ void __launch_bounds__(256,3) partA_kernel(const float* __restrict__ edwb, const float* __restrict__ epwb){
    extern __shared__ float sm[];
    uint32_t sbase = smem_u32(sm);
    uint32_t sb1k = (sbase + 1023u) & ~1023u;
    float* base = sm + ((sb1k - sbase) >> 2);
    float* Bbuf = base + 8192;
    float* halo = base + 12292;
    float* red  = halo;
    float* dq   = base + 17476;
    float* db   = base + 18052;
    float* pb   = base + 18116;
    float* ys   = base + 18180;
    int tid = threadIdx.x;
    int zz = blockIdx.z;
    int e = zz >> 2, bb = zz & 3;
    int wsel = e*2 + BLK;
    int eb64 = zz * 64;
    const float* srcf = g_feat + (size_t)bb*IMG;
    const float* src1 = BLK ? (g_b0e + (size_t)eb64 * HW) : (const float*)0;
    float* outb = (BLK ? g_b1e : g_b0e) + (size_t)eb64 * HW;
    for (int i = tid; i < 4096; i += 256) Bbuf[i] = d_epw[wsel*4096 + i];
    for (int i = tid; i < 576;  i += 256) dq[i]   = d_edw[wsel*576 + i];
    if (tid < 64){
        db[tid] = edwb[wsel*64 + tid];
        pb[tid] = epwb[wsel*64 + tid];
        ys[tid] = BLK ? g_y0[eb64 + tid] : 0.f;
    }
    __syncthreads();
    int tx = blockIdx.x, ty = blockIdx.y;
    int x0 = tx*16 - 1, y0 = ty*16 - 1;
    int px_ = tid & 15, py_ = tid >> 4;
    float sf[11];
    float sbv[BLK ? 11 : 1];
    auto stage = [&](int ch){
        const float* fp = srcf + (size_t)(ch*8)*HW;
        const float* bp = BLK ? (src1 + (size_t)(ch*8)*HW) : (const float*)0;
        #pragma unroll
        for (int k = 0; k < 11; k++){
            int i = tid + k*256;
            float f = 0.f, b = 0.f;
            if (i < 2592){
                int cil = i / 324;
                int r = i - cil*324;
                int yy = r / 18;
                int xx = r - yy*18;
                int gy = y0 + yy, gx = x0 + xx;
                if ((unsigned)gy < 256u && (unsigned)gx < 256u){
                    int off = cil*HW + gy*256 + gx;
                    f = fp[off];
                    if (BLK) b = bp[off];
                }
            }
            sf[k] = f;
            if (BLK) sbv[k] = b;
        }
    };
    unsigned long long acc[32];
    #pragma unroll
    for (int j = 0; j < 32; j++) acc[j] = 0ull;
    stage(0);
    #pragma unroll 1
    for (int ch = 0; ch < 8; ch++){
        float* hbuf = halo + (ch & 1)*2592;
        #pragma unroll
        for (int k = 0; k < 11; k++){
            int i = tid + k*256;
            if (i < 2592){
                float v = sf[k];
                if (BLK){ int cil = i/324; v += sbv[k]*ys[ch*8 + cil]; }
                hbuf[i] = v;
            }
        }
        if (ch < 7) stage(ch+1);
        __syncthreads();
        #pragma unroll
        for (int u = 0; u < 8; u++){
            int cg = ch*8 + u;
            const float* h = hbuf + u*324 + py_*18 + px_;
            const float* w9 = dq + cg*9;
            float v = db[cg];
            #pragma unroll
            for (int ky = 0; ky < 3; ky++)
                #pragma unroll
                for (int kx = 0; kx < 3; kx++)
                    v += w9[ky*3 + kx] * h[ky*18 + kx];
            v = fmaxf(v, 0.f);
            unsigned long long x2 = pack2(v, v);
            const ulonglong2* w4 = (const ulonglong2*)(Bbuf + cg*64);
            #pragma unroll
            for (int j = 0; j < 16; j++){
                ulonglong2 w = w4[j];
                fma2(acc[2*j],   w.x, x2);
                fma2(acc[2*j+1], w.y, x2);
            }
        }
        __syncthreads();
    }
    int gy = ty*16 + py_, gx = tx*16 + px_;
    size_t ob = (size_t)gy*256 + gx;
    int lane = tid & 31, warp = tid >> 5;
    #pragma unroll
    for (int j = 0; j < 32; j++){
        float a, b2; unpack2(acc[j], a, b2);
        a  += pb[2*j];
        b2 += pb[2*j+1];
        outb[(size_t)(2*j)*HW + ob]   = a;
        outb[(size_t)(2*j+1)*HW + ob] = b2;
        float ra = a, rb2 = b2;
        ra  += __shfl_xor_sync(0xffffffffu, ra, 16);
        ra  += __shfl_xor_sync(0xffffffffu, ra, 8);
        ra  += __shfl_xor_sync(0xffffffffu, ra, 4);
        ra  += __shfl_xor_sync(0xffffffffu, ra, 2);
        ra  += __shfl_xor_sync(0xffffffffu, ra, 1);
        rb2 += __shfl_xor_sync(0xffffffffu, rb2, 16);
        rb2 += __shfl_xor_sync(0xffffffffu, rb2, 8);
        rb2 += __shfl_xor_sync(0xffffffffu, rb2, 4);
        rb2 += __shfl_xor_sync(0xffffffffu, rb2, 2);
        rb2 += __shfl_xor_sync(0xffffffffu, rb2, 1);
        if (lane == 0){ red[(2*j)*8 + warp] = ra; red[(2*j+1)*8 + warp] = rb2; }
    }
    __syncthreads();
    if (tid < 64){
        float s = 0.f;
        #pragma unroll
        for (int i = 0; i < 8; i++) s += red[tid*8 + i];
        atomicAdd(&g_gsum[eb64 + tid], s);
    }
}
#endif

// ---------------- channel attention (one block per expert) ----------------
__global__ void y_kernel(const float* __restrict__ fc1_all, const float* __restrict__ fc2_all, int blk){
    __shared__ float m[256];
    __shared__ float h1[64];
    int tid = threadIdx.x;
    int e = blockIdx.x;
    const float* fc1 = fc1_all + (e*2 + blk)*1024;
    const float* fc2 = fc2_all + (e*2 + blk)*1024;
    int base = e*256;
    m[tid] = g_gsum[base + tid] * (1.f / 65536.f);
    __syncthreads();
    g_gsum[base + tid] = 0.f;
    if (tid < 64){
        int b = tid / 16, j = tid % 16;
        float s = 0.f;
        for (int c = 0; c < 64; c++) s += m[b*64 + c] * fc1[j*64 + c];
        h1[tid] = fmaxf(s, 0.f);
    }
    __syncthreads();
    int b = tid / 64, co = tid % 64;
    float s = 0.f;
    #pragma unroll
    for (int j = 0; j < 16; j++) s += h1[b*16 + j] * fc2[co*16 + j];
    float yv = 1.f / (1.f + expf(-s));
    if (blk) g_y1[base + tid] = yv; else g_y0[base + tid] = yv;
}

// ---------------- MoE select: per-pixel expert gather ----------------
__global__ void __launch_bounds__(256) select_kernel(){
    int pix = blockIdx.x*256 + threadIdx.x;
    int bb = pix / HW, pr = pix % HW;
    int e = g_top[pix];
    int eb64 = (e*4 + bb)*64;
    const float* y0 = g_y0 + eb64;
    const float* y1 = g_y1 + eb64;
    const float* b0 = g_b0e + (size_t)eb64*HW + pr;
    const float* b1 = g_b1e + (size_t)eb64*HW + pr;
    int base = bb*IMG + pr;
    #pragma unroll 4
    for (int c = 0; c < 64; c++){
        g_moe[base + c*HW] = g_feat[base + c*HW] + b0[(size_t)c*HW]*y0[c] + b1[(size_t)c*HW]*y1[c];
    }
}

// ---------------- recon 64->12 3x3 + pixel shuffle + bilinear skip ----------------
#define RC_SMEM ((20736 + 972 + 6912 + 12) * 4)
__global__ void __launch_bounds__(256) recon_kernel(const float* __restrict__ x, const float* __restrict__ rcb){
    extern __shared__ float sm[];
    float* halo = sm;            // 20736
    float* xs   = halo + 20736;  // 972
    float* wt   = xs + 972;      // 6912
    float* rb   = wt + 6912;     // 12
    int tid = threadIdx.x;
    for (int i = tid; i < 6912; i += 256) wt[i] = d_rect[i];
    if (tid < 12) rb[tid] = rcb[tid];
    int tx = blockIdx.x, ty = blockIdx.y, bb = blockIdx.z;
    int x0 = tx*16 - 1, y0 = ty*16 - 1;
    for (int i = tid; i < 64*324; i += 256){
        int c = i/324, r = i%324, yy = r/18, xx = r%18;
        int gy = y0 + yy, gx = x0 + xx;
        float v = 0.f;
        if ((unsigned)gy < 256u && (unsigned)gx < 256u) v = g_moe[(bb*64+c)*HW + gy*256 + gx];
        halo[i] = v;
    }
    for (int i = tid; i < 3*324; i += 256){
        int c = i/324, r = i%324, yy = r/18, xx = r%18;
        int gy = min(max(y0 + yy, 0), 255), gx = min(max(x0 + xx, 0), 255);
        xs[i] = x[(bb*3+c)*HW + gy*256 + gx];
    }
    __syncthreads();
    int px = tid % 16, py = tid / 16;
    unsigned long long acc[6];
    #pragma unroll
    for (int j = 0; j < 6; j++) acc[j] = 0ull;
    for (int ci = 0; ci < 64; ci++){
        const float* h = halo + ci*324 + py*18 + px;
        #pragma unroll
        for (int k = 0; k < 9; k++){
            float xv = h[(k/3)*18 + (k%3)];
            unsigned long long x2 = pack2(xv, xv);
            const unsigned long long* w2 = (const unsigned long long*)(wt + (ci*9 + k)*12);
            ulonglong2 wa = *(const ulonglong2*)w2;
            unsigned long long wc = w2[2];
            fma2(acc[0], wa.x, x2);
            fma2(acc[1], wa.y, x2);
            fma2(acc[2], wc,   x2);
            ulonglong2 wb = *(const ulonglong2*)(w2 + 3);
            unsigned long long wd = w2[5];
            fma2(acc[3], wb.x, x2);
            fma2(acc[4], wb.y, x2);
            fma2(acc[5], wd,   x2);
        }
    }
    float cv[12];
    #pragma unroll
    for (int j = 0; j < 6; j++){
        float a, b2; unpack2(acc[j], a, b2);
        cv[2*j]   = a  + rb[2*j];
        cv[2*j+1] = b2 + rb[2*j+1];
    }
    int gy = ty*16 + py, gx = tx*16 + px;
    #pragma unroll
    for (int r1 = 0; r1 < 2; r1++){
        int ly0 = r1 ? py+1 : py;
        int ly1 = ly0 + 1;
        float wy0 = r1 ? 0.75f : 0.25f;
        float wy1 = 1.f - wy0;
        #pragma unroll
        for (int r2 = 0; r2 < 2; r2++){
            int lx0 = r2 ? px+1 : px;
            int lx1 = lx0 + 1;
            float wx0 = r2 ? 0.75f : 0.25f;
            float wx1 = 1.f - wx0;
            int oh = 2*gy + r1, ow = 2*gx + r2;
            #pragma unroll
            for (int co = 0; co < 3; co++){
                const float* xc = xs + co*324;
                float up = wy0*(wx0*xc[ly0*18+lx0] + wx1*xc[ly0*18+lx1])
                         + wy1*(wx0*xc[ly1*18+lx0] + wx1*xc[ly1*18+lx1]);
                int ch = co*4 + r1*2 + r2;
                g_sr[(bb*3+co)*262144 + oh*512 + ow] = cv[ch] + up;
            }
        }
    }
}

// ---------------- refinement: out = sr + conv2(relu(conv1(sr))) ----------------
__global__ void __launch_bounds__(256) ref_kernel(const float* __restrict__ b1, const float* __restrict__ b2,
                                                  float* __restrict__ out){
    __shared__ float srh[3*432];   // 3 x 12 x 36
    __shared__ float th[3*340];    // 3 x 10 x 34
    __shared__ float w1[81], w2[81], sb1[3], sb2[3];
    int tid = threadIdx.x;
    if (tid < 81){ w1[tid] = d_ref1[tid]; w2[tid] = d_ref2[tid]; }
    if (tid < 3){ sb1[tid] = b1[tid]; sb2[tid] = b2[tid]; }
    int tx = blockIdx.x, ty = blockIdx.y, bb = blockIdx.z;
    int X0 = tx*32, Y0 = ty*8;
    for (int i = tid; i < 3*432; i += 256){
        int c = i/432, r = i%432, yy = r/36, xx = r%36;
        int gy = Y0 + yy - 2, gx = X0 + xx - 2;
        float v = 0.f;
        if ((unsigned)gy < 512u && (unsigned)gx < 512u) v = g_sr[(bb*3+c)*262144 + gy*512 + gx];
        srh[i] = v;
    }
    __syncthreads();
    for (int i = tid; i < 3*340; i += 256){
        int c = i/340, r = i%340, yy = r/34, xx = r%34;
        int gy = Y0 + yy - 1, gx = X0 + xx - 1;
        float v = 0.f;
        if ((unsigned)gy < 512u && (unsigned)gx < 512u){
            v = sb1[c];
            #pragma unroll
            for (int ci = 0; ci < 3; ci++)
                #pragma unroll
                for (int ky = 0; ky < 3; ky++)
                    #pragma unroll
                    for (int kx = 0; kx < 3; kx++)
                        v += w1[(c*3+ci)*9 + ky*3 + kx] * srh[ci*432 + (yy+ky)*36 + (xx+kx)];
            v = fmaxf(v, 0.f);
        }
        th[i] = v;
    }
    __syncthreads();
    int px = tid % 32, py = tid / 32;
    int oh = Y0 + py, ow = X0 + px;
    #pragma unroll
    for (int co = 0; co < 3; co++){
        float v = sb2[co];
        #pragma unroll
        for (int ci = 0; ci < 3; ci++)
            #pragma unroll
            for (int ky = 0; ky < 3; ky++)
                #pragma unroll
                for (int kx = 0; kx < 3; kx++)
                    v += w2[(co*3+ci)*9 + ky*3 + kx] * th[ci*340 + (py+ky)*34 + (px+kx)];
        out[(bb*3+co)*262144 + oh*512 + ow] = srh[co*432 + (py+2)*36 + (px+2)] + v;
    }
}

// ---------------- launch ----------------
extern "C" void kernel_launch(void* const* d_in, const int* in_sizes, int n_in,
                              void* d_out, int out_size){
    const float* x         = (const float*)d_in[0];
    const float* shallow_w = (const float*)d_in[1];
    const float* shallow_b = (const float*)d_in[2];
    const float* tex_dw_w  = (const float*)d_in[3];
    const float* tex_dw_b  = (const float*)d_in[4];
    const float* tex_pw_w  = (const float*)d_in[5];
    const float* tex_pw_b  = (const float*)d_in[6];
    const float* router_w  = (const float*)d_in[7];
    const float* router_b  = (const float*)d_in[8];
    const float* exp_dw_w  = (const float*)d_in[9];
    const float* exp_dw_b  = (const float*)d_in[10];
    const float* exp_pw_w  = (const float*)d_in[11];
    const float* exp_pw_b  = (const float*)d_in[12];
    const float* fc1       = (const float*)d_in[13];
    const float* fc2       = (const float*)d_in[14];
    const float* recon_w   = (const float*)d_in[15];
    const float* recon_b   = (const float*)d_in[16];
    const float* ref1_w    = (const float*)d_in[17];
    const float* ref1_b    = (const float*)d_in[18];
    const float* ref2_w    = (const float*)d_in[19];
    const float* ref2_b    = (const float*)d_in[20];
    float* out = (float*)d_out;

    cudaFuncSetAttribute(shallow_tex_kernel, cudaFuncAttributeMaxDynamicSharedMemorySize, ST_SMEM);
    cudaFuncSetAttribute(partA_kernel<0>, cudaFuncAttributeMaxDynamicSharedMemorySize, PA_SMEM);
    cudaFuncSetAttribute(partA_kernel<1>, cudaFuncAttributeMaxDynamicSharedMemorySize, PA_SMEM);
    cudaFuncSetAttribute(recon_kernel,    cudaFuncAttributeMaxDynamicSharedMemorySize, RC_SMEM);

    prep_kernel<<<22, 256>>>(shallow_w, tex_dw_w, tex_pw_w, exp_dw_w, exp_pw_w, ref1_w, ref2_w, recon_w);

    dim3 g16(16, 16, 4);
    shallow_tex_kernel<<<g16, 256, ST_SMEM>>>(x, shallow_b, tex_dw_b, tex_pw_b, router_w, router_b);

    dim3 gA(16, 16, 16);   // z = e*4 + batch
    partA_kernel<0><<<gA, 256, PA_SMEM>>>(exp_dw_b, exp_pw_b);
    y_kernel<<<4, 256>>>(fc1, fc2, 0);
    partA_kernel<1><<<gA, 256, PA_SMEM>>>(exp_dw_b, exp_pw_b);
    y_kernel<<<4, 256>>>(fc1, fc2, 1);
    select_kernel<<<1024, 256>>>();

    recon_kernel<<<g16, 256, RC_SMEM>>>(x, recon_b);

    dim3 gref(16, 64, 4);
    ref_kernel<<<gref, 256>>>(ref1_b, ref2_b, out);
}

// round 11
// speedup vs baseline: 1.6220x; 1.0869x over previous
#include <cuda_runtime.h>
#include <math.h>
#include <stdint.h>

#if (defined(__CUDA_ARCH_FEAT_SM103_ALL) || (defined(__CUDA_ARCH_SPECIFIC__) && (__CUDA_ARCH__ == 1030)))
#define USE_TC 1
#else
#define USE_TC 0
#endif

#define BATCH 4
#define CCH 64
#define HH 256
#define WWI 256
#define HW (HH*WWI)
#define IMG (CCH*HW)
#define NPIX (BATCH*HW)

// ---------------- scratch (device globals, no allocs) ----------------
__device__ float g_feat[BATCH*CCH*HW];
__device__ float g_b0e[4*BATCH*CCH*HW];   // per-expert block-0 residual branch
__device__ float g_b1e[4*BATCH*CCH*HW];   // per-expert block-1 residual branch
__device__ float g_moe[BATCH*CCH*HW];
__device__ float g_sr[BATCH*3*512*512];
__device__ int   g_top[NPIX];
__device__ float g_dsum[4*BATCH*CCH];     // [e][b][ci]: per-image sums of relu(dw)
__device__ float g_y0[4*BATCH*CCH];
__device__ float g_y1[4*BATCH*CCH];
// quantized / transposed weights
__device__ float d_sq_t[27*64];     // shallow, transposed [k][co]
__device__ float d_texdw[576];
__device__ float d_texpw[512];
__device__ float d_edw[8*576];
__device__ float d_epw[8*4096];     // pw weights: SW128 MMA layout (TC) or [ci][co] (fallback)
__device__ float d_epw_p[8*4096];   // pw weights plain [co][ci] (ternarized) for y_kernel
__device__ float d_ref1[81];
__device__ float d_ref2[81];
__device__ float d_rect[576*12];    // recon transposed [ci*9+k][co]

// ---------------- f32x2 helpers ----------------
__device__ __forceinline__ unsigned long long pack2(float a, float b){
    unsigned long long r;
    asm("mov.b64 %0, {%1, %2};" : "=l"(r) : "r"(__float_as_uint(a)), "r"(__float_as_uint(b)));
    return r;
}
__device__ __forceinline__ void unpack2(unsigned long long v, float& a, float& b){
    unsigned int x, y;
    asm("mov.b64 {%0, %1}, %2;" : "=r"(x), "=r"(y) : "l"(v));
    a = __uint_as_float(x); b = __uint_as_float(y);
}
__device__ __forceinline__ void fma2(unsigned long long& acc, unsigned long long w, unsigned long long x){
    asm("fma.rn.f32x2 %0, %1, %2, %0;" : "+l"(acc) : "l"(w), "l"(x));
}

__device__ __forceinline__ uint32_t smem_u32(const void* p){
    uint32_t a;
    asm("{ .reg .u64 t; cvta.to.shared.u64 t, %1; cvt.u32.u64 %0, t; }" : "=r"(a) : "l"(p));
    return a;
}

__host__ __device__ __forceinline__ uint32_t sw128(uint32_t off){ return off ^ ((off >> 3) & 0x70); }

#if USE_TC
// ---------------- tcgen05 / mbarrier helpers (sm_103a-specific pass only) ----------------
__device__ __forceinline__ uint32_t elect_one_pred(){
    uint32_t pred;
    asm volatile("{\n\t.reg .pred p;\n\telect.sync _|p, 0xFFFFFFFF;\n\tselp.b32 %0, 1, 0, p;\n\t}" : "=r"(pred));
    return pred;
}
#define TC_ALLOC(sa, n)   asm volatile("tcgen05.alloc.cta_group::1.sync.aligned.shared::cta.b32 [%0], %1;" :: "r"(sa), "r"((uint32_t)(n)) : "memory")
#define TC_DEALLOC(t, n)  asm volatile("tcgen05.dealloc.cta_group::1.sync.aligned.b32 %0, %1;" :: "r"(t), "r"((uint32_t)(n)))
#define TC_RELINQ()       asm volatile("tcgen05.relinquish_alloc_permit.cta_group::1.sync.aligned;")
#define TC_COMMIT(mb)     asm volatile("tcgen05.commit.cta_group::1.mbarrier::arrive::one.shared::cluster.b64 [%0];" :: "r"(mb) : "memory")
#define TC_FENCE_AFTER()  asm volatile("tcgen05.fence::after_thread_sync;" ::: "memory")
#define TC_WAIT_LD()      asm volatile("tcgen05.wait::ld.sync.aligned;" ::: "memory")
#define FENCE_ASYNC()     asm volatile("fence.proxy.async.shared::cta;" ::: "memory")
#define MBAR_INIT(mb, c)  asm volatile("mbarrier.init.shared.b64 [%0], %1;" :: "r"(mb), "r"((uint32_t)(c)) : "memory")
#define MBAR_INVAL(mb)    asm volatile("mbarrier.inval.shared.b64 [%0];" :: "r"(mb) : "memory")
#define MBAR_WAIT(mb, ph) do { \
    uint32_t _mb = (mb); uint32_t _p = (ph); uint32_t _done; \
    asm volatile("{\n\t.reg .pred p;\n\tmbarrier.try_wait.parity.acquire.cta.shared::cta.b64 p, [%1], %2;\n\tselp.b32 %0, 1, 0, p;\n\t}" \
        : "=r"(_done) : "r"(_mb), "r"(_p) : "memory"); \
    if (!_done){ \
        asm volatile("{\n\t.reg .pred P1;\n\tWL_%=:\n\tmbarrier.try_wait.parity.acquire.cta.shared::cta.b64 P1, [%0], %1, 0x989680;\n\t@P1 bra.uni WD_%=;\n\tbra.uni WL_%=;\n\tWD_%=:\n\t}" \
            :: "r"(_mb), "r"(_p) : "memory"); \
    } \
} while(0)
#define TC_LD_X32(r, ta) \
    asm volatile("tcgen05.ld.sync.aligned.32x32b.x32.b32 " \
        "{%0, %1, %2, %3, %4, %5, %6, %7, %8, %9, %10, %11, %12, %13, %14, %15, " \
        " %16, %17, %18, %19, %20, %21, %22, %23, %24, %25, %26, %27, %28, %29, %30, %31}, [%32];" \
        : "=r"((r)[0]),  "=r"((r)[1]),  "=r"((r)[2]),  "=r"((r)[3]), \
          "=r"((r)[4]),  "=r"((r)[5]),  "=r"((r)[6]),  "=r"((r)[7]), \
          "=r"((r)[8]),  "=r"((r)[9]),  "=r"((r)[10]), "=r"((r)[11]), \
          "=r"((r)[12]), "=r"((r)[13]), "=r"((r)[14]), "=r"((r)[15]), \
          "=r"((r)[16]), "=r"((r)[17]), "=r"((r)[18]), "=r"((r)[19]), \
          "=r"((r)[20]), "=r"((r)[21]), "=r"((r)[22]), "=r"((r)[23]), \
          "=r"((r)[24]), "=r"((r)[25]), "=r"((r)[26]), "=r"((r)[27]), \
          "=r"((r)[28]), "=r"((r)[29]), "=r"((r)[30]), "=r"((r)[31]) \
        : "r"(ta))

__device__ __forceinline__ void mma_tf32_ss(uint32_t d_tmem, unsigned long long a_desc,
                                            unsigned long long b_desc, uint32_t idesc, int en){
    asm volatile(
        "{\n\t.reg .pred p;\n\tsetp.ne.u32 p, %4, 0;\n\t"
        "tcgen05.mma.cta_group::1.kind::tf32 [%0], %1, %2, %3, p;\n\t}"
        :: "r"(d_tmem), "l"(a_desc), "l"(b_desc), "r"(idesc), "r"((uint32_t)en) : "memory");
}

// SW128 smem descriptor: LBO=1, SBO=64, version=1, layout SW128
__device__ __forceinline__ unsigned long long make_desc(uint32_t addr){
    const unsigned long long base =
        (2ull << 61) | (1ull << 46) | (64ull << 32) | (1ull << 16);
    return base | (((unsigned long long)(addr >> 4)) & 0x3FFF);
}
// idesc: dtype F32, atype/btype TF32 (2), N=64, M=128
#define TF32_IDESC 0x8100910u
#endif  // USE_TC

// ---------------- weight prep: TWN ternarize (+ transposes) ----------------
__global__ void prep_kernel(const float* shallow_w, const float* tex_dw_w, const float* tex_pw_w,
                            const float* exp_dw_w, const float* exp_pw_w,
                            const float* ref1_w, const float* ref2_w, const float* recon_w)
{
    __shared__ float sred[256];
    __shared__ float sred2[256];
    int blk = blockIdx.x, tid = threadIdx.x;
    const float* src; float* dst; int n; int mode; bool quant = true;
    if (blk == 0)       { src = shallow_w; dst = d_sq_t;  n = 1728; mode = 1; }
    else if (blk == 1)  { src = tex_dw_w;  dst = d_texdw; n = 576;  mode = 0; }
    else if (blk == 2)  { src = tex_pw_w;  dst = d_texpw; n = 512;  mode = 0; }
    else if (blk < 11)  { int eb = blk-3;  src = exp_dw_w + eb*576;  dst = d_edw + eb*576;  n = 576;  mode = 0; }
    else if (blk < 19)  { int eb = blk-11; src = exp_pw_w + eb*4096; dst = d_epw + eb*4096; n = 4096; mode = 2; }
    else if (blk == 19) { src = ref1_w; dst = d_ref1; n = 81; mode = 0; }
    else if (blk == 20) { src = ref2_w; dst = d_ref2; n = 81; mode = 0; }
    else                { src = recon_w; dst = d_rect; n = 6912; mode = 3; quant = false; }

    if (!quant){
        for (int i = tid; i < n; i += 256){ int co = i/576, t = i%576; dst[t*12 + co] = src[i]; }
        for (int i = tid; i < 4*BATCH*CCH; i += 256) g_dsum[i] = 0.f;   // init GAP accumulator once
        return;
    }
    float s = 0.f;
    for (int i = tid; i < n; i += 256) s += fabsf(src[i]);
    sred[tid] = s; __syncthreads();
    for (int off = 128; off; off >>= 1){ if (tid < off) sred[tid] += sred[tid+off]; __syncthreads(); }
    float delta = 0.75f * sred[0] / (float)n;
    __syncthreads();
    float s2 = 0.f, c2 = 0.f;
    for (int i = tid; i < n; i += 256){ float a = fabsf(src[i]); if (a > delta){ s2 += a; c2 += 1.f; } }
    sred[tid] = s2; sred2[tid] = c2; __syncthreads();
    for (int off = 128; off; off >>= 1){
        if (tid < off){ sred[tid] += sred[tid+off]; sred2[tid] += sred2[tid+off]; }
        __syncthreads();
    }
    float alpha = sred[0] / fmaxf(sred2[0], 1.f);
    for (int i = tid; i < n; i += 256){
        float w = src[i];
        float q = (fabsf(w) > delta) ? copysignf(alpha, w) : 0.f;
        int j;
        if (mode == 0) j = i;
        else if (mode == 1){ int co = i/27, k = i%27; j = k*64 + co; }
        else {
            int co = i/64, ci = i%64;
            d_epw_p[(blk-11)*4096 + i] = q;   // plain [co][ci] copy for y_kernel
#if USE_TC
            // MMA SW128 K-major layout: chunk(ci/32), row co (128B), col ci%32
            uint32_t byte = (uint32_t)(ci>>5)*8192u + sw128((uint32_t)co*128u + (uint32_t)(ci&31)*4u);
            j = (int)(byte >> 2);
#else
            j = ci*64 + co;   // transposed [ci][co]
#endif
        }
        dst[j] = q;
    }
}

// ---------------- FUSED shallow conv + texture encoder + router + argmax ----------------
#define ST_SMEM ((20736 + 1200 + 1728 + 576 + 64 + 512 + 8 + 32 + 4 + 64) * 4)
__global__ void __launch_bounds__(256,2) shallow_tex_kernel(
    const float* __restrict__ x, const float* __restrict__ sb,
    const float* __restrict__ tdwb, const float* __restrict__ tpwb,
    const float* __restrict__ rw,   const float* __restrict__ rb){
    extern __shared__ float sm[];
    float* fs  = sm;             // 20736 (64 x 324)
    float* xs  = fs + 20736;     // 1200 (3 x 400: 20x20 x-halo)
    float* wt  = xs + 1200;      // 1728 (shallow, [k][co])
    float* tq  = wt + 1728;      // 576
    float* tb  = tq + 576;       // 64
    float* pq  = tb + 64;        // 512
    float* pb  = pq + 512;       // 8
    float* rws = pb + 8;         // 32
    float* rbs = rws + 32;       // 4
    float* bs  = rbs + 4;        // 64
    int tid = threadIdx.x;
    int tx = blockIdx.x, ty = blockIdx.y, bb = blockIdx.z;
    for (int i = tid; i < 1728; i += 256) wt[i] = d_sq_t[i];
    for (int i = tid; i < 576;  i += 256) tq[i] = d_texdw[i];
    for (int i = tid; i < 512;  i += 256) pq[i] = d_texpw[i];
    if (tid < 64) tb[tid] = tdwb[tid];
    if (tid < 8)  pb[tid] = tpwb[tid];
    if (tid < 32) rws[tid] = rw[tid];
    if (tid < 4)  rbs[tid] = rb[tid];
    if (tid < 64) bs[tid] = sb[tid];
    int X0 = tx*16 - 2, Y0 = ty*16 - 2;
    for (int i = tid; i < 1200; i += 256){
        int c = i/400, r = i%400, yy = r/20, xx = r%20;
        int gy = Y0 + yy, gx = X0 + xx;
        float v = 0.f;
        if ((unsigned)gy < 256u && (unsigned)gx < 256u) v = x[(bb*3+c)*HW + gy*256 + gx];
        xs[i] = v;
    }
    __syncthreads();
    for (int hp = tid; hp < 324; hp += 256){
        int yy = hp/18, xx = hp%18;
        int gy = ty*16 - 1 + yy, gx = tx*16 - 1 + xx;
        if ((unsigned)gy >= 256u || (unsigned)gx >= 256u){
            #pragma unroll 8
            for (int c = 0; c < 64; c++) fs[c*324 + hp] = 0.f;
            continue;
        }
        float in[27];
        #pragma unroll
        for (int c = 0; c < 3; c++)
            #pragma unroll
            for (int ky = 0; ky < 3; ky++)
                #pragma unroll
                for (int kx = 0; kx < 3; kx++)
                    in[c*9 + ky*3 + kx] = xs[c*400 + (yy+ky)*20 + (xx+kx)];
        unsigned long long acc[32];
        #pragma unroll
        for (int j = 0; j < 32; j++) acc[j] = 0ull;
        #pragma unroll
        for (int k = 0; k < 27; k++){
            unsigned long long x2 = pack2(in[k], in[k]);
            const unsigned long long* w2 = (const unsigned long long*)(wt + k*64);
            #pragma unroll
            for (int j = 0; j < 32; j++) fma2(acc[j], w2[j], x2);
        }
        bool inter = (yy >= 1 && yy <= 16 && xx >= 1 && xx <= 16);
        int ob = bb*IMG + gy*256 + gx;
        #pragma unroll
        for (int j = 0; j < 32; j++){
            float a, b2; unpack2(acc[j], a, b2);
            a  = fmaxf(a  + bs[2*j],   0.f);
            b2 = fmaxf(b2 + bs[2*j+1], 0.f);
            fs[(2*j)*324 + hp]   = a;
            fs[(2*j+1)*324 + hp] = b2;
            if (inter){
                g_feat[ob + (2*j)*HW]   = a;
                g_feat[ob + (2*j+1)*HW] = b2;
            }
        }
    }
    __syncthreads();
    int px = tid % 16, py = tid / 16;
    float a8[8];
    #pragma unroll
    for (int k = 0; k < 8; k++) a8[k] = 0.f;
    for (int c = 0; c < 64; c++){
        const float* h = fs + c*324 + py*18 + px;
        float v = tb[c];
        #pragma unroll
        for (int ky = 0; ky < 3; ky++)
            #pragma unroll
            for (int kx = 0; kx < 3; kx++)
                v += tq[c*9 + ky*3 + kx] * h[ky*18 + kx];
        v = fmaxf(v, 0.f);
        #pragma unroll
        for (int k = 0; k < 8; k++) a8[k] += pq[k*64 + c] * v;
    }
    float s[8];
    #pragma unroll
    for (int k = 0; k < 8; k++) s[k] = 1.f / (1.f + expf(-(a8[k] + pb[k])));
    float best = -1e30f; int be = 0;
    #pragma unroll
    for (int e = 0; e < 4; e++){
        float l = rbs[e];
        #pragma unroll
        for (int k = 0; k < 8; k++) l += rws[e*8 + k] * s[k];
        if (l > best){ best = l; be = e; }
    }
    g_top[bb*HW + (ty*16+py)*256 + (tx*16+px)] = be;
}

// ---------------- res-block part A ----------------
// z = e*4+bb; in = feat (BLK 0) or feat + b0e*y0 (BLK 1, folded at stage time)
// GAP via linearity: accumulate per-channel sums of relu(dw) into g_dsum;
// y_kernel applies the pw matrix to these sums (pw is linear).
#define PA_SMEM ((256 + 18756) * 4)
#if USE_TC
template<int BLK>
__global__ void __launch_bounds__(256,3) partA_kernel(const float* __restrict__ edwb, const float* __restrict__ epwb){
    extern __shared__ float sm[];
    uint32_t sbase = smem_u32(sm);
    uint32_t sb1k = (sbase + 1023u) & ~1023u;
    float* base = sm + ((sb1k - sbase) >> 2);
    float* halo  = base + 12292;   // 2912 (8 ch x 364)
    float* dqp   = base + 15204;   // 768
    float* db    = base + 15972;   // 64
    float* pb    = base + 16036;   // 64
    float* ys    = base + 16100;   // 64
    float* dsred = base + 16164;   // 512 (64 ch x 8 warps)
    int tid = threadIdx.x;
    int zz = blockIdx.z;
    int e = zz >> 2, bb = zz & 3;
    int wsel = e*2 + BLK;
    int eb64 = zz * 64;
    const float* srcf = g_feat + (size_t)bb*IMG;
    const float* src1 = BLK ? (g_b0e + (size_t)eb64 * HW) : (const float*)0;
    float* outb = (BLK ? g_b1e : g_b0e) + (size_t)eb64 * HW;
    uint32_t A_addr = sb1k;
    uint32_t B_addr = sb1k + 32768u;
    uint32_t meta   = sb1k + 49152u;
    uint32_t mbar   = sb1k + 49160u;
    if (tid < 32){
        TC_ALLOC(meta, 128);
        TC_RELINQ();
    }
    if (tid == 64) MBAR_INIT(mbar, 1);
    {
        float* Bbuf = base + 8192;
        for (int i = tid; i < 4096; i += 256) Bbuf[i] = d_epw[wsel*4096 + i];
    }
    for (int i = tid; i < 576; i += 256){
        int c9 = i/9, k = i - c9*9;
        dqp[c9*12 + k] = d_edw[wsel*576 + i];
    }
    if (tid < 64){
        db[tid] = edwb[wsel*64 + tid];
        pb[tid] = epwb[wsel*64 + tid];
        ys[tid] = BLK ? g_y0[eb64 + tid] : 0.f;
    }
    __syncthreads();
    uint32_t tmem;
    asm volatile("ld.shared.b32 %0, [%1];" : "=r"(tmem) : "r"(meta));

    int tx = blockIdx.x, ty = blockIdx.y;
    int x0 = tx*16 - 1, y0 = ty*16 - 1;

    // dw strip mapping: q = channel-pair, s = strip (py, 4-px group)
    int q  = tid & 3;
    int s  = tid >> 2;
    int spy = s >> 2;
    int ssx = (s & 3) * 4;
    int lane = tid & 31, warp = tid >> 5;

    // register staging for pipelined halo (8-ci chunks, coalesced i = tid + k*256)
    float sf[11];
    float sbv[BLK ? 11 : 1];
    auto stage = [&](int ch){
        const float* fp = srcf + (size_t)(ch*8)*HW;
        const float* bp = BLK ? (src1 + (size_t)(ch*8)*HW) : (const float*)0;
        #pragma unroll
        for (int k = 0; k < 11; k++){
            int i = tid + k*256;
            float f = 0.f, b = 0.f;
            if (i < 2592){
                int cil = i / 324;
                int r = i - cil*324;
                int yy = r / 18;
                int xx = r - yy*18;
                int gy = y0 + yy, gx = x0 + xx;
                if ((unsigned)gy < 256u && (unsigned)gx < 256u){
                    int off = cil*HW + gy*256 + gx;
                    f = fp[off];
                    if (BLK) b = bp[off];
                }
            }
            sf[k] = f;
            if (BLK) sbv[k] = b;
        }
    };

    stage(0);
    #pragma unroll 1
    for (int ch = 0; ch < 8; ch++){
        __syncthreads();   // prior chunk's halo LDS complete
        #pragma unroll
        for (int k = 0; k < 11; k++){
            int i = tid + k*256;
            if (i < 2592){
                int cil = i / 324;
                int r = i - cil*324;
                int yy = r / 18;
                int xx = r - yy*18;
                float v = sf[k];
                if (BLK) v += sbv[k]*ys[ch*8 + cil];
                halo[cil*364 + yy*20 + xx] = v;
            }
        }
        if (ch < 7) stage(ch+1);
        __syncthreads();
        if (ch == 4){   // A (ci 0-31) fully written -> issue MMA batch 0
            FENCE_ASYNC();
            if (tid < 32 && elect_one_pred()){
                unsigned long long a0 = make_desc(A_addr);
                unsigned long long b0d = make_desc(B_addr);
                #pragma unroll
                for (int t = 0; t < 2; t++)
                    #pragma unroll
                    for (int k = 0; k < 4; k++)
                        mma_tf32_ss(tmem + 64*t, a0 + t*1024 + k*2, b0d + k*2, TF32_IDESC, k > 0);
                TC_COMMIT(mbar);
            }
        }
        // dw conv: 2 channels x 4 pixels per thread, vectorized LDS
        float o[8];
        #pragma unroll
        for (int cc = 0; cc < 2; cc++){
            int cil = q*2 + cc;
            int cg = ch*8 + cil;
            const float* hb = halo + cil*364;
            const float4* wp = (const float4*)(dqp + cg*12);
            float4 wA = wp[0];
            float4 wB = wp[1];
            float4 wC = wp[2];
            float bias = db[cg];
            float o0 = bias, o1 = bias, o2 = bias, o3 = bias;
            #pragma unroll
            for (int ky = 0; ky < 3; ky++){
                const float* rp = hb + (spy + ky)*20 + ssx;
                float4 a = *(const float4*)rp;
                float2 b2 = *(const float2*)(rp + 4);
                float w0, w1, w2;
                if (ky == 0){ w0 = wA.x; w1 = wA.y; w2 = wA.z; }
                else if (ky == 1){ w0 = wA.w; w1 = wB.x; w2 = wB.y; }
                else { w0 = wB.z; w1 = wB.w; w2 = wC.x; }
                o0 += w0*a.x + w1*a.y + w2*a.z;
                o1 += w0*a.y + w1*a.z + w2*a.w;
                o2 += w0*a.z + w1*a.w + w2*b2.x;
                o3 += w0*a.w + w1*b2.x + w2*b2.y;
            }
            o[cc*4+0] = fmaxf(o0, 0.f);
            o[cc*4+1] = fmaxf(o1, 0.f);
            o[cc*4+2] = fmaxf(o2, 0.f);
            o[cc*4+3] = fmaxf(o3, 0.f);
        }
        // GAP partial for dw outputs: 6 shfl per chunk (vs 40 on pw outputs)
        {
            float t0 = (o[0]+o[1]) + (o[2]+o[3]);
            float t1 = (o[4]+o[5]) + (o[6]+o[7]);
            t0 += __shfl_xor_sync(0xffffffffu, t0, 4);
            t0 += __shfl_xor_sync(0xffffffffu, t0, 8);
            t0 += __shfl_xor_sync(0xffffffffu, t0, 16);
            t1 += __shfl_xor_sync(0xffffffffu, t1, 4);
            t1 += __shfl_xor_sync(0xffffffffu, t1, 8);
            t1 += __shfl_xor_sync(0xffffffffu, t1, 16);
            if (lane < 4){
                dsred[(ch*8 + lane*2)*8 + warp]     = t0;
                dsred[(ch*8 + lane*2 + 1)*8 + warp] = t1;
            }
        }
        if (ch == 4) MBAR_WAIT(mbar, 0);   // batch-0 MMA done before A overwrite
        #pragma unroll
        for (int j = 0; j < 4; j++){
            int p = spy*16 + ssx + j;
            uint32_t ad = A_addr + sw128((uint32_t)p*128u + (uint32_t)((ch & 3)*8 + q*2)*4u);
            asm volatile("st.shared.v2.b32 [%0], {%1,%2};"
                :: "r"(ad), "r"(__float_as_uint(o[j])), "r"(__float_as_uint(o[4+j])) : "memory");
        }
    }
    __syncthreads();   // all A-STS + dsred writes done

    if (tid < 64){
        float ssum = (dsred[tid*8+0] + dsred[tid*8+1]) + (dsred[tid*8+2] + dsred[tid*8+3])
                   + (dsred[tid*8+4] + dsred[tid*8+5]) + (dsred[tid*8+6] + dsred[tid*8+7]);
        atomicAdd(&g_dsum[eb64 + tid], ssum);
    }

    FENCE_ASYNC();
    if (tid < 32 && elect_one_pred()){
        unsigned long long a0 = make_desc(A_addr);
        unsigned long long b1d = make_desc(B_addr + 8192u);
        #pragma unroll
        for (int t = 0; t < 2; t++)
            #pragma unroll
            for (int k = 0; k < 4; k++)
                mma_tf32_ss(tmem + 64*t, a0 + t*1024 + k*2, b1d + k*2, TF32_IDESC, 1);
        TC_COMMIT(mbar);
    }
    MBAR_WAIT(mbar, 1);
    TC_FENCE_AFTER();

    int px_ = tid & 15, py_ = tid >> 4;
    int gy = ty*16 + py_, gx = tx*16 + px_;
    size_t ob = (size_t)gy*256 + gx;
    #pragma unroll 1
    for (int hh = 0; hh < 2; hh++){
        uint32_t dr[32];
        TC_LD_X32(dr, tmem + 64*(tid >> 7) + hh*32);
        TC_WAIT_LD();
        #pragma unroll
        for (int c2 = 0; c2 < 32; c2++){
            int c = hh*32 + c2;
            outb[(size_t)c*HW + ob] = __uint_as_float(dr[c2]) + pb[c];
        }
    }
    if (tid == 64) MBAR_INVAL(mbar);
    if (tid < 32) TC_DEALLOC(tmem, 128);
}
#else
// fallback (non-sm_103a pass): f32x2 implementation with dsum GAP
template<int BLK>
__global__ void __launch_bounds__(256,3) partA_kernel(const float* __restrict__ edwb, const float* __restrict__ epwb){
    extern __shared__ float sm[];
    uint32_t sbase = smem_u32(sm);
    uint32_t sb1k = (sbase + 1023u) & ~1023u;
    float* base = sm + ((sb1k - sbase) >> 2);
    float* Bbuf = base + 8192;
    float* halo = base + 12292;
    float* dq   = base + 17476;
    float* db   = base + 18052;
    float* pb   = base + 18116;
    float* ys   = base + 18180;
    float* dsred= base + 18244;   // 512
    int tid = threadIdx.x;
    int zz = blockIdx.z;
    int e = zz >> 2, bb = zz & 3;
    int wsel = e*2 + BLK;
    int eb64 = zz * 64;
    const float* srcf = g_feat + (size_t)bb*IMG;
    const float* src1 = BLK ? (g_b0e + (size_t)eb64 * HW) : (const float*)0;
    float* outb = (BLK ? g_b1e : g_b0e) + (size_t)eb64 * HW;
    for (int i = tid; i < 4096; i += 256) Bbuf[i] = d_epw[wsel*4096 + i];
    for (int i = tid; i < 576;  i += 256) dq[i]   = d_edw[wsel*576 + i];
    if (tid < 64){
        db[tid] = edwb[wsel*64 + tid];
        pb[tid] = epwb[wsel*64 + tid];
        ys[tid] = BLK ? g_y0[eb64 + tid] : 0.f;
    }
    __syncthreads();
    int tx = blockIdx.x, ty = blockIdx.y;
    int x0 = tx*16 - 1, y0 = ty*16 - 1;
    int px_ = tid & 15, py_ = tid >> 4;
    int lane = tid & 31, warp = tid >> 5;
    float sf[11];
    float sbv[BLK ? 11 : 1];
    auto stage = [&](int ch){
        const float* fp = srcf + (size_t)(ch*8)*HW;
        const float* bp = BLK ? (src1 + (size_t)(ch*8)*HW) : (const float*)0;
        #pragma unroll
        for (int k = 0; k < 11; k++){
            int i = tid + k*256;
            float f = 0.f, b = 0.f;
            if (i < 2592){
                int cil = i / 324;
                int r = i - cil*324;
                int yy = r / 18;
                int xx = r - yy*18;
                int gy = y0 + yy, gx = x0 + xx;
                if ((unsigned)gy < 256u && (unsigned)gx < 256u){
                    int off = cil*HW + gy*256 + gx;
                    f = fp[off];
                    if (BLK) b = bp[off];
                }
            }
            sf[k] = f;
            if (BLK) sbv[k] = b;
        }
    };
    unsigned long long acc[32];
    #pragma unroll
    for (int j = 0; j < 32; j++) acc[j] = 0ull;
    stage(0);
    #pragma unroll 1
    for (int ch = 0; ch < 8; ch++){
        float* hbuf = halo + (ch & 1)*2592;
        #pragma unroll
        for (int k = 0; k < 11; k++){
            int i = tid + k*256;
            if (i < 2592){
                float v = sf[k];
                if (BLK){ int cil = i/324; v += sbv[k]*ys[ch*8 + cil]; }
                hbuf[i] = v;
            }
        }
        if (ch < 7) stage(ch+1);
        __syncthreads();
        #pragma unroll
        for (int u = 0; u < 8; u++){
            int cg = ch*8 + u;
            const float* h = hbuf + u*324 + py_*18 + px_;
            const float* w9 = dq + cg*9;
            float v = db[cg];
            #pragma unroll
            for (int ky = 0; ky < 3; ky++)
                #pragma unroll
                for (int kx = 0; kx < 3; kx++)
                    v += w9[ky*3 + kx] * h[ky*18 + kx];
            v = fmaxf(v, 0.f);
            // dsum reduction over pixels
            float r2 = v;
            r2 += __shfl_xor_sync(0xffffffffu, r2, 16);
            r2 += __shfl_xor_sync(0xffffffffu, r2, 8);
            r2 += __shfl_xor_sync(0xffffffffu, r2, 4);
            r2 += __shfl_xor_sync(0xffffffffu, r2, 2);
            r2 += __shfl_xor_sync(0xffffffffu, r2, 1);
            if (lane == 0) dsred[cg*8 + warp] = r2;
            unsigned long long x2 = pack2(v, v);
            const ulonglong2* w4 = (const ulonglong2*)(Bbuf + cg*64);
            #pragma unroll
            for (int j = 0; j < 16; j++){
                ulonglong2 w = w4[j];
                fma2(acc[2*j],   w.x, x2);
                fma2(acc[2*j+1], w.y, x2);
            }
        }
        __syncthreads();
    }
    if (tid < 64){
        float s = 0.f;
        #pragma unroll
        for (int i = 0; i < 8; i++) s += dsred[tid*8 + i];
        atomicAdd(&g_dsum[eb64 + tid], s);
    }
    int gy = ty*16 + py_, gx = tx*16 + px_;
    size_t ob = (size_t)gy*256 + gx;
    #pragma unroll
    for (int j = 0; j < 32; j++){
        float a, b2; unpack2(acc[j], a, b2);
        outb[(size_t)(2*j)*HW + ob]   = a  + pb[2*j];
        outb[(size_t)(2*j+1)*HW + ob] = b2 + pb[2*j+1];
    }
}
#endif

// ---------------- channel attention (one block per expert) ----------------
// m[c] = (pwW[c,:] . dsum)/65536 + pwb[c]  (pw is linear; exact GAP)
__global__ void y_kernel(const float* __restrict__ fc1_all, const float* __restrict__ fc2_all,
                         const float* __restrict__ epwb, int blk){
    __shared__ float m[256];
    __shared__ float h1[64];
    __shared__ float ds[256];
    int tid = threadIdx.x;
    int e = blockIdx.x;
    int wsel = e*2 + blk;
    const float* fc1 = fc1_all + wsel*1024;
    const float* fc2 = fc2_all + wsel*1024;
    int base = e*256;
    ds[tid] = g_dsum[base + tid];
    __syncthreads();
    g_dsum[base + tid] = 0.f;
    {
        int b = tid >> 6, c = tid & 63;
        const float* W = d_epw_p + wsel*4096 + c*64;
        const float* dv = ds + b*64;
        float s = 0.f;
        #pragma unroll 8
        for (int ci = 0; ci < 64; ci++) s += W[ci] * dv[ci];
        m[tid] = s * (1.f / 65536.f) + epwb[wsel*64 + c];
    }
    __syncthreads();
    if (tid < 64){
        int b = tid / 16, j = tid % 16;
        float s = 0.f;
        for (int c = 0; c < 64; c++) s += m[b*64 + c] * fc1[j*64 + c];
        h1[tid] = fmaxf(s, 0.f);
    }
    __syncthreads();
    int b = tid / 64, co = tid % 64;
    float s = 0.f;
    #pragma unroll
    for (int j = 0; j < 16; j++) s += h1[b*16 + j] * fc2[co*16 + j];
    float yv = 1.f / (1.f + expf(-s));
    if (blk) g_y1[base + tid] = yv; else g_y0[base + tid] = yv;
}

// ---------------- MoE select: per-pixel expert gather ----------------
__global__ void __launch_bounds__(256) select_kernel(){
    int pix = blockIdx.x*256 + threadIdx.x;
    int bb = pix / HW, pr = pix % HW;
    int e = g_top[pix];
    int eb64 = (e*4 + bb)*64;
    const float* y0 = g_y0 + eb64;
    const float* y1 = g_y1 + eb64;
    const float* b0 = g_b0e + (size_t)eb64*HW + pr;
    const float* b1 = g_b1e + (size_t)eb64*HW + pr;
    int base = bb*IMG + pr;
    #pragma unroll 4
    for (int c = 0; c < 64; c++){
        g_moe[base + c*HW] = g_feat[base + c*HW] + b0[(size_t)c*HW]*y0[c] + b1[(size_t)c*HW]*y1[c];
    }
}

// ---------------- recon 64->12 3x3 + pixel shuffle + bilinear skip ----------------
#define RC_SMEM ((20736 + 972 + 6912 + 12) * 4)
__global__ void __launch_bounds__(256) recon_kernel(const float* __restrict__ x, const float* __restrict__ rcb){
    extern __shared__ float sm[];
    float* halo = sm;            // 20736
    float* xs   = halo + 20736;  // 972
    float* wt   = xs + 972;      // 6912
    float* rb   = wt + 6912;     // 12
    int tid = threadIdx.x;
    for (int i = tid; i < 6912; i += 256) wt[i] = d_rect[i];
    if (tid < 12) rb[tid] = rcb[tid];
    int tx = blockIdx.x, ty = blockIdx.y, bb = blockIdx.z;
    int x0 = tx*16 - 1, y0 = ty*16 - 1;
    for (int i = tid; i < 64*324; i += 256){
        int c = i/324, r = i%324, yy = r/18, xx = r%18;
        int gy = y0 + yy, gx = x0 + xx;
        float v = 0.f;
        if ((unsigned)gy < 256u && (unsigned)gx < 256u) v = g_moe[(bb*64+c)*HW + gy*256 + gx];
        halo[i] = v;
    }
    for (int i = tid; i < 3*324; i += 256){
        int c = i/324, r = i%324, yy = r/18, xx = r%18;
        int gy = min(max(y0 + yy, 0), 255), gx = min(max(x0 + xx, 0), 255);
        xs[i] = x[(bb*3+c)*HW + gy*256 + gx];
    }
    __syncthreads();
    int px = tid % 16, py = tid / 16;
    unsigned long long acc[6];
    #pragma unroll
    for (int j = 0; j < 6; j++) acc[j] = 0ull;
    for (int ci = 0; ci < 64; ci++){
        const float* h = halo + ci*324 + py*18 + px;
        #pragma unroll
        for (int k = 0; k < 9; k++){
            float xv = h[(k/3)*18 + (k%3)];
            unsigned long long x2 = pack2(xv, xv);
            const unsigned long long* w2 = (const unsigned long long*)(wt + (ci*9 + k)*12);
            ulonglong2 wa = *(const ulonglong2*)w2;
            unsigned long long wc = w2[2];
            fma2(acc[0], wa.x, x2);
            fma2(acc[1], wa.y, x2);
            fma2(acc[2], wc,   x2);
            ulonglong2 wb = *(const ulonglong2*)(w2 + 3);
            unsigned long long wd = w2[5];
            fma2(acc[3], wb.x, x2);
            fma2(acc[4], wb.y, x2);
            fma2(acc[5], wd,   x2);
        }
    }
    float cv[12];
    #pragma unroll
    for (int j = 0; j < 6; j++){
        float a, b2; unpack2(acc[j], a, b2);
        cv[2*j]   = a  + rb[2*j];
        cv[2*j+1] = b2 + rb[2*j+1];
    }
    int gy = ty*16 + py, gx = tx*16 + px;
    #pragma unroll
    for (int r1 = 0; r1 < 2; r1++){
        int ly0 = r1 ? py+1 : py;
        int ly1 = ly0 + 1;
        float wy0 = r1 ? 0.75f : 0.25f;
        float wy1 = 1.f - wy0;
        #pragma unroll
        for (int r2 = 0; r2 < 2; r2++){
            int lx0 = r2 ? px+1 : px;
            int lx1 = lx0 + 1;
            float wx0 = r2 ? 0.75f : 0.25f;
            float wx1 = 1.f - wx0;
            int oh = 2*gy + r1, ow = 2*gx + r2;
            #pragma unroll
            for (int co = 0; co < 3; co++){
                const float* xc = xs + co*324;
                float up = wy0*(wx0*xc[ly0*18+lx0] + wx1*xc[ly0*18+lx1])
                         + wy1*(wx0*xc[ly1*18+lx0] + wx1*xc[ly1*18+lx1]);
                int ch = co*4 + r1*2 + r2;
                g_sr[(bb*3+co)*262144 + oh*512 + ow] = cv[ch] + up;
            }
        }
    }
}

// ---------------- refinement: out = sr + conv2(relu(conv1(sr))) ----------------
__global__ void __launch_bounds__(256) ref_kernel(const float* __restrict__ b1, const float* __restrict__ b2,
                                                  float* __restrict__ out){
    __shared__ float srh[3*432];   // 3 x 12 x 36
    __shared__ float th[3*340];    // 3 x 10 x 34
    __shared__ float w1[81], w2[81], sb1[3], sb2[3];
    int tid = threadIdx.x;
    if (tid < 81){ w1[tid] = d_ref1[tid]; w2[tid] = d_ref2[tid]; }
    if (tid < 3){ sb1[tid] = b1[tid]; sb2[tid] = b2[tid]; }
    int tx = blockIdx.x, ty = blockIdx.y, bb = blockIdx.z;
    int X0 = tx*32, Y0 = ty*8;
    for (int i = tid; i < 3*432; i += 256){
        int c = i/432, r = i%432, yy = r/36, xx = r%36;
        int gy = Y0 + yy - 2, gx = X0 + xx - 2;
        float v = 0.f;
        if ((unsigned)gy < 512u && (unsigned)gx < 512u) v = g_sr[(bb*3+c)*262144 + gy*512 + gx];
        srh[i] = v;
    }
    __syncthreads();
    for (int i = tid; i < 3*340; i += 256){
        int c = i/340, r = i%340, yy = r/34, xx = r%34;
        int gy = Y0 + yy - 1, gx = X0 + xx - 1;
        float v = 0.f;
        if ((unsigned)gy < 512u && (unsigned)gx < 512u){
            v = sb1[c];
            #pragma unroll
            for (int ci = 0; ci < 3; ci++)
                #pragma unroll
                for (int ky = 0; ky < 3; ky++)
                    #pragma unroll
                    for (int kx = 0; kx < 3; kx++)
                        v += w1[(c*3+ci)*9 + ky*3 + kx] * srh[ci*432 + (yy+ky)*36 + (xx+kx)];
            v = fmaxf(v, 0.f);
        }
        th[i] = v;
    }
    __syncthreads();
    int px = tid % 32, py = tid / 32;
    int oh = Y0 + py, ow = X0 + px;
    #pragma unroll
    for (int co = 0; co < 3; co++){
        float v = sb2[co];
        #pragma unroll
        for (int ci = 0; ci < 3; ci++)
            #pragma unroll
            for (int ky = 0; ky < 3; ky++)
                #pragma unroll
                for (int kx = 0; kx < 3; kx++)
                    v += w2[(co*3+ci)*9 + ky*3 + kx] * th[ci*340 + (py+ky)*34 + (px+kx)];
        out[(bb*3+co)*262144 + oh*512 + ow] = srh[co*432 + (py+2)*36 + (px+2)] + v;
    }
}

// ---------------- launch ----------------
extern "C" void kernel_launch(void* const* d_in, const int* in_sizes, int n_in,
                              void* d_out, int out_size){
    const float* x         = (const float*)d_in[0];
    const float* shallow_w = (const float*)d_in[1];
    const float* shallow_b = (const float*)d_in[2];
    const float* tex_dw_w  = (const float*)d_in[3];
    const float* tex_dw_b  = (const float*)d_in[4];
    const float* tex_pw_w  = (const float*)d_in[5];
    const float* tex_pw_b  = (const float*)d_in[6];
    const float* router_w  = (const float*)d_in[7];
    const float* router_b  = (const float*)d_in[8];
    const float* exp_dw_w  = (const float*)d_in[9];
    const float* exp_dw_b  = (const float*)d_in[10];
    const float* exp_pw_w  = (const float*)d_in[11];
    const float* exp_pw_b  = (const float*)d_in[12];
    const float* fc1       = (const float*)d_in[13];
    const float* fc2       = (const float*)d_in[14];
    const float* recon_w   = (const float*)d_in[15];
    const float* recon_b   = (const float*)d_in[16];
    const float* ref1_w    = (const float*)d_in[17];
    const float* ref1_b    = (const float*)d_in[18];
    const float* ref2_w    = (const float*)d_in[19];
    const float* ref2_b    = (const float*)d_in[20];
    float* out = (float*)d_out;

    cudaFuncSetAttribute(shallow_tex_kernel, cudaFuncAttributeMaxDynamicSharedMemorySize, ST_SMEM);
    cudaFuncSetAttribute(partA_kernel<0>, cudaFuncAttributeMaxDynamicSharedMemorySize, PA_SMEM);
    cudaFuncSetAttribute(partA_kernel<1>, cudaFuncAttributeMaxDynamicSharedMemorySize, PA_SMEM);
    cudaFuncSetAttribute(recon_kernel,    cudaFuncAttributeMaxDynamicSharedMemorySize, RC_SMEM);

    prep_kernel<<<22, 256>>>(shallow_w, tex_dw_w, tex_pw_w, exp_dw_w, exp_pw_w, ref1_w, ref2_w, recon_w);

    dim3 g16(16, 16, 4);
    shallow_tex_kernel<<<g16, 256, ST_SMEM>>>(x, shallow_b, tex_dw_b, tex_pw_b, router_w, router_b);

    dim3 gA(16, 16, 16);   // z = e*4 + batch
    partA_kernel<0><<<gA, 256, PA_SMEM>>>(exp_dw_b, exp_pw_b);
    y_kernel<<<4, 256>>>(fc1, fc2, exp_pw_b, 0);
    partA_kernel<1><<<gA, 256, PA_SMEM>>>(exp_dw_b, exp_pw_b);
    y_kernel<<<4, 256>>>(fc1, fc2, exp_pw_b, 1);
    select_kernel<<<1024, 256>>>();

    recon_kernel<<<g16, 256, RC_SMEM>>>(x, recon_b);

    dim3 gref(16, 64, 4);
    ref_kernel<<<gref, 256>>>(ref1_b, ref2_b, out);
}

// round 12
// speedup vs baseline: 1.6849x; 1.0388x over previous
#include <cuda_runtime.h>
#include <math.h>
#include <stdint.h>

#if (defined(__CUDA_ARCH_FEAT_SM103_ALL) || (defined(__CUDA_ARCH_SPECIFIC__) && (__CUDA_ARCH__ == 1030)))
#define USE_TC 1
#else
#define USE_TC 0
#endif

#define BATCH 4
#define CCH 64
#define HH 256
#define WWI 256
#define HW (HH*WWI)
#define IMG (CCH*HW)
#define NPIX (BATCH*HW)

// ---------------- scratch (device globals, no allocs) ----------------
__device__ float g_feat[BATCH*CCH*HW];
__device__ float g_b0e[4*BATCH*CCH*HW];   // per-expert block-0 residual branch
__device__ float g_b1e[4*BATCH*CCH*HW];   // per-expert block-1 residual branch
__device__ float g_moe[BATCH*CCH*HW];
__device__ float g_sr[BATCH*3*512*512];
__device__ int   g_top[NPIX];
__device__ float g_dsum[4*BATCH*CCH];     // [e][b][ci]: per-image sums of relu(dw)
__device__ float g_y0[4*BATCH*CCH];
__device__ float g_y1[4*BATCH*CCH];
// quantized / transposed weights
__device__ float d_sq_t[27*64];     // shallow, transposed [k][co]
__device__ float d_texdw[576];
__device__ float d_texpw[512];
__device__ float d_edw[8*576];
__device__ float d_epw[8*4096];     // pw weights: SW128 MMA layout (TC) or [ci][co] (fallback)
__device__ float d_epw_p[8*4096];   // pw weights plain [co][ci] (ternarized) for y_kernel
__device__ float d_ref1[81];
__device__ float d_ref2[81];
__device__ float d_rect[576*12];    // recon transposed [ci*9+k][co]

// ---------------- f32x2 helpers ----------------
__device__ __forceinline__ unsigned long long pack2(float a, float b){
    unsigned long long r;
    asm("mov.b64 %0, {%1, %2};" : "=l"(r) : "r"(__float_as_uint(a)), "r"(__float_as_uint(b)));
    return r;
}
__device__ __forceinline__ void unpack2(unsigned long long v, float& a, float& b){
    unsigned int x, y;
    asm("mov.b64 {%0, %1}, %2;" : "=r"(x), "=r"(y) : "l"(v));
    a = __uint_as_float(x); b = __uint_as_float(y);
}
__device__ __forceinline__ void fma2(unsigned long long& acc, unsigned long long w, unsigned long long x){
    asm("fma.rn.f32x2 %0, %1, %2, %0;" : "+l"(acc) : "l"(w), "l"(x));
}

__device__ __forceinline__ uint32_t smem_u32(const void* p){
    uint32_t a;
    asm("{ .reg .u64 t; cvta.to.shared.u64 t, %1; cvt.u32.u64 %0, t; }" : "=r"(a) : "l"(p));
    return a;
}

__host__ __device__ __forceinline__ uint32_t sw128(uint32_t off){ return off ^ ((off >> 3) & 0x70); }

#if USE_TC
// ---------------- tcgen05 / mbarrier helpers (sm_103a-specific pass only) ----------------
__device__ __forceinline__ uint32_t elect_one_pred(){
    uint32_t pred;
    asm volatile("{\n\t.reg .pred p;\n\telect.sync _|p, 0xFFFFFFFF;\n\tselp.b32 %0, 1, 0, p;\n\t}" : "=r"(pred));
    return pred;
}
#define TC_ALLOC(sa, n)   asm volatile("tcgen05.alloc.cta_group::1.sync.aligned.shared::cta.b32 [%0], %1;" :: "r"(sa), "r"((uint32_t)(n)) : "memory")
#define TC_DEALLOC(t, n)  asm volatile("tcgen05.dealloc.cta_group::1.sync.aligned.b32 %0, %1;" :: "r"(t), "r"((uint32_t)(n)))
#define TC_RELINQ()       asm volatile("tcgen05.relinquish_alloc_permit.cta_group::1.sync.aligned;")
#define TC_COMMIT(mb)     asm volatile("tcgen05.commit.cta_group::1.mbarrier::arrive::one.shared::cluster.b64 [%0];" :: "r"(mb) : "memory")
#define TC_FENCE_AFTER()  asm volatile("tcgen05.fence::after_thread_sync;" ::: "memory")
#define TC_WAIT_LD()      asm volatile("tcgen05.wait::ld.sync.aligned;" ::: "memory")
#define FENCE_ASYNC()     asm volatile("fence.proxy.async.shared::cta;" ::: "memory")
#define MBAR_INIT(mb, c)  asm volatile("mbarrier.init.shared.b64 [%0], %1;" :: "r"(mb), "r"((uint32_t)(c)) : "memory")
#define MBAR_INVAL(mb)    asm volatile("mbarrier.inval.shared.b64 [%0];" :: "r"(mb) : "memory")
#define MBAR_WAIT(mb, ph) do { \
    uint32_t _mb = (mb); uint32_t _p = (ph); uint32_t _done; \
    asm volatile("{\n\t.reg .pred p;\n\tmbarrier.try_wait.parity.acquire.cta.shared::cta.b64 p, [%1], %2;\n\tselp.b32 %0, 1, 0, p;\n\t}" \
        : "=r"(_done) : "r"(_mb), "r"(_p) : "memory"); \
    if (!_done){ \
        asm volatile("{\n\t.reg .pred P1;\n\tWL_%=:\n\tmbarrier.try_wait.parity.acquire.cta.shared::cta.b64 P1, [%0], %1, 0x989680;\n\t@P1 bra.uni WD_%=;\n\tbra.uni WL_%=;\n\tWD_%=:\n\t}" \
            :: "r"(_mb), "r"(_p) : "memory"); \
    } \
} while(0)
#define TC_LD_X32(r, ta) \
    asm volatile("tcgen05.ld.sync.aligned.32x32b.x32.b32 " \
        "{%0, %1, %2, %3, %4, %5, %6, %7, %8, %9, %10, %11, %12, %13, %14, %15, " \
        " %16, %17, %18, %19, %20, %21, %22, %23, %24, %25, %26, %27, %28, %29, %30, %31}, [%32];" \
        : "=r"((r)[0]),  "=r"((r)[1]),  "=r"((r)[2]),  "=r"((r)[3]), \
          "=r"((r)[4]),  "=r"((r)[5]),  "=r"((r)[6]),  "=r"((r)[7]), \
          "=r"((r)[8]),  "=r"((r)[9]),  "=r"((r)[10]), "=r"((r)[11]), \
          "=r"((r)[12]), "=r"((r)[13]), "=r"((r)[14]), "=r"((r)[15]), \
          "=r"((r)[16]), "=r"((r)[17]), "=r"((r)[18]), "=r"((r)[19]), \
          "=r"((r)[20]), "=r"((r)[21]), "=r"((r)[22]), "=r"((r)[23]), \
          "=r"((r)[24]), "=r"((r)[25]), "=r"((r)[26]), "=r"((r)[27]), \
          "=r"((r)[28]), "=r"((r)[29]), "=r"((r)[30]), "=r"((r)[31]) \
        : "r"(ta))

__device__ __forceinline__ void mma_tf32_ss(uint32_t d_tmem, unsigned long long a_desc,
                                            unsigned long long b_desc, uint32_t idesc, int en){
    asm volatile(
        "{\n\t.reg .pred p;\n\tsetp.ne.u32 p, %4, 0;\n\t"
        "tcgen05.mma.cta_group::1.kind::tf32 [%0], %1, %2, %3, p;\n\t}"
        :: "r"(d_tmem), "l"(a_desc), "l"(b_desc), "r"(idesc), "r"((uint32_t)en) : "memory");
}

// SW128 smem descriptor: LBO=1, SBO=64, version=1, layout SW128
__device__ __forceinline__ unsigned long long make_desc(uint32_t addr){
    const unsigned long long base =
        (2ull << 61) | (1ull << 46) | (64ull << 32) | (1ull << 16);
    return base | (((unsigned long long)(addr >> 4)) & 0x3FFF);
}
// idesc: dtype F32, atype/btype TF32 (2), N=64, M=128
#define TF32_IDESC 0x8100910u
#endif  // USE_TC

// ---------------- weight prep: TWN ternarize (+ transposes) ----------------
__global__ void prep_kernel(const float* shallow_w, const float* tex_dw_w, const float* tex_pw_w,
                            const float* exp_dw_w, const float* exp_pw_w,
                            const float* ref1_w, const float* ref2_w, const float* recon_w)
{
    __shared__ float sred[256];
    __shared__ float sred2[256];
    int blk = blockIdx.x, tid = threadIdx.x;
    const float* src; float* dst; int n; int mode; bool quant = true;
    if (blk == 0)       { src = shallow_w; dst = d_sq_t;  n = 1728; mode = 1; }
    else if (blk == 1)  { src = tex_dw_w;  dst = d_texdw; n = 576;  mode = 0; }
    else if (blk == 2)  { src = tex_pw_w;  dst = d_texpw; n = 512;  mode = 0; }
    else if (blk < 11)  { int eb = blk-3;  src = exp_dw_w + eb*576;  dst = d_edw + eb*576;  n = 576;  mode = 0; }
    else if (blk < 19)  { int eb = blk-11; src = exp_pw_w + eb*4096; dst = d_epw + eb*4096; n = 4096; mode = 2; }
    else if (blk == 19) { src = ref1_w; dst = d_ref1; n = 81; mode = 0; }
    else if (blk == 20) { src = ref2_w; dst = d_ref2; n = 81; mode = 0; }
    else                { src = recon_w; dst = d_rect; n = 6912; mode = 3; quant = false; }

    if (!quant){
        for (int i = tid; i < n; i += 256){ int co = i/576, t = i%576; dst[t*12 + co] = src[i]; }
        for (int i = tid; i < 4*BATCH*CCH; i += 256) g_dsum[i] = 0.f;   // init GAP accumulator once
        return;
    }
    float s = 0.f;
    for (int i = tid; i < n; i += 256) s += fabsf(src[i]);
    sred[tid] = s; __syncthreads();
    for (int off = 128; off; off >>= 1){ if (tid < off) sred[tid] += sred[tid+off]; __syncthreads(); }
    float delta = 0.75f * sred[0] / (float)n;
    __syncthreads();
    float s2 = 0.f, c2 = 0.f;
    for (int i = tid; i < n; i += 256){ float a = fabsf(src[i]); if (a > delta){ s2 += a; c2 += 1.f; } }
    sred[tid] = s2; sred2[tid] = c2; __syncthreads();
    for (int off = 128; off; off >>= 1){
        if (tid < off){ sred[tid] += sred[tid+off]; sred2[tid] += sred2[tid+off]; }
        __syncthreads();
    }
    float alpha = sred[0] / fmaxf(sred2[0], 1.f);
    for (int i = tid; i < n; i += 256){
        float w = src[i];
        float q = (fabsf(w) > delta) ? copysignf(alpha, w) : 0.f;
        int j;
        if (mode == 0) j = i;
        else if (mode == 1){ int co = i/27, k = i%27; j = k*64 + co; }
        else {
            int co = i/64, ci = i%64;
            d_epw_p[(blk-11)*4096 + i] = q;   // plain [co][ci] copy for y_kernel
#if USE_TC
            // MMA SW128 K-major layout: chunk(ci/32), row co (128B), col ci%32
            uint32_t byte = (uint32_t)(ci>>5)*8192u + sw128((uint32_t)co*128u + (uint32_t)(ci&31)*4u);
            j = (int)(byte >> 2);
#else
            j = ci*64 + co;   // transposed [ci][co]
#endif
        }
        dst[j] = q;
    }
}

// ---------------- FUSED shallow conv + texture encoder + router + argmax ----------------
#define ST_SMEM ((20736 + 1200 + 1728 + 576 + 64 + 512 + 8 + 32 + 4 + 64) * 4)
__global__ void __launch_bounds__(256,2) shallow_tex_kernel(
    const float* __restrict__ x, const float* __restrict__ sb,
    const float* __restrict__ tdwb, const float* __restrict__ tpwb,
    const float* __restrict__ rw,   const float* __restrict__ rb){
    extern __shared__ float sm[];
    float* fs  = sm;             // 20736 (64 x 324)
    float* xs  = fs + 20736;     // 1200 (3 x 400: 20x20 x-halo)
    float* wt  = xs + 1200;      // 1728 (shallow, [k][co])
    float* tq  = wt + 1728;      // 576
    float* tb  = tq + 576;       // 64
    float* pq  = tb + 64;        // 512
    float* pb  = pq + 512;       // 8
    float* rws = pb + 8;         // 32
    float* rbs = rws + 32;       // 4
    float* bs  = rbs + 4;        // 64
    int tid = threadIdx.x;
    int tx = blockIdx.x, ty = blockIdx.y, bb = blockIdx.z;
    for (int i = tid; i < 1728; i += 256) wt[i] = d_sq_t[i];
    for (int i = tid; i < 576;  i += 256) tq[i] = d_texdw[i];
    for (int i = tid; i < 512;  i += 256) pq[i] = d_texpw[i];
    if (tid < 64) tb[tid] = tdwb[tid];
    if (tid < 8)  pb[tid] = tpwb[tid];
    if (tid < 32) rws[tid] = rw[tid];
    if (tid < 4)  rbs[tid] = rb[tid];
    if (tid < 64) bs[tid] = sb[tid];
    int X0 = tx*16 - 2, Y0 = ty*16 - 2;
    for (int i = tid; i < 1200; i += 256){
        int c = i/400, r = i%400, yy = r/20, xx = r%20;
        int gy = Y0 + yy, gx = X0 + xx;
        float v = 0.f;
        if ((unsigned)gy < 256u && (unsigned)gx < 256u) v = x[(bb*3+c)*HW + gy*256 + gx];
        xs[i] = v;
    }
    __syncthreads();
    for (int hp = tid; hp < 324; hp += 256){
        int yy = hp/18, xx = hp%18;
        int gy = ty*16 - 1 + yy, gx = tx*16 - 1 + xx;
        if ((unsigned)gy >= 256u || (unsigned)gx >= 256u){
            #pragma unroll 8
            for (int c = 0; c < 64; c++) fs[c*324 + hp] = 0.f;
            continue;
        }
        float in[27];
        #pragma unroll
        for (int c = 0; c < 3; c++)
            #pragma unroll
            for (int ky = 0; ky < 3; ky++)
                #pragma unroll
                for (int kx = 0; kx < 3; kx++)
                    in[c*9 + ky*3 + kx] = xs[c*400 + (yy+ky)*20 + (xx+kx)];
        unsigned long long acc[32];
        #pragma unroll
        for (int j = 0; j < 32; j++) acc[j] = 0ull;
        #pragma unroll
        for (int k = 0; k < 27; k++){
            unsigned long long x2 = pack2(in[k], in[k]);
            const unsigned long long* w2 = (const unsigned long long*)(wt + k*64);
            #pragma unroll
            for (int j = 0; j < 32; j++) fma2(acc[j], w2[j], x2);
        }
        bool inter = (yy >= 1 && yy <= 16 && xx >= 1 && xx <= 16);
        int ob = bb*IMG + gy*256 + gx;
        #pragma unroll
        for (int j = 0; j < 32; j++){
            float a, b2; unpack2(acc[j], a, b2);
            a  = fmaxf(a  + bs[2*j],   0.f);
            b2 = fmaxf(b2 + bs[2*j+1], 0.f);
            fs[(2*j)*324 + hp]   = a;
            fs[(2*j+1)*324 + hp] = b2;
            if (inter){
                g_feat[ob + (2*j)*HW]   = a;
                g_feat[ob + (2*j+1)*HW] = b2;
            }
        }
    }
    __syncthreads();
    int px = tid % 16, py = tid / 16;
    float a8[8];
    #pragma unroll
    for (int k = 0; k < 8; k++) a8[k] = 0.f;
    for (int c = 0; c < 64; c++){
        const float* h = fs + c*324 + py*18 + px;
        float v = tb[c];
        #pragma unroll
        for (int ky = 0; ky < 3; ky++)
            #pragma unroll
            for (int kx = 0; kx < 3; kx++)
                v += tq[c*9 + ky*3 + kx] * h[ky*18 + kx];
        v = fmaxf(v, 0.f);
        #pragma unroll
        for (int k = 0; k < 8; k++) a8[k] += pq[k*64 + c] * v;
    }
    float s[8];
    #pragma unroll
    for (int k = 0; k < 8; k++) s[k] = 1.f / (1.f + expf(-(a8[k] + pb[k])));
    float best = -1e30f; int be = 0;
    #pragma unroll
    for (int e = 0; e < 4; e++){
        float l = rbs[e];
        #pragma unroll
        for (int k = 0; k < 8; k++) l += rws[e*8 + k] * s[k];
        if (l > best){ best = l; be = e; }
    }
    g_top[bb*HW + (ty*16+py)*256 + (tx*16+px)] = be;
}

// ---------------- res-block part A ----------------
// z = e*4+bb; in = feat (BLK 0) or feat + b0e*y0 (BLK 1, folded at stage time)
// halo: 8 ch x (18 rows x 20 cols), channel stride 364, col h <-> gx = tx*16-2+h
// staging in float2 units (gx even, width even => lanes jointly valid)
#define PA_SMEM ((256 + 18756) * 4)
#if USE_TC
template<int BLK>
__global__ void __launch_bounds__(256,3) partA_kernel(const float* __restrict__ edwb, const float* __restrict__ epwb){
    extern __shared__ float sm[];
    uint32_t sbase = smem_u32(sm);
    uint32_t sb1k = (sbase + 1023u) & ~1023u;
    float* base = sm + ((sb1k - sbase) >> 2);
    float* halo  = base + 12292;   // 2912 (8 ch x 364)
    float* dqp   = base + 15204;   // 768
    float* db    = base + 15972;   // 64
    float* pb    = base + 16036;   // 64
    float* ys    = base + 16100;   // 64
    float* dsred = base + 16164;   // 512 (64 ch x 8 warps)
    int tid = threadIdx.x;
    int zz = blockIdx.z;
    int e = zz >> 2, bb = zz & 3;
    int wsel = e*2 + BLK;
    int eb64 = zz * 64;
    const float* srcf = g_feat + (size_t)bb*IMG;
    const float* src1 = BLK ? (g_b0e + (size_t)eb64 * HW) : (const float*)0;
    float* outb = (BLK ? g_b1e : g_b0e) + (size_t)eb64 * HW;
    uint32_t A_addr = sb1k;
    uint32_t B_addr = sb1k + 32768u;
    uint32_t meta   = sb1k + 49152u;
    uint32_t mbar   = sb1k + 49160u;
    if (tid < 32){
        TC_ALLOC(meta, 128);
        TC_RELINQ();
    }
    if (tid == 64) MBAR_INIT(mbar, 1);
    {
        float* Bbuf = base + 8192;
        for (int i = tid; i < 4096; i += 256) Bbuf[i] = d_epw[wsel*4096 + i];
    }
    for (int i = tid; i < 576; i += 256){
        int c9 = i/9, k = i - c9*9;
        dqp[c9*12 + k] = d_edw[wsel*576 + i];
    }
    if (tid < 64){
        db[tid] = edwb[wsel*64 + tid];
        pb[tid] = epwb[wsel*64 + tid];
        ys[tid] = BLK ? g_y0[eb64 + tid] : 0.f;
    }
    __syncthreads();
    uint32_t tmem;
    asm volatile("ld.shared.b32 %0, [%1];" : "=r"(tmem) : "r"(meta));

    int tx = blockIdx.x, ty = blockIdx.y;
    int y0m1 = ty*16 - 1;     // halo row 0 => gy = y0m1
    int x0m2 = tx*16 - 2;     // halo col 0 => gx = x0m2 (even)

    // dw strip mapping: q = channel-pair, s = strip (py, 4-px group)
    int q  = tid & 3;
    int s  = tid >> 2;
    int spy = s >> 2;
    int ssx = (s & 3) * 4;
    int lane = tid & 31, warp = tid >> 5;

    // float2 staging: 1440 units/chunk, 6 per thread
    float2 sf[6];
    float2 sbv[BLK ? 6 : 1];
    auto stage = [&](int ch){
        const float* fp = srcf + (size_t)(ch*8)*HW;
        const float* bp = BLK ? (src1 + (size_t)(ch*8)*HW) : (const float*)0;
        #pragma unroll
        for (int k = 0; k < 6; k++){
            int u = tid + k*256;
            float2 f = make_float2(0.f, 0.f);
            float2 b = make_float2(0.f, 0.f);
            if (u < 1440){
                int cil = u / 180;
                int rem = u - cil*180;
                int yy = rem / 10;
                int xc = rem - yy*10;
                int gy = y0m1 + yy;
                int gx = x0m2 + xc*2;
                if ((unsigned)gy < 256u && (unsigned)gx < 256u){
                    int off = cil*HW + gy*256 + gx;
                    f = *(const float2*)(fp + off);
                    if (BLK) b = *(const float2*)(bp + off);
                }
            }
            sf[k] = f;
            if (BLK) sbv[k] = b;
        }
    };

    stage(0);
    #pragma unroll 1
    for (int ch = 0; ch < 8; ch++){
        __syncthreads();   // prior chunk's halo LDS complete
        #pragma unroll
        for (int k = 0; k < 6; k++){
            int u = tid + k*256;
            if (u < 1440){
                int cil = u / 180;
                int rem = u - cil*180;
                int yy = rem / 10;
                int xc = rem - yy*10;
                float2 v = sf[k];
                if (BLK){
                    float ysc = ys[ch*8 + cil];
                    v.x += sbv[k].x * ysc;
                    v.y += sbv[k].y * ysc;
                }
                *(float2*)(halo + cil*364 + yy*20 + xc*2) = v;
            }
        }
        if (ch < 7) stage(ch+1);
        __syncthreads();
        if (ch == 4){   // A (ci 0-31) fully written -> issue MMA batch 0
            FENCE_ASYNC();
            if (tid < 32 && elect_one_pred()){
                unsigned long long a0 = make_desc(A_addr);
                unsigned long long b0d = make_desc(B_addr);
                #pragma unroll
                for (int t = 0; t < 2; t++)
                    #pragma unroll
                    for (int k = 0; k < 4; k++)
                        mma_tf32_ss(tmem + 64*t, a0 + t*1024 + k*2, b0d + k*2, TF32_IDESC, k > 0);
                TC_COMMIT(mbar);
            }
        }
        // dw conv: 2 channels x 4 pixels per thread; two aligned LDS.128 per row
        // output px ssx+j needs halo cols ssx+1+j .. ssx+3+j (taps A.y..B.z)
        float o[8];
        #pragma unroll
        for (int cc = 0; cc < 2; cc++){
            int cil = q*2 + cc;
            int cg = ch*8 + cil;
            const float* hb = halo + cil*364;
            const float4* wp = (const float4*)(dqp + cg*12);
            float4 wA = wp[0];
            float4 wB = wp[1];
            float4 wC = wp[2];
            float bias = db[cg];
            float o0 = bias, o1 = bias, o2 = bias, o3 = bias;
            #pragma unroll
            for (int ky = 0; ky < 3; ky++){
                const float* rp = hb + (spy + ky)*20 + ssx;
                float4 A = *(const float4*)rp;
                float4 B = *(const float4*)(rp + 4);
                float w0, w1, w2;
                if (ky == 0){ w0 = wA.x; w1 = wA.y; w2 = wA.z; }
                else if (ky == 1){ w0 = wA.w; w1 = wB.x; w2 = wB.y; }
                else { w0 = wB.z; w1 = wB.w; w2 = wC.x; }
                o0 += w0*A.y + w1*A.z + w2*A.w;
                o1 += w0*A.z + w1*A.w + w2*B.x;
                o2 += w0*A.w + w1*B.x + w2*B.y;
                o3 += w0*B.x + w1*B.y + w2*B.z;
            }
            o[cc*4+0] = fmaxf(o0, 0.f);
            o[cc*4+1] = fmaxf(o1, 0.f);
            o[cc*4+2] = fmaxf(o2, 0.f);
            o[cc*4+3] = fmaxf(o3, 0.f);
        }
        // GAP partial for dw outputs: 6 shfl per chunk
        {
            float t0 = (o[0]+o[1]) + (o[2]+o[3]);
            float t1 = (o[4]+o[5]) + (o[6]+o[7]);
            t0 += __shfl_xor_sync(0xffffffffu, t0, 4);
            t0 += __shfl_xor_sync(0xffffffffu, t0, 8);
            t0 += __shfl_xor_sync(0xffffffffu, t0, 16);
            t1 += __shfl_xor_sync(0xffffffffu, t1, 4);
            t1 += __shfl_xor_sync(0xffffffffu, t1, 8);
            t1 += __shfl_xor_sync(0xffffffffu, t1, 16);
            if (lane < 4){
                dsred[(ch*8 + lane*2)*8 + warp]     = t0;
                dsred[(ch*8 + lane*2 + 1)*8 + warp] = t1;
            }
        }
        if (ch == 4) MBAR_WAIT(mbar, 0);   // batch-0 MMA done before A overwrite
        #pragma unroll
        for (int j = 0; j < 4; j++){
            int p = spy*16 + ssx + j;
            uint32_t ad = A_addr + sw128((uint32_t)p*128u + (uint32_t)((ch & 3)*8 + q*2)*4u);
            asm volatile("st.shared.v2.b32 [%0], {%1,%2};"
                :: "r"(ad), "r"(__float_as_uint(o[j])), "r"(__float_as_uint(o[4+j])) : "memory");
        }
    }
    __syncthreads();   // all A-STS + dsred writes done

    if (tid < 64){
        float ssum = (dsred[tid*8+0] + dsred[tid*8+1]) + (dsred[tid*8+2] + dsred[tid*8+3])
                   + (dsred[tid*8+4] + dsred[tid*8+5]) + (dsred[tid*8+6] + dsred[tid*8+7]);
        atomicAdd(&g_dsum[eb64 + tid], ssum);
    }

    FENCE_ASYNC();
    if (tid < 32 && elect_one_pred()){
        unsigned long long a0 = make_desc(A_addr);
        unsigned long long b1d = make_desc(B_addr + 8192u);
        #pragma unroll
        for (int t = 0; t < 2; t++)
            #pragma unroll
            for (int k = 0; k < 4; k++)
                mma_tf32_ss(tmem + 64*t, a0 + t*1024 + k*2, b1d + k*2, TF32_IDESC, 1);
        TC_COMMIT(mbar);
    }
    MBAR_WAIT(mbar, 1);
    TC_FENCE_AFTER();

    int px_ = tid & 15, py_ = tid >> 4;
    int gy = ty*16 + py_, gx = tx*16 + px_;
    size_t ob = (size_t)gy*256 + gx;
    #pragma unroll 1
    for (int hh = 0; hh < 2; hh++){
        uint32_t dr[32];
        TC_LD_X32(dr, tmem + 64*(tid >> 7) + hh*32);
        TC_WAIT_LD();
        #pragma unroll
        for (int c2 = 0; c2 < 32; c2++){
            int c = hh*32 + c2;
            outb[(size_t)c*HW + ob] = __uint_as_float(dr[c2]) + pb[c];
        }
    }
    if (tid == 64) MBAR_INVAL(mbar);
    if (tid < 32) TC_DEALLOC(tmem, 128);
}
#else
// fallback (non-sm_103a pass): f32x2 implementation with dsum GAP
template<int BLK>
__global__ void __launch_bounds__(256,3) partA_kernel(const float* __restrict__ edwb, const float* __restrict__ epwb){
    extern __shared__ float sm[];
    uint32_t sbase = smem_u32(sm);
    uint32_t sb1k = (sbase + 1023u) & ~1023u;
    float* base = sm + ((sb1k - sbase) >> 2);
    float* Bbuf = base + 8192;
    float* halo = base + 12292;
    float* dq   = base + 17476;
    float* db   = base + 18052;
    float* pb   = base + 18116;
    float* ys   = base + 18180;
    float* dsred= base + 18244;   // 512
    int tid = threadIdx.x;
    int zz = blockIdx.z;
    int e = zz >> 2, bb = zz & 3;
    int wsel = e*2 + BLK;
    int eb64 = zz * 64;
    const float* srcf = g_feat + (size_t)bb*IMG;
    const float* src1 = BLK ? (g_b0e + (size_t)eb64 * HW) : (const float*)0;
    float* outb = (BLK ? g_b1e : g_b0e) + (size_t)eb64 * HW;
    for (int i = tid; i < 4096; i += 256) Bbuf[i] = d_epw[wsel*4096 + i];
    for (int i = tid; i < 576;  i += 256) dq[i]   = d_edw[wsel*576 + i];
    if (tid < 64){
        db[tid] = edwb[wsel*64 + tid];
        pb[tid] = epwb[wsel*64 + tid];
        ys[tid] = BLK ? g_y0[eb64 + tid] : 0.f;
    }
    __syncthreads();
    int tx = blockIdx.x, ty = blockIdx.y;
    int x0 = tx*16 - 1, y0 = ty*16 - 1;
    int px_ = tid & 15, py_ = tid >> 4;
    int lane = tid & 31, warp = tid >> 5;
    float sf[11];
    float sbv[BLK ? 11 : 1];
    auto stage = [&](int ch){
        const float* fp = srcf + (size_t)(ch*8)*HW;
        const float* bp = BLK ? (src1 + (size_t)(ch*8)*HW) : (const float*)0;
        #pragma unroll
        for (int k = 0; k < 11; k++){
            int i = tid + k*256;
            float f = 0.f, b = 0.f;
            if (i < 2592){
                int cil = i / 324;
                int r = i - cil*324;
                int yy = r / 18;
                int xx = r - yy*18;
                int gy = y0 + yy, gx = x0 + xx;
                if ((unsigned)gy < 256u && (unsigned)gx < 256u){
                    int off = cil*HW + gy*256 + gx;
                    f = fp[off];
                    if (BLK) b = bp[off];
                }
            }
            sf[k] = f;
            if (BLK) sbv[k] = b;
        }
    };
    unsigned long long acc[32];
    #pragma unroll
    for (int j = 0; j < 32; j++) acc[j] = 0ull;
    stage(0);
    #pragma unroll 1
    for (int ch = 0; ch < 8; ch++){
        float* hbuf = halo + (ch & 1)*2592;
        #pragma unroll
        for (int k = 0; k < 11; k++){
            int i = tid + k*256;
            if (i < 2592){
                float v = sf[k];
                if (BLK){ int cil = i/324; v += sbv[k]*ys[ch*8 + cil]; }
                hbuf[i] = v;
            }
        }
        if (ch < 7) stage(ch+1);
        __syncthreads();
        #pragma unroll
        for (int u = 0; u < 8; u++){
            int cg = ch*8 + u;
            const float* h = hbuf + u*324 + py_*18 + px_;
            const float* w9 = dq + cg*9;
            float v = db[cg];
            #pragma unroll
            for (int ky = 0; ky < 3; ky++)
                #pragma unroll
                for (int kx = 0; kx < 3; kx++)
                    v += w9[ky*3 + kx] * h[ky*18 + kx];
            v = fmaxf(v, 0.f);
            // dsum reduction over pixels
            float r2 = v;
            r2 += __shfl_xor_sync(0xffffffffu, r2, 16);
            r2 += __shfl_xor_sync(0xffffffffu, r2, 8);
            r2 += __shfl_xor_sync(0xffffffffu, r2, 4);
            r2 += __shfl_xor_sync(0xffffffffu, r2, 2);
            r2 += __shfl_xor_sync(0xffffffffu, r2, 1);
            if (lane == 0) dsred[cg*8 + warp] = r2;
            unsigned long long x2 = pack2(v, v);
            const ulonglong2* w4 = (const ulonglong2*)(Bbuf + cg*64);
            #pragma unroll
            for (int j = 0; j < 16; j++){
                ulonglong2 w = w4[j];
                fma2(acc[2*j],   w.x, x2);
                fma2(acc[2*j+1], w.y, x2);
            }
        }
        __syncthreads();
    }
    if (tid < 64){
        float s = 0.f;
        #pragma unroll
        for (int i = 0; i < 8; i++) s += dsred[tid*8 + i];
        atomicAdd(&g_dsum[eb64 + tid], s);
    }
    int gy = ty*16 + py_, gx = tx*16 + px_;
    size_t ob = (size_t)gy*256 + gx;
    #pragma unroll
    for (int j = 0; j < 32; j++){
        float a, b2; unpack2(acc[j], a, b2);
        outb[(size_t)(2*j)*HW + ob]   = a  + pb[2*j];
        outb[(size_t)(2*j+1)*HW + ob] = b2 + pb[2*j+1];
    }
}
#endif

// ---------------- channel attention (one block per expert) ----------------
// m[c] = (pwW[c,:] . dsum)/65536 + pwb[c]  (pw is linear; exact GAP)
__global__ void y_kernel(const float* __restrict__ fc1_all, const float* __restrict__ fc2_all,
                         const float* __restrict__ epwb, int blk){
    __shared__ float m[256];
    __shared__ float h1[64];
    __shared__ float ds[256];
    int tid = threadIdx.x;
    int e = blockIdx.x;
    int wsel = e*2 + blk;
    const float* fc1 = fc1_all + wsel*1024;
    const float* fc2 = fc2_all + wsel*1024;
    int base = e*256;
    ds[tid] = g_dsum[base + tid];
    __syncthreads();
    g_dsum[base + tid] = 0.f;
    {
        int b = tid >> 6, c = tid & 63;
        const float* W = d_epw_p + wsel*4096 + c*64;
        const float* dv = ds + b*64;
        float s = 0.f;
        #pragma unroll 8
        for (int ci = 0; ci < 64; ci++) s += W[ci] * dv[ci];
        m[tid] = s * (1.f / 65536.f) + epwb[wsel*64 + c];
    }
    __syncthreads();
    if (tid < 64){
        int b = tid / 16, j = tid % 16;
        float s = 0.f;
        for (int c = 0; c < 64; c++) s += m[b*64 + c] * fc1[j*64 + c];
        h1[tid] = fmaxf(s, 0.f);
    }
    __syncthreads();
    int b = tid / 64, co = tid % 64;
    float s = 0.f;
    #pragma unroll
    for (int j = 0; j < 16; j++) s += h1[b*16 + j] * fc2[co*16 + j];
    float yv = 1.f / (1.f + expf(-s));
    if (blk) g_y1[base + tid] = yv; else g_y0[base + tid] = yv;
}

// ---------------- MoE select: per-pixel expert gather ----------------
__global__ void __launch_bounds__(256) select_kernel(){
    int pix = blockIdx.x*256 + threadIdx.x;
    int bb = pix / HW, pr = pix % HW;
    int e = g_top[pix];
    int eb64 = (e*4 + bb)*64;
    const float* y0 = g_y0 + eb64;
    const float* y1 = g_y1 + eb64;
    const float* b0 = g_b0e + (size_t)eb64*HW + pr;
    const float* b1 = g_b1e + (size_t)eb64*HW + pr;
    int base = bb*IMG + pr;
    #pragma unroll 4
    for (int c = 0; c < 64; c++){
        g_moe[base + c*HW] = g_feat[base + c*HW] + b0[(size_t)c*HW]*y0[c] + b1[(size_t)c*HW]*y1[c];
    }
}

// ---------------- recon 64->12 3x3 + pixel shuffle + bilinear skip ----------------
#define RC_SMEM ((20736 + 972 + 6912 + 12) * 4)
__global__ void __launch_bounds__(256) recon_kernel(const float* __restrict__ x, const float* __restrict__ rcb){
    extern __shared__ float sm[];
    float* halo = sm;            // 20736
    float* xs   = halo + 20736;  // 972
    float* wt   = xs + 972;      // 6912
    float* rb   = wt + 6912;     // 12
    int tid = threadIdx.x;
    for (int i = tid; i < 6912; i += 256) wt[i] = d_rect[i];
    if (tid < 12) rb[tid] = rcb[tid];
    int tx = blockIdx.x, ty = blockIdx.y, bb = blockIdx.z;
    int x0 = tx*16 - 1, y0 = ty*16 - 1;
    for (int i = tid; i < 64*324; i += 256){
        int c = i/324, r = i%324, yy = r/18, xx = r%18;
        int gy = y0 + yy, gx = x0 + xx;
        float v = 0.f;
        if ((unsigned)gy < 256u && (unsigned)gx < 256u) v = g_moe[(bb*64+c)*HW + gy*256 + gx];
        halo[i] = v;
    }
    for (int i = tid; i < 3*324; i += 256){
        int c = i/324, r = i%324, yy = r/18, xx = r%18;
        int gy = min(max(y0 + yy, 0), 255), gx = min(max(x0 + xx, 0), 255);
        xs[i] = x[(bb*3+c)*HW + gy*256 + gx];
    }
    __syncthreads();
    int px = tid % 16, py = tid / 16;
    unsigned long long acc[6];
    #pragma unroll
    for (int j = 0; j < 6; j++) acc[j] = 0ull;
    for (int ci = 0; ci < 64; ci++){
        const float* h = halo + ci*324 + py*18 + px;
        #pragma unroll
        for (int k = 0; k < 9; k++){
            float xv = h[(k/3)*18 + (k%3)];
            unsigned long long x2 = pack2(xv, xv);
            const unsigned long long* w2 = (const unsigned long long*)(wt + (ci*9 + k)*12);
            ulonglong2 wa = *(const ulonglong2*)w2;
            unsigned long long wc = w2[2];
            fma2(acc[0], wa.x, x2);
            fma2(acc[1], wa.y, x2);
            fma2(acc[2], wc,   x2);
            ulonglong2 wb = *(const ulonglong2*)(w2 + 3);
            unsigned long long wd = w2[5];
            fma2(acc[3], wb.x, x2);
            fma2(acc[4], wb.y, x2);
            fma2(acc[5], wd,   x2);
        }
    }
    float cv[12];
    #pragma unroll
    for (int j = 0; j < 6; j++){
        float a, b2; unpack2(acc[j], a, b2);
        cv[2*j]   = a  + rb[2*j];
        cv[2*j+1] = b2 + rb[2*j+1];
    }
    int gy = ty*16 + py, gx = tx*16 + px;
    #pragma unroll
    for (int r1 = 0; r1 < 2; r1++){
        int ly0 = r1 ? py+1 : py;
        int ly1 = ly0 + 1;
        float wy0 = r1 ? 0.75f : 0.25f;
        float wy1 = 1.f - wy0;
        #pragma unroll
        for (int r2 = 0; r2 < 2; r2++){
            int lx0 = r2 ? px+1 : px;
            int lx1 = lx0 + 1;
            float wx0 = r2 ? 0.75f : 0.25f;
            float wx1 = 1.f - wx0;
            int oh = 2*gy + r1, ow = 2*gx + r2;
            #pragma unroll
            for (int co = 0; co < 3; co++){
                const float* xc = xs + co*324;
                float up = wy0*(wx0*xc[ly0*18+lx0] + wx1*xc[ly0*18+lx1])
                         + wy1*(wx0*xc[ly1*18+lx0] + wx1*xc[ly1*18+lx1]);
                int ch = co*4 + r1*2 + r2;
                g_sr[(bb*3+co)*262144 + oh*512 + ow] = cv[ch] + up;
            }
        }
    }
}

// ---------------- refinement: out = sr + conv2(relu(conv1(sr))) ----------------
__global__ void __launch_bounds__(256) ref_kernel(const float* __restrict__ b1, const float* __restrict__ b2,
                                                  float* __restrict__ out){
    __shared__ float srh[3*432];   // 3 x 12 x 36
    __shared__ float th[3*340];    // 3 x 10 x 34
    __shared__ float w1[81], w2[81], sb1[3], sb2[3];
    int tid = threadIdx.x;
    if (tid < 81){ w1[tid] = d_ref1[tid]; w2[tid] = d_ref2[tid]; }
    if (tid < 3){ sb1[tid] = b1[tid]; sb2[tid] = b2[tid]; }
    int tx = blockIdx.x, ty = blockIdx.y, bb = blockIdx.z;
    int X0 = tx*32, Y0 = ty*8;
    for (int i = tid; i < 3*432; i += 256){
        int c = i/432, r = i%432, yy = r/36, xx = r%36;
        int gy = Y0 + yy - 2, gx = X0 + xx - 2;
        float v = 0.f;
        if ((unsigned)gy < 512u && (unsigned)gx < 512u) v = g_sr[(bb*3+c)*262144 + gy*512 + gx];
        srh[i] = v;
    }
    __syncthreads();
    for (int i = tid; i < 3*340; i += 256){
        int c = i/340, r = i%340, yy = r/34, xx = r%34;
        int gy = Y0 + yy - 1, gx = X0 + xx - 1;
        float v = 0.f;
        if ((unsigned)gy < 512u && (unsigned)gx < 512u){
            v = sb1[c];
            #pragma unroll
            for (int ci = 0; ci < 3; ci++)
                #pragma unroll
                for (int ky = 0; ky < 3; ky++)
                    #pragma unroll
                    for (int kx = 0; kx < 3; kx++)
                        v += w1[(c*3+ci)*9 + ky*3 + kx] * srh[ci*432 + (yy+ky)*36 + (xx+kx)];
            v = fmaxf(v, 0.f);
        }
        th[i] = v;
    }
    __syncthreads();
    int px = tid % 32, py = tid / 32;
    int oh = Y0 + py, ow = X0 + px;
    #pragma unroll
    for (int co = 0; co < 3; co++){
        float v = sb2[co];
        #pragma unroll
        for (int ci = 0; ci < 3; ci++)
            #pragma unroll
            for (int ky = 0; ky < 3; ky++)
                #pragma unroll
                for (int kx = 0; kx < 3; kx++)
                    v += w2[(co*3+ci)*9 + ky*3 + kx] * th[ci*340 + (py+ky)*34 + (px+kx)];
        out[(bb*3+co)*262144 + oh*512 + ow] = srh[co*432 + (py+2)*36 + (px+2)] + v;
    }
}

// ---------------- launch ----------------
extern "C" void kernel_launch(void* const* d_in, const int* in_sizes, int n_in,
                              void* d_out, int out_size){
    const float* x         = (const float*)d_in[0];
    const float* shallow_w = (const float*)d_in[1];
    const float* shallow_b = (const float*)d_in[2];
    const float* tex_dw_w  = (const float*)d_in[3];
    const float* tex_dw_b  = (const float*)d_in[4];
    const float* tex_pw_w  = (const float*)d_in[5];
    const float* tex_pw_b  = (const float*)d_in[6];
    const float* router_w  = (const float*)d_in[7];
    const float* router_b  = (const float*)d_in[8];
    const float* exp_dw_w  = (const float*)d_in[9];
    const float* exp_dw_b  = (const float*)d_in[10];
    const float* exp_pw_w  = (const float*)d_in[11];
    const float* exp_pw_b  = (const float*)d_in[12];
    const float* fc1       = (const float*)d_in[13];
    const float* fc2       = (const float*)d_in[14];
    const float* recon_w   = (const float*)d_in[15];
    const float* recon_b   = (const float*)d_in[16];
    const float* ref1_w    = (const float*)d_in[17];
    const float* ref1_b    = (const float*)d_in[18];
    const float* ref2_w    = (const float*)d_in[19];
    const float* ref2_b    = (const float*)d_in[20];
    float* out = (float*)d_out;

    cudaFuncSetAttribute(shallow_tex_kernel, cudaFuncAttributeMaxDynamicSharedMemorySize, ST_SMEM);
    cudaFuncSetAttribute(partA_kernel<0>, cudaFuncAttributeMaxDynamicSharedMemorySize, PA_SMEM);
    cudaFuncSetAttribute(partA_kernel<1>, cudaFuncAttributeMaxDynamicSharedMemorySize, PA_SMEM);
    cudaFuncSetAttribute(recon_kernel,    cudaFuncAttributeMaxDynamicSharedMemorySize, RC_SMEM);

    prep_kernel<<<22, 256>>>(shallow_w, tex_dw_w, tex_pw_w, exp_dw_w, exp_pw_w, ref1_w, ref2_w, recon_w);

    dim3 g16(16, 16, 4);
    shallow_tex_kernel<<<g16, 256, ST_SMEM>>>(x, shallow_b, tex_dw_b, tex_pw_b, router_w, router_b);

    dim3 gA(16, 16, 16);   // z = e*4 + batch
    partA_kernel<0><<<gA, 256, PA_SMEM>>>(exp_dw_b, exp_pw_b);
    y_kernel<<<4, 256>>>(fc1, fc2, exp_pw_b, 0);
    partA_kernel<1><<<gA, 256, PA_SMEM>>>(exp_dw_b, exp_pw_b);
    y_kernel<<<4, 256>>>(fc1, fc2, exp_pw_b, 1);
    select_kernel<<<1024, 256>>>();

    recon_kernel<<<g16, 256, RC_SMEM>>>(x, recon_b);

    dim3 gref(16, 64, 4);
    ref_kernel<<<gref, 256>>>(ref1_b, ref2_b, out);
}

// round 14
// speedup vs baseline: 1.7698x; 1.0504x over previous
#include <cuda_runtime.h>
#include <math.h>
#include <stdint.h>

#if (defined(__CUDA_ARCH_FEAT_SM103_ALL) || (defined(__CUDA_ARCH_SPECIFIC__) && (__CUDA_ARCH__ == 1030)))
#define USE_TC 1
#else
#define USE_TC 0
#endif

#define BATCH 4
#define CCH 64
#define HH 256
#define WWI 256
#define HW (HH*WWI)
#define IMG (CCH*HW)
#define NPIX (BATCH*HW)

// ---------------- scratch (device globals, no allocs) ----------------
__device__ float g_feat[BATCH*CCH*HW];
__device__ float g_b0e[4*BATCH*CCH*HW];   // per-expert block-0 residual branch
__device__ float g_b1e[4*BATCH*CCH*HW];   // per-expert block-1 residual branch
__device__ float g_moe[BATCH*CCH*HW];
__device__ float g_sr[BATCH*3*512*512];
__device__ int   g_top[NPIX];
__device__ float g_dsum[4*BATCH*CCH];     // [e][b][ci]: per-image sums of relu(dw)
__device__ float g_y0[4*BATCH*CCH];
__device__ float g_y1[4*BATCH*CCH];
// quantized / transposed weights
__device__ float d_sq_t[27*64];     // shallow, transposed [k][co]
__device__ float d_texdw[576];
__device__ float d_texpw[512];
__device__ float d_edw[8*576];
__device__ float d_epw[8*4096];     // pw weights: SW128 MMA layout (TC) or [ci][co] (fallback)
__device__ float d_epw_p[8*4096];   // pw weights plain [co][ci] (ternarized) for y_kernel
__device__ float d_ref1[81];
__device__ float d_ref2[81];
__device__ float d_rect[576*12];    // recon transposed [ci*9+k][co]

// ---------------- f32x2 helpers ----------------
__device__ __forceinline__ unsigned long long pack2(float a, float b){
    unsigned long long r;
    asm("mov.b64 %0, {%1, %2};" : "=l"(r) : "r"(__float_as_uint(a)), "r"(__float_as_uint(b)));
    return r;
}
__device__ __forceinline__ void unpack2(unsigned long long v, float& a, float& b){
    unsigned int x, y;
    asm("mov.b64 {%0, %1}, %2;" : "=r"(x), "=r"(y) : "l"(v));
    a = __uint_as_float(x); b = __uint_as_float(y);
}
__device__ __forceinline__ void fma2(unsigned long long& acc, unsigned long long w, unsigned long long x){
    asm("fma.rn.f32x2 %0, %1, %2, %0;" : "+l"(acc) : "l"(w), "l"(x));
}

__device__ __forceinline__ uint32_t smem_u32(const void* p){
    uint32_t a;
    asm("{ .reg .u64 t; cvta.to.shared.u64 t, %1; cvt.u32.u64 %0, t; }" : "=r"(a) : "l"(p));
    return a;
}

__host__ __device__ __forceinline__ uint32_t sw128(uint32_t off){ return off ^ ((off >> 3) & 0x70); }

#if USE_TC
// ---------------- tcgen05 / mbarrier helpers (sm_103a-specific pass only) ----------------
__device__ __forceinline__ uint32_t elect_one_pred(){
    uint32_t pred;
    asm volatile("{\n\t.reg .pred p;\n\telect.sync _|p, 0xFFFFFFFF;\n\tselp.b32 %0, 1, 0, p;\n\t}" : "=r"(pred));
    return pred;
}
#define TC_ALLOC(sa, n)   asm volatile("tcgen05.alloc.cta_group::1.sync.aligned.shared::cta.b32 [%0], %1;" :: "r"(sa), "r"((uint32_t)(n)) : "memory")
#define TC_DEALLOC(t, n)  asm volatile("tcgen05.dealloc.cta_group::1.sync.aligned.b32 %0, %1;" :: "r"(t), "r"((uint32_t)(n)))
#define TC_RELINQ()       asm volatile("tcgen05.relinquish_alloc_permit.cta_group::1.sync.aligned;")
#define TC_COMMIT(mb)     asm volatile("tcgen05.commit.cta_group::1.mbarrier::arrive::one.shared::cluster.b64 [%0];" :: "r"(mb) : "memory")
#define TC_FENCE_AFTER()  asm volatile("tcgen05.fence::after_thread_sync;" ::: "memory")
#define TC_WAIT_LD()      asm volatile("tcgen05.wait::ld.sync.aligned;" ::: "memory")
#define FENCE_ASYNC()     asm volatile("fence.proxy.async.shared::cta;" ::: "memory")
#define MBAR_INIT(mb, c)  asm volatile("mbarrier.init.shared.b64 [%0], %1;" :: "r"(mb), "r"((uint32_t)(c)) : "memory")
#define MBAR_INVAL(mb)    asm volatile("mbarrier.inval.shared.b64 [%0];" :: "r"(mb) : "memory")
#define MBAR_WAIT(mb, ph) do { \
    uint32_t _mb = (mb); uint32_t _p = (ph); uint32_t _done; \
    asm volatile("{\n\t.reg .pred p;\n\tmbarrier.try_wait.parity.acquire.cta.shared::cta.b64 p, [%1], %2;\n\tselp.b32 %0, 1, 0, p;\n\t}" \
        : "=r"(_done) : "r"(_mb), "r"(_p) : "memory"); \
    if (!_done){ \
        asm volatile("{\n\t.reg .pred P1;\n\tWL_%=:\n\tmbarrier.try_wait.parity.acquire.cta.shared::cta.b64 P1, [%0], %1, 0x989680;\n\t@P1 bra.uni WD_%=;\n\tbra.uni WL_%=;\n\tWD_%=:\n\t}" \
            :: "r"(_mb), "r"(_p) : "memory"); \
    } \
} while(0)
#define TC_LD_X32(r, ta) \
    asm volatile("tcgen05.ld.sync.aligned.32x32b.x32.b32 " \
        "{%0, %1, %2, %3, %4, %5, %6, %7, %8, %9, %10, %11, %12, %13, %14, %15, " \
        " %16, %17, %18, %19, %20, %21, %22, %23, %24, %25, %26, %27, %28, %29, %30, %31}, [%32];" \
        : "=r"((r)[0]),  "=r"((r)[1]),  "=r"((r)[2]),  "=r"((r)[3]), \
          "=r"((r)[4]),  "=r"((r)[5]),  "=r"((r)[6]),  "=r"((r)[7]), \
          "=r"((r)[8]),  "=r"((r)[9]),  "=r"((r)[10]), "=r"((r)[11]), \
          "=r"((r)[12]), "=r"((r)[13]), "=r"((r)[14]), "=r"((r)[15]), \
          "=r"((r)[16]), "=r"((r)[17]), "=r"((r)[18]), "=r"((r)[19]), \
          "=r"((r)[20]), "=r"((r)[21]), "=r"((r)[22]), "=r"((r)[23]), \
          "=r"((r)[24]), "=r"((r)[25]), "=r"((r)[26]), "=r"((r)[27]), \
          "=r"((r)[28]), "=r"((r)[29]), "=r"((r)[30]), "=r"((r)[31]) \
        : "r"(ta))

__device__ __forceinline__ void mma_tf32_ss(uint32_t d_tmem, unsigned long long a_desc,
                                            unsigned long long b_desc, uint32_t idesc, int en){
    asm volatile(
        "{\n\t.reg .pred p;\n\tsetp.ne.u32 p, %4, 0;\n\t"
        "tcgen05.mma.cta_group::1.kind::tf32 [%0], %1, %2, %3, p;\n\t}"
        :: "r"(d_tmem), "l"(a_desc), "l"(b_desc), "r"(idesc), "r"((uint32_t)en) : "memory");
}

// SW128 smem descriptor: LBO=1, SBO=64, version=1, layout SW128
__device__ __forceinline__ unsigned long long make_desc(uint32_t addr){
    const unsigned long long base =
        (2ull << 61) | (1ull << 46) | (64ull << 32) | (1ull << 16);
    return base | (((unsigned long long)(addr >> 4)) & 0x3FFF);
}
// idesc: dtype F32, atype/btype TF32 (2), N=64, M=128
#define TF32_IDESC 0x8100910u
#endif  // USE_TC

// ---------------- weight prep: TWN ternarize (+ transposes) ----------------
__global__ void prep_kernel(const float* shallow_w, const float* tex_dw_w, const float* tex_pw_w,
                            const float* exp_dw_w, const float* exp_pw_w,
                            const float* ref1_w, const float* ref2_w, const float* recon_w)
{
    __shared__ float sred[256];
    __shared__ float sred2[256];
    int blk = blockIdx.x, tid = threadIdx.x;
    const float* src; float* dst; int n; int mode; bool quant = true;
    if (blk == 0)       { src = shallow_w; dst = d_sq_t;  n = 1728; mode = 1; }
    else if (blk == 1)  { src = tex_dw_w;  dst = d_texdw; n = 576;  mode = 0; }
    else if (blk == 2)  { src = tex_pw_w;  dst = d_texpw; n = 512;  mode = 0; }
    else if (blk < 11)  { int eb = blk-3;  src = exp_dw_w + eb*576;  dst = d_edw + eb*576;  n = 576;  mode = 0; }
    else if (blk < 19)  { int eb = blk-11; src = exp_pw_w + eb*4096; dst = d_epw + eb*4096; n = 4096; mode = 2; }
    else if (blk == 19) { src = ref1_w; dst = d_ref1; n = 81; mode = 0; }
    else if (blk == 20) { src = ref2_w; dst = d_ref2; n = 81; mode = 0; }
    else                { src = recon_w; dst = d_rect; n = 6912; mode = 3; quant = false; }

    if (!quant){
        for (int i = tid; i < n; i += 256){ int co = i/576, t = i%576; dst[t*12 + co] = src[i]; }
        for (int i = tid; i < 4*BATCH*CCH; i += 256) g_dsum[i] = 0.f;   // init GAP accumulator once
        return;
    }
    float s = 0.f;
    for (int i = tid; i < n; i += 256) s += fabsf(src[i]);
    sred[tid] = s; __syncthreads();
    for (int off = 128; off; off >>= 1){ if (tid < off) sred[tid] += sred[tid+off]; __syncthreads(); }
    float delta = 0.75f * sred[0] / (float)n;
    __syncthreads();
    float s2 = 0.f, c2 = 0.f;
    for (int i = tid; i < n; i += 256){ float a = fabsf(src[i]); if (a > delta){ s2 += a; c2 += 1.f; } }
    sred[tid] = s2; sred2[tid] = c2; __syncthreads();
    for (int off = 128; off; off >>= 1){
        if (tid < off){ sred[tid] += sred[tid+off]; sred2[tid] += sred2[tid+off]; }
        __syncthreads();
    }
    float alpha = sred[0] / fmaxf(sred2[0], 1.f);
    for (int i = tid; i < n; i += 256){
        float w = src[i];
        float q = (fabsf(w) > delta) ? copysignf(alpha, w) : 0.f;
        int j;
        if (mode == 0) j = i;
        else if (mode == 1){ int co = i/27, k = i%27; j = k*64 + co; }
        else {
            int co = i/64, ci = i%64;
            d_epw_p[(blk-11)*4096 + i] = q;   // plain [co][ci] copy for y_kernel
#if USE_TC
            // MMA SW128 K-major layout: chunk(ci/32), row co (128B), col ci%32
            uint32_t byte = (uint32_t)(ci>>5)*8192u + sw128((uint32_t)co*128u + (uint32_t)(ci&31)*4u);
            j = (int)(byte >> 2);
#else
            j = ci*64 + co;   // transposed [ci][co]
#endif
        }
        dst[j] = q;
    }
}

// ---------------- FUSED shallow conv + texture encoder + router + argmax ----------------
#define ST_SMEM ((20736 + 1200 + 1728 + 576 + 64 + 512 + 8 + 32 + 4 + 64) * 4)
__global__ void __launch_bounds__(256,2) shallow_tex_kernel(
    const float* __restrict__ x, const float* __restrict__ sb,
    const float* __restrict__ tdwb, const float* __restrict__ tpwb,
    const float* __restrict__ rw,   const float* __restrict__ rb){
    extern __shared__ float sm[];
    float* fs  = sm;             // 20736 (64 x 324)
    float* xs  = fs + 20736;     // 1200 (3 x 400: 20x20 x-halo)
    float* wt  = xs + 1200;      // 1728 (shallow, [k][co])
    float* tq  = wt + 1728;      // 576
    float* tb  = tq + 576;       // 64
    float* pq  = tb + 64;        // 512
    float* pb  = pq + 512;       // 8
    float* rws = pb + 8;         // 32
    float* rbs = rws + 32;       // 4
    float* bs  = rbs + 4;        // 64
    int tid = threadIdx.x;
    int tx = blockIdx.x, ty = blockIdx.y, bb = blockIdx.z;
    for (int i = tid; i < 1728; i += 256) wt[i] = d_sq_t[i];
    for (int i = tid; i < 576;  i += 256) tq[i] = d_texdw[i];
    for (int i = tid; i < 512;  i += 256) pq[i] = d_texpw[i];
    if (tid < 64) tb[tid] = tdwb[tid];
    if (tid < 8)  pb[tid] = tpwb[tid];
    if (tid < 32) rws[tid] = rw[tid];
    if (tid < 4)  rbs[tid] = rb[tid];
    if (tid < 64) bs[tid] = sb[tid];
    int X0 = tx*16 - 2, Y0 = ty*16 - 2;
    for (int i = tid; i < 1200; i += 256){
        int c = i/400, r = i%400, yy = r/20, xx = r%20;
        int gy = Y0 + yy, gx = X0 + xx;
        float v = 0.f;
        if ((unsigned)gy < 256u && (unsigned)gx < 256u) v = x[(bb*3+c)*HW + gy*256 + gx];
        xs[i] = v;
    }
    __syncthreads();
    for (int hp = tid; hp < 324; hp += 256){
        int yy = hp/18, xx = hp%18;
        int gy = ty*16 - 1 + yy, gx = tx*16 - 1 + xx;
        if ((unsigned)gy >= 256u || (unsigned)gx >= 256u){
            #pragma unroll 8
            for (int c = 0; c < 64; c++) fs[c*324 + hp] = 0.f;
            continue;
        }
        float in[27];
        #pragma unroll
        for (int c = 0; c < 3; c++)
            #pragma unroll
            for (int ky = 0; ky < 3; ky++)
                #pragma unroll
                for (int kx = 0; kx < 3; kx++)
                    in[c*9 + ky*3 + kx] = xs[c*400 + (yy+ky)*20 + (xx+kx)];
        unsigned long long acc[32];
        #pragma unroll
        for (int j = 0; j < 32; j++) acc[j] = 0ull;
        #pragma unroll
        for (int k = 0; k < 27; k++){
            unsigned long long x2 = pack2(in[k], in[k]);
            const unsigned long long* w2 = (const unsigned long long*)(wt + k*64);
            #pragma unroll
            for (int j = 0; j < 32; j++) fma2(acc[j], w2[j], x2);
        }
        bool inter = (yy >= 1 && yy <= 16 && xx >= 1 && xx <= 16);
        int ob = bb*IMG + gy*256 + gx;
        #pragma unroll
        for (int j = 0; j < 32; j++){
            float a, b2; unpack2(acc[j], a, b2);
            a  = fmaxf(a  + bs[2*j],   0.f);
            b2 = fmaxf(b2 + bs[2*j+1], 0.f);
            fs[(2*j)*324 + hp]   = a;
            fs[(2*j+1)*324 + hp] = b2;
            if (inter){
                g_feat[ob + (2*j)*HW]   = a;
                g_feat[ob + (2*j+1)*HW] = b2;
            }
        }
    }
    __syncthreads();
    int px = tid % 16, py = tid / 16;
    float a8[8];
    #pragma unroll
    for (int k = 0; k < 8; k++) a8[k] = 0.f;
    for (int c = 0; c < 64; c++){
        const float* h = fs + c*324 + py*18 + px;
        float v = tb[c];
        #pragma unroll
        for (int ky = 0; ky < 3; ky++)
            #pragma unroll
            for (int kx = 0; kx < 3; kx++)
                v += tq[c*9 + ky*3 + kx] * h[ky*18 + kx];
        v = fmaxf(v, 0.f);
        #pragma unroll
        for (int k = 0; k < 8; k++) a8[k] += pq[k*64 + c] * v;
    }
    float s[8];
    #pragma unroll
    for (int k = 0; k < 8; k++) s[k] = 1.f / (1.f + expf(-(a8[k] + pb[k])));
    float best = -1e30f; int be = 0;
    #pragma unroll
    for (int e = 0; e < 4; e++){
        float l = rbs[e];
        #pragma unroll
        for (int k = 0; k < 8; k++) l += rws[e*8 + k] * s[k];
        if (l > best){ best = l; be = e; }
    }
    g_top[bb*HW + (ty*16+py)*256 + (tx*16+px)] = be;
}

// ---------------- res-block part A ----------------
// z = e*4+bb; in = feat (BLK 0) or feat + b0e*y0 (BLK 1, folded at stage time)
// halo: 8 ch x (18 rows x 20 cols), channel stride 364, col h <-> gx = tx*16-2+h
// staging in float2 units (gx even, width even => lanes jointly valid)
#define PA_SMEM ((256 + 18756) * 4)
#if USE_TC
template<int BLK>
__global__ void __launch_bounds__(256,3) partA_kernel(const float* __restrict__ edwb, const float* __restrict__ epwb){
    extern __shared__ float sm[];
    uint32_t sbase = smem_u32(sm);
    uint32_t sb1k = (sbase + 1023u) & ~1023u;
    float* base = sm + ((sb1k - sbase) >> 2);
    float* halo  = base + 12292;   // 2912 (8 ch x 364)
    float* dqp   = base + 15204;   // 768
    float* db    = base + 15972;   // 64
    float* pb    = base + 16036;   // 64
    float* ys    = base + 16100;   // 64
    float* dsred = base + 16164;   // 512 (64 ch x 8 warps)
    int tid = threadIdx.x;
    int zz = blockIdx.z;
    int e = zz >> 2, bb = zz & 3;
    int wsel = e*2 + BLK;
    int eb64 = zz * 64;
    const float* srcf = g_feat + (size_t)bb*IMG;
    const float* src1 = BLK ? (g_b0e + (size_t)eb64 * HW) : (const float*)0;
    float* outb = (BLK ? g_b1e : g_b0e) + (size_t)eb64 * HW;
    uint32_t A_addr = sb1k;
    uint32_t B_addr = sb1k + 32768u;
    uint32_t meta   = sb1k + 49152u;
    uint32_t mbar   = sb1k + 49160u;
    if (tid < 32){
        TC_ALLOC(meta, 128);
        TC_RELINQ();
    }
    if (tid == 64) MBAR_INIT(mbar, 1);
    {
        float* Bbuf = base + 8192;
        for (int i = tid; i < 4096; i += 256) Bbuf[i] = d_epw[wsel*4096 + i];
    }
    for (int i = tid; i < 576; i += 256){
        int c9 = i/9, k = i - c9*9;
        dqp[c9*12 + k] = d_edw[wsel*576 + i];
    }
    if (tid < 64){
        db[tid] = edwb[wsel*64 + tid];
        pb[tid] = epwb[wsel*64 + tid];
        ys[tid] = BLK ? g_y0[eb64 + tid] : 0.f;
    }
    __syncthreads();
    uint32_t tmem;
    asm volatile("ld.shared.b32 %0, [%1];" : "=r"(tmem) : "r"(meta));

    int tx = blockIdx.x, ty = blockIdx.y;
    int y0m1 = ty*16 - 1;     // halo row 0 => gy = y0m1
    int x0m2 = tx*16 - 2;     // halo col 0 => gx = x0m2 (even)

    // dw strip mapping: q = channel-pair, s = strip (py, 4-px group)
    int q  = tid & 3;
    int s  = tid >> 2;
    int spy = s >> 2;
    int ssx = (s & 3) * 4;
    int lane = tid & 31, warp = tid >> 5;

    // float2 staging: 1440 units/chunk, 6 per thread
    float2 sf[6];
    float2 sbv[BLK ? 6 : 1];
    auto stage = [&](int ch){
        const float* fp = srcf + (size_t)(ch*8)*HW;
        const float* bp = BLK ? (src1 + (size_t)(ch*8)*HW) : (const float*)0;
        #pragma unroll
        for (int k = 0; k < 6; k++){
            int u = tid + k*256;
            float2 f = make_float2(0.f, 0.f);
            float2 b = make_float2(0.f, 0.f);
            if (u < 1440){
                int cil = u / 180;
                int rem = u - cil*180;
                int yy = rem / 10;
                int xc = rem - yy*10;
                int gy = y0m1 + yy;
                int gx = x0m2 + xc*2;
                if ((unsigned)gy < 256u && (unsigned)gx < 256u){
                    int off = cil*HW + gy*256 + gx;
                    f = *(const float2*)(fp + off);
                    if (BLK) b = *(const float2*)(bp + off);
                }
            }
            sf[k] = f;
            if (BLK) sbv[k] = b;
        }
    };

    stage(0);
    #pragma unroll 1
    for (int ch = 0; ch < 8; ch++){
        __syncthreads();   // prior chunk's halo LDS complete
        #pragma unroll
        for (int k = 0; k < 6; k++){
            int u = tid + k*256;
            if (u < 1440){
                int cil = u / 180;
                int rem = u - cil*180;
                int yy = rem / 10;
                int xc = rem - yy*10;
                float2 v = sf[k];
                if (BLK){
                    float ysc = ys[ch*8 + cil];
                    v.x += sbv[k].x * ysc;
                    v.y += sbv[k].y * ysc;
                }
                *(float2*)(halo + cil*364 + yy*20 + xc*2) = v;
            }
        }
        if (ch < 7) stage(ch+1);
        __syncthreads();
        if (ch == 4){   // A (ci 0-31) fully written -> issue MMA batch 0
            FENCE_ASYNC();
            if (tid < 32 && elect_one_pred()){
                unsigned long long a0 = make_desc(A_addr);
                unsigned long long b0d = make_desc(B_addr);
                #pragma unroll
                for (int t = 0; t < 2; t++)
                    #pragma unroll
                    for (int k = 0; k < 4; k++)
                        mma_tf32_ss(tmem + 64*t, a0 + t*1024 + k*2, b0d + k*2, TF32_IDESC, k > 0);
                TC_COMMIT(mbar);
            }
        }
        // dw conv: 2 channels x 4 pixels per thread; two aligned LDS.128 per row
        float o[8];
        #pragma unroll
        for (int cc = 0; cc < 2; cc++){
            int cil = q*2 + cc;
            int cg = ch*8 + cil;
            const float* hb = halo + cil*364;
            const float4* wp = (const float4*)(dqp + cg*12);
            float4 wA = wp[0];
            float4 wB = wp[1];
            float4 wC = wp[2];
            float bias = db[cg];
            float o0 = bias, o1 = bias, o2 = bias, o3 = bias;
            #pragma unroll
            for (int ky = 0; ky < 3; ky++){
                const float* rp = hb + (spy + ky)*20 + ssx;
                float4 A = *(const float4*)rp;
                float4 B = *(const float4*)(rp + 4);
                float w0, w1, w2;
                if (ky == 0){ w0 = wA.x; w1 = wA.y; w2 = wA.z; }
                else if (ky == 1){ w0 = wA.w; w1 = wB.x; w2 = wB.y; }
                else { w0 = wB.z; w1 = wB.w; w2 = wC.x; }
                o0 += w0*A.y + w1*A.z + w2*A.w;
                o1 += w0*A.z + w1*A.w + w2*B.x;
                o2 += w0*A.w + w1*B.x + w2*B.y;
                o3 += w0*B.x + w1*B.y + w2*B.z;
            }
            o[cc*4+0] = fmaxf(o0, 0.f);
            o[cc*4+1] = fmaxf(o1, 0.f);
            o[cc*4+2] = fmaxf(o2, 0.f);
            o[cc*4+3] = fmaxf(o3, 0.f);
        }
        // GAP partial for dw outputs: 6 shfl per chunk
        {
            float t0 = (o[0]+o[1]) + (o[2]+o[3]);
            float t1 = (o[4]+o[5]) + (o[6]+o[7]);
            t0 += __shfl_xor_sync(0xffffffffu, t0, 4);
            t0 += __shfl_xor_sync(0xffffffffu, t0, 8);
            t0 += __shfl_xor_sync(0xffffffffu, t0, 16);
            t1 += __shfl_xor_sync(0xffffffffu, t1, 4);
            t1 += __shfl_xor_sync(0xffffffffu, t1, 8);
            t1 += __shfl_xor_sync(0xffffffffu, t1, 16);
            if (lane < 4){
                dsred[(ch*8 + lane*2)*8 + warp]     = t0;
                dsred[(ch*8 + lane*2 + 1)*8 + warp] = t1;
            }
        }
        if (ch == 4) MBAR_WAIT(mbar, 0);   // batch-0 MMA done before A overwrite
        #pragma unroll
        for (int j = 0; j < 4; j++){
            int p = spy*16 + ssx + j;
            uint32_t ad = A_addr + sw128((uint32_t)p*128u + (uint32_t)((ch & 3)*8 + q*2)*4u);
            asm volatile("st.shared.v2.b32 [%0], {%1,%2};"
                :: "r"(ad), "r"(__float_as_uint(o[j])), "r"(__float_as_uint(o[4+j])) : "memory");
        }
    }
    __syncthreads();   // all A-STS + dsred writes done

    if (tid < 64){
        float ssum = (dsred[tid*8+0] + dsred[tid*8+1]) + (dsred[tid*8+2] + dsred[tid*8+3])
                   + (dsred[tid*8+4] + dsred[tid*8+5]) + (dsred[tid*8+6] + dsred[tid*8+7]);
        atomicAdd(&g_dsum[eb64 + tid], ssum);
    }

    FENCE_ASYNC();
    if (tid < 32 && elect_one_pred()){
        unsigned long long a0 = make_desc(A_addr);
        unsigned long long b1d = make_desc(B_addr + 8192u);
        #pragma unroll
        for (int t = 0; t < 2; t++)
            #pragma unroll
            for (int k = 0; k < 4; k++)
                mma_tf32_ss(tmem + 64*t, a0 + t*1024 + k*2, b1d + k*2, TF32_IDESC, 1);
        TC_COMMIT(mbar);
    }
    MBAR_WAIT(mbar, 1);
    TC_FENCE_AFTER();

    int px_ = tid & 15, py_ = tid >> 4;
    int gy = ty*16 + py_, gx = tx*16 + px_;
    size_t ob = (size_t)gy*256 + gx;
    #pragma unroll 1
    for (int hh = 0; hh < 2; hh++){
        uint32_t dr[32];
        TC_LD_X32(dr, tmem + 64*(tid >> 7) + hh*32);
        TC_WAIT_LD();
        #pragma unroll
        for (int c2 = 0; c2 < 32; c2++){
            int c = hh*32 + c2;
            outb[(size_t)c*HW + ob] = __uint_as_float(dr[c2]) + pb[c];
        }
    }
    if (tid == 64) MBAR_INVAL(mbar);
    if (tid < 32) TC_DEALLOC(tmem, 128);
}
#else
// fallback (non-sm_103a pass): f32x2 implementation with dsum GAP
template<int BLK>
__global__ void __launch_bounds__(256,3) partA_kernel(const float* __restrict__ edwb, const float* __restrict__ epwb){
    extern __shared__ float sm[];
    uint32_t sbase = smem_u32(sm);
    uint32_t sb1k = (sbase + 1023u) & ~1023u;
    float* base = sm + ((sb1k - sbase) >> 2);
    float* Bbuf = base + 8192;
    float* halo = base + 12292;
    float* dq   = base + 17476;
    float* db   = base + 18052;
    float* pb   = base + 18116;
    float* ys   = base + 18180;
    float* dsred= base + 18244;   // 512
    int tid = threadIdx.x;
    int zz = blockIdx.z;
    int e = zz >> 2, bb = zz & 3;
    int wsel = e*2 + BLK;
    int eb64 = zz * 64;
    const float* srcf = g_feat + (size_t)bb*IMG;
    const float* src1 = BLK ? (g_b0e + (size_t)eb64 * HW) : (const float*)0;
    float* outb = (BLK ? g_b1e : g_b0e) + (size_t)eb64 * HW;
    for (int i = tid; i < 4096; i += 256) Bbuf[i] = d_epw[wsel*4096 + i];
    for (int i = tid; i < 576;  i += 256) dq[i]   = d_edw[wsel*576 + i];
    if (tid < 64){
        db[tid] = edwb[wsel*64 + tid];
        pb[tid] = epwb[wsel*64 + tid];
        ys[tid] = BLK ? g_y0[eb64 + tid] : 0.f;
    }
    __syncthreads();
    int tx = blockIdx.x, ty = blockIdx.y;
    int x0 = tx*16 - 1, y0 = ty*16 - 1;
    int px_ = tid & 15, py_ = tid >> 4;
    int lane = tid & 31, warp = tid >> 5;
    float sf[11];
    float sbv[BLK ? 11 : 1];
    auto stage = [&](int ch){
        const float* fp = srcf + (size_t)(ch*8)*HW;
        const float* bp = BLK ? (src1 + (size_t)(ch*8)*HW) : (const float*)0;
        #pragma unroll
        for (int k = 0; k < 11; k++){
            int i = tid + k*256;
            float f = 0.f, b = 0.f;
            if (i < 2592){
                int cil = i / 324;
                int r = i - cil*324;
                int yy = r / 18;
                int xx = r - yy*18;
                int gy = y0 + yy, gx = x0 + xx;
                if ((unsigned)gy < 256u && (unsigned)gx < 256u){
                    int off = cil*HW + gy*256 + gx;
                    f = fp[off];
                    if (BLK) b = bp[off];
                }
            }
            sf[k] = f;
            if (BLK) sbv[k] = b;
        }
    };
    unsigned long long acc[32];
    #pragma unroll
    for (int j = 0; j < 32; j++) acc[j] = 0ull;
    stage(0);
    #pragma unroll 1
    for (int ch = 0; ch < 8; ch++){
        float* hbuf = halo + (ch & 1)*2592;
        #pragma unroll
        for (int k = 0; k < 11; k++){
            int i = tid + k*256;
            if (i < 2592){
                float v = sf[k];
                if (BLK){ int cil = i/324; v += sbv[k]*ys[ch*8 + cil]; }
                hbuf[i] = v;
            }
        }
        if (ch < 7) stage(ch+1);
        __syncthreads();
        #pragma unroll
        for (int u = 0; u < 8; u++){
            int cg = ch*8 + u;
            const float* h = hbuf + u*324 + py_*18 + px_;
            const float* w9 = dq + cg*9;
            float v = db[cg];
            #pragma unroll
            for (int ky = 0; ky < 3; ky++)
                #pragma unroll
                for (int kx = 0; kx < 3; kx++)
                    v += w9[ky*3 + kx] * h[ky*18 + kx];
            v = fmaxf(v, 0.f);
            // dsum reduction over pixels
            float r2 = v;
            r2 += __shfl_xor_sync(0xffffffffu, r2, 16);
            r2 += __shfl_xor_sync(0xffffffffu, r2, 8);
            r2 += __shfl_xor_sync(0xffffffffu, r2, 4);
            r2 += __shfl_xor_sync(0xffffffffu, r2, 2);
            r2 += __shfl_xor_sync(0xffffffffu, r2, 1);
            if (lane == 0) dsred[cg*8 + warp] = r2;
            unsigned long long x2 = pack2(v, v);
            const ulonglong2* w4 = (const ulonglong2*)(Bbuf + cg*64);
            #pragma unroll
            for (int j = 0; j < 16; j++){
                ulonglong2 w = w4[j];
                fma2(acc[2*j],   w.x, x2);
                fma2(acc[2*j+1], w.y, x2);
            }
        }
        __syncthreads();
    }
    if (tid < 64){
        float s = 0.f;
        #pragma unroll
        for (int i = 0; i < 8; i++) s += dsred[tid*8 + i];
        atomicAdd(&g_dsum[eb64 + tid], s);
    }
    int gy = ty*16 + py_, gx = tx*16 + px_;
    size_t ob = (size_t)gy*256 + gx;
    #pragma unroll
    for (int j = 0; j < 32; j++){
        float a, b2; unpack2(acc[j], a, b2);
        outb[(size_t)(2*j)*HW + ob]   = a  + pb[2*j];
        outb[(size_t)(2*j+1)*HW + ob] = b2 + pb[2*j+1];
    }
}
#endif

// ---------------- channel attention (one block per expert) ----------------
// m[c] = (pwW[c,:] . dsum)/65536 + pwb[c]  (pw is linear; exact GAP)
__global__ void y_kernel(const float* __restrict__ fc1_all, const float* __restrict__ fc2_all,
                         const float* __restrict__ epwb, int blk){
    __shared__ float m[256];
    __shared__ float h1[64];
    __shared__ float ds[256];
    int tid = threadIdx.x;
    int e = blockIdx.x;
    int wsel = e*2 + blk;
    const float* fc1 = fc1_all + wsel*1024;
    const float* fc2 = fc2_all + wsel*1024;
    int base = e*256;
    ds[tid] = g_dsum[base + tid];
    __syncthreads();
    g_dsum[base + tid] = 0.f;
    {
        int b = tid >> 6, c = tid & 63;
        const float* W = d_epw_p + wsel*4096 + c*64;
        const float* dv = ds + b*64;
        float s = 0.f;
        #pragma unroll 8
        for (int ci = 0; ci < 64; ci++) s += W[ci] * dv[ci];
        m[tid] = s * (1.f / 65536.f) + epwb[wsel*64 + c];
    }
    __syncthreads();
    if (tid < 64){
        int b = tid / 16, j = tid % 16;
        float s = 0.f;
        for (int c = 0; c < 64; c++) s += m[b*64 + c] * fc1[j*64 + c];
        h1[tid] = fmaxf(s, 0.f);
    }
    __syncthreads();
    int b = tid / 64, co = tid % 64;
    float s = 0.f;
    #pragma unroll
    for (int j = 0; j < 16; j++) s += h1[b*16 + j] * fc2[co*16 + j];
    float yv = 1.f / (1.f + expf(-s));
    if (blk) g_y1[base + tid] = yv; else g_y0[base + tid] = yv;
}

// ---------------- MoE select: per-pixel expert gather ----------------
__global__ void __launch_bounds__(256) select_kernel(){
    int pix = blockIdx.x*256 + threadIdx.x;
    int bb = pix / HW, pr = pix % HW;
    int e = g_top[pix];
    int eb64 = (e*4 + bb)*64;
    const float* y0 = g_y0 + eb64;
    const float* y1 = g_y1 + eb64;
    const float* b0 = g_b0e + (size_t)eb64*HW + pr;
    const float* b1 = g_b1e + (size_t)eb64*HW + pr;
    int base = bb*IMG + pr;
    #pragma unroll 4
    for (int c = 0; c < 64; c++){
        g_moe[base + c*HW] = g_feat[base + c*HW] + b0[(size_t)c*HW]*y0[c] + b1[(size_t)c*HW]*y1[c];
    }
}

// ---------------- recon 64->12 3x3 + pixel shuffle + bilinear skip ----------------
// halo chunked (8 ci, double-buffered, register-staged) -> 52KB smem, 2 CTAs/SM
#define RC_SMEM ((5184 + 972 + 6912 + 12) * 4)
__global__ void __launch_bounds__(256,2) recon_kernel(const float* __restrict__ x, const float* __restrict__ rcb){
    extern __shared__ float sm[];
    float* halo = sm;            // 2 x 2592
    float* xs   = halo + 5184;   // 972
    float* wt   = xs + 972;      // 6912
    float* rb   = wt + 6912;     // 12
    int tid = threadIdx.x;
    for (int i = tid; i < 6912; i += 256) wt[i] = d_rect[i];
    if (tid < 12) rb[tid] = rcb[tid];
    int tx = blockIdx.x, ty = blockIdx.y, bb = blockIdx.z;
    int x0 = tx*16 - 1, y0 = ty*16 - 1;
    for (int i = tid; i < 3*324; i += 256){
        int c = i/324, r = i%324, yy = r/18, xx = r%18;
        int gy = min(max(y0 + yy, 0), 255), gx = min(max(x0 + xx, 0), 255);
        xs[i] = x[(bb*3+c)*HW + gy*256 + gx];
    }

    const float* srcm = g_moe + (size_t)bb*IMG;
    float sf[11];
    auto stage = [&](int ch){
        const float* mp = srcm + (size_t)(ch*8)*HW;
        #pragma unroll
        for (int k = 0; k < 11; k++){
            int i = tid + k*256;
            float v = 0.f;
            if (i < 2592){
                int cil = i / 324;
                int r = i - cil*324;
                int yy = r / 18;
                int xx = r - yy*18;
                int gy = y0 + yy, gx = x0 + xx;
                if ((unsigned)gy < 256u && (unsigned)gx < 256u)
                    v = mp[cil*HW + gy*256 + gx];
            }
            sf[k] = v;
        }
    };

    int px = tid % 16, py = tid / 16;
    unsigned long long acc[6];
    #pragma unroll
    for (int j = 0; j < 6; j++) acc[j] = 0ull;

    stage(0);
    #pragma unroll 1
    for (int ch = 0; ch < 8; ch++){
        float* hbuf = halo + (ch & 1)*2592;
        #pragma unroll
        for (int k = 0; k < 11; k++){
            int i = tid + k*256;
            if (i < 2592) hbuf[i] = sf[k];
        }
        if (ch < 7) stage(ch+1);   // next chunk's LDGs in flight across barrier + compute
        __syncthreads();
        #pragma unroll
        for (int cil = 0; cil < 8; cil++){
            int ci = ch*8 + cil;
            const float* h = hbuf + cil*324 + py*18 + px;
            #pragma unroll
            for (int k = 0; k < 9; k++){
                float xv = h[(k/3)*18 + (k%3)];
                unsigned long long x2 = pack2(xv, xv);
                const unsigned long long* w2 = (const unsigned long long*)(wt + (ci*9 + k)*12);
                ulonglong2 wa = *(const ulonglong2*)w2;
                unsigned long long wc = w2[2];
                fma2(acc[0], wa.x, x2);
                fma2(acc[1], wa.y, x2);
                fma2(acc[2], wc,   x2);
                ulonglong2 wb = *(const ulonglong2*)(w2 + 3);
                unsigned long long wd = w2[5];
                fma2(acc[3], wb.x, x2);
                fma2(acc[4], wb.y, x2);
                fma2(acc[5], wd,   x2);
            }
        }
        __syncthreads();
    }
    float cv[12];
    #pragma unroll
    for (int j = 0; j < 6; j++){
        float a, b2; unpack2(acc[j], a, b2);
        cv[2*j]   = a  + rb[2*j];
        cv[2*j+1] = b2 + rb[2*j+1];
    }
    int gy = ty*16 + py, gx = tx*16 + px;
    #pragma unroll
    for (int r1 = 0; r1 < 2; r1++){
        int ly0 = r1 ? py+1 : py;
        int ly1 = ly0 + 1;
        float wy0 = r1 ? 0.75f : 0.25f;
        float wy1 = 1.f - wy0;
        #pragma unroll
        for (int r2 = 0; r2 < 2; r2++){
            int lx0 = r2 ? px+1 : px;
            int lx1 = lx0 + 1;
            float wx0 = r2 ? 0.75f : 0.25f;
            float wx1 = 1.f - wx0;
            int oh = 2*gy + r1, ow = 2*gx + r2;
            #pragma unroll
            for (int co = 0; co < 3; co++){
                const float* xc = xs + co*324;
                float up = wy0*(wx0*xc[ly0*18+lx0] + wx1*xc[ly0*18+lx1])
                         + wy1*(wx0*xc[ly1*18+lx0] + wx1*xc[ly1*18+lx1]);
                int ch2 = co*4 + r1*2 + r2;
                g_sr[(bb*3+co)*262144 + oh*512 + ow] = cv[ch2] + up;
            }
        }
    }
}

// ---------------- refinement: out = sr + conv2(relu(conv1(sr))) ----------------
__global__ void __launch_bounds__(256) ref_kernel(const float* __restrict__ b1, const float* __restrict__ b2,
                                                  float* __restrict__ out){
    __shared__ float srh[3*432];   // 3 x 12 x 36
    __shared__ float th[3*340];    // 3 x 10 x 34
    __shared__ float w1[81], w2[81], sb1[3], sb2[3];
    int tid = threadIdx.x;
    if (tid < 81){ w1[tid] = d_ref1[tid]; w2[tid] = d_ref2[tid]; }
    if (tid < 3){ sb1[tid] = b1[tid]; sb2[tid] = b2[tid]; }
    int tx = blockIdx.x, ty = blockIdx.y, bb = blockIdx.z;
    int X0 = tx*32, Y0 = ty*8;
    for (int i = tid; i < 3*432; i += 256){
        int c = i/432, r = i%432, yy = r/36, xx = r%36;
        int gy = Y0 + yy - 2, gx = X0 + xx - 2;
        float v = 0.f;
        if ((unsigned)gy < 512u && (unsigned)gx < 512u) v = g_sr[(bb*3+c)*262144 + gy*512 + gx];
        srh[i] = v;
    }
    __syncthreads();
    for (int i = tid; i < 3*340; i += 256){
        int c = i/340, r = i%340, yy = r/34, xx = r%34;
        int gy = Y0 + yy - 1, gx = X0 + xx - 1;
        float v = 0.f;
        if ((unsigned)gy < 512u && (unsigned)gx < 512u){
            v = sb1[c];
            #pragma unroll
            for (int ci = 0; ci < 3; ci++)
                #pragma unroll
                for (int ky = 0; ky < 3; ky++)
                    #pragma unroll
                    for (int kx = 0; kx < 3; kx++)
                        v += w1[(c*3+ci)*9 + ky*3 + kx] * srh[ci*432 + (yy+ky)*36 + (xx+kx)];
            v = fmaxf(v, 0.f);
        }
        th[i] = v;
    }
    __syncthreads();
    int px = tid % 32, py = tid / 32;
    int oh = Y0 + py, ow = X0 + px;
    #pragma unroll
    for (int co = 0; co < 3; co++){
        float v = sb2[co];
        #pragma unroll
        for (int ci = 0; ci < 3; ci++)
            #pragma unroll
            for (int ky = 0; ky < 3; ky++)
                #pragma unroll
                for (int kx = 0; kx < 3; kx++)
                    v += w2[(co*3+ci)*9 + ky*3 + kx] * th[ci*340 + (py+ky)*34 + (px+kx)];
        out[(bb*3+co)*262144 + oh*512 + ow] = srh[co*432 + (py+2)*36 + (px+2)] + v;
    }
}

// ---------------- launch ----------------
extern "C" void kernel_launch(void* const* d_in, const int* in_sizes, int n_in,
                              void* d_out, int out_size){
    const float* x         = (const float*)d_in[0];
    const float* shallow_w = (const float*)d_in[1];
    const float* shallow_b = (const float*)d_in[2];
    const float* tex_dw_w  = (const float*)d_in[3];
    const float* tex_dw_b  = (const float*)d_in[4];
    const float* tex_pw_w  = (const float*)d_in[5];
    const float* tex_pw_b  = (const float*)d_in[6];
    const float* router_w  = (const float*)d_in[7];
    const float* router_b  = (const float*)d_in[8];
    const float* exp_dw_w  = (const float*)d_in[9];
    const float* exp_dw_b  = (const float*)d_in[10];
    const float* exp_pw_w  = (const float*)d_in[11];
    const float* exp_pw_b  = (const float*)d_in[12];
    const float* fc1       = (const float*)d_in[13];
    const float* fc2       = (const float*)d_in[14];
    const float* recon_w   = (const float*)d_in[15];
    const float* recon_b   = (const float*)d_in[16];
    const float* ref1_w    = (const float*)d_in[17];
    const float* ref1_b    = (const float*)d_in[18];
    const float* ref2_w    = (const float*)d_in[19];
    const float* ref2_b    = (const float*)d_in[20];
    float* out = (float*)d_out;

    cudaFuncSetAttribute(shallow_tex_kernel, cudaFuncAttributeMaxDynamicSharedMemorySize, ST_SMEM);
    cudaFuncSetAttribute(partA_kernel<0>, cudaFuncAttributeMaxDynamicSharedMemorySize, PA_SMEM);
    cudaFuncSetAttribute(partA_kernel<1>, cudaFuncAttributeMaxDynamicSharedMemorySize, PA_SMEM);
    cudaFuncSetAttribute(recon_kernel,    cudaFuncAttributeMaxDynamicSharedMemorySize, RC_SMEM);

    prep_kernel<<<22, 256>>>(shallow_w, tex_dw_w, tex_pw_w, exp_dw_w, exp_pw_w, ref1_w, ref2_w, recon_w);

    dim3 g16(16, 16, 4);
    shallow_tex_kernel<<<g16, 256, ST_SMEM>>>(x, shallow_b, tex_dw_b, tex_pw_b, router_w, router_b);

    dim3 gA(16, 16, 16);   // z = e*4 + batch
    partA_kernel<0><<<gA, 256, PA_SMEM>>>(exp_dw_b, exp_pw_b);
    y_kernel<<<4, 256>>>(fc1, fc2, exp_pw_b, 0);
    partA_kernel<1><<<gA, 256, PA_SMEM>>>(exp_dw_b, exp_pw_b);
    y_kernel<<<4, 256>>>(fc1, fc2, exp_pw_b, 1);
    select_kernel<<<1024, 256>>>();

    recon_kernel<<<g16, 256, RC_SMEM>>>(x, recon_b);

    dim3 gref(16, 64, 4);
    ref_kernel<<<gref, 256>>>(ref1_b, ref2_b, out);
}